// round 7
// baseline (speedup 1.0000x reference)
#include <cuda_runtime.h>
#include <cuda_bf16.h>
#include <stdint.h>

#define NB  2
#define NS  2048
#define ND  1024
#define NH  16
#define NDH 64

// Scratch (allocation-free rule: __device__ globals).
__device__ __nv_bfloat16 g_Whi[4u << 20];     // 4 x W^T hi: [n][k] k-major
__device__ __nv_bfloat16 g_Wlo[4u << 20];     // 4 x W^T lo
__device__ __nv_bfloat16 g_Xhi[3u << 22], g_Xlo[3u << 22];   // split Xq/Xk/Xv [4096][1024]
__device__ __nv_bfloat16 g_AOhi[1u << 22], g_AOlo[1u << 22]; // split attn out [4096][1024]
// Q/K/V split bf16, head-major [B,H,S,DH]
__device__ __nv_bfloat16 g_Qhi[NB*NH*NS*NDH], g_Qlo[NB*NH*NS*NDH];
__device__ __nv_bfloat16 g_Khi[NB*NH*NS*NDH], g_Klo[NB*NH*NS*NDH];
__device__ __nv_bfloat16 g_Vhi[NB*NH*NS*NDH], g_Vlo[NB*NH*NS*NDH];

// ---------------------------------------------------------------------------
// helpers
// ---------------------------------------------------------------------------
__device__ __forceinline__ uint32_t smem_u32(const void* p) {
    uint32_t a;
    asm("{ .reg .u64 t; cvta.to.shared.u64 t, %1; cvt.u32.u64 %0, t; }" : "=r"(a) : "l"(p));
    return a;
}
__device__ __forceinline__ void cpasync16(uint32_t dst, const void* src) {
    asm volatile("cp.async.cg.shared.global [%0], [%1], 16;" :: "r"(dst), "l"(src));
}
#define CP_COMMIT() asm volatile("cp.async.commit_group;" ::: "memory")
#define CP_WAIT0()  asm volatile("cp.async.wait_group 0;" ::: "memory")
#define CP_WAIT1()  asm volatile("cp.async.wait_group 1;" ::: "memory")

#define LDSM_X4(r0, r1, r2, r3, addr)                                          \
    asm volatile("ldmatrix.sync.aligned.m8n8.x4.shared.b16 {%0,%1,%2,%3}, [%4];" \
        : "=r"(r0), "=r"(r1), "=r"(r2), "=r"(r3) : "r"(addr))
#define LDSM_X4_T(r0, r1, r2, r3, addr)                                        \
    asm volatile("ldmatrix.sync.aligned.m8n8.x4.trans.shared.b16 {%0,%1,%2,%3}, [%4];" \
        : "=r"(r0), "=r"(r1), "=r"(r2), "=r"(r3) : "r"(addr))

#define MMA_BF16(d, a, b)                                                      \
    asm volatile("mma.sync.aligned.m16n8k16.row.col.f32.bf16.bf16.f32 "        \
        "{%0,%1,%2,%3},{%4,%5,%6,%7},{%8,%9},{%0,%1,%2,%3};"                   \
        : "+f"((d)[0]), "+f"((d)[1]), "+f"((d)[2]), "+f"((d)[3])               \
        : "r"((a)[0]), "r"((a)[1]), "r"((a)[2]), "r"((a)[3]),                  \
          "r"((b)[0]), "r"((b)[1]))

__device__ __forceinline__ float ex2f(float x) {
    float y; asm("ex2.approx.f32 %0, %1;" : "=f"(y) : "f"(x)); return y;
}

__device__ __forceinline__ void split2(float a, float b, uint32_t& hi, uint32_t& lo) {
    __nv_bfloat16 ha = __float2bfloat16(a), hb = __float2bfloat16(b);
    float ra = a - __bfloat162float(ha), rb = b - __bfloat162float(hb);
    hi = (uint32_t)__bfloat16_as_ushort(ha) | ((uint32_t)__bfloat16_as_ushort(hb) << 16);
    __nv_bfloat16 la = __float2bfloat16(ra), lb = __float2bfloat16(rb);
    lo = (uint32_t)__bfloat16_as_ushort(la) | ((uint32_t)__bfloat16_as_ushort(lb) << 16);
}

// ---------------------------------------------------------------------------
// X split: fp32 -> bf16 hi/lo, row-major passthrough.
// ---------------------------------------------------------------------------
__global__ __launch_bounds__(256) void splitx_kernel(
    const float* __restrict__ X0, const float* __restrict__ X1,
    const float* __restrict__ X2)
{
    const int z = blockIdx.y;
    const float* X = (z == 0) ? X0 : (z == 1) ? X1 : X2;
    __nv_bfloat16* Ohi = g_Xhi + ((size_t)z << 22);
    __nv_bfloat16* Olo = g_Xlo + ((size_t)z << 22);
    size_t idx = (size_t)blockIdx.x * 256 + threadIdx.x;
    float4 v = *((const float4*)X + idx);
    uint2 hi, lo;
    split2(v.x, v.y, hi.x, lo.x);
    split2(v.z, v.w, hi.y, lo.y);
    *((uint2*)Ohi + idx) = hi;
    *((uint2*)Olo + idx) = lo;
}

// ---------------------------------------------------------------------------
// W transpose + split. Out[n][k] = W[k][n].
// ---------------------------------------------------------------------------
__global__ __launch_bounds__(256) void wsplit_kernel(
    const float* __restrict__ W0, const float* __restrict__ W1,
    const float* __restrict__ W2, const float* __restrict__ W3)
{
    __shared__ float t[32][33];
    const float* W = (blockIdx.z == 0) ? W0 : (blockIdx.z == 1) ? W1 :
                     (blockIdx.z == 2) ? W2 : W3;
    __nv_bfloat16* Ohi = g_Whi + ((size_t)blockIdx.z << 20);
    __nv_bfloat16* Olo = g_Wlo + ((size_t)blockIdx.z << 20);

    int tx = threadIdx.x & 31, ty = threadIdx.x >> 5;
    int n0 = blockIdx.x * 32, k0 = blockIdx.y * 32;

    #pragma unroll
    for (int i = 0; i < 4; i++)
        t[ty + i*8][tx] = W[(size_t)(k0 + ty + i*8) * ND + n0 + tx];
    __syncthreads();
    #pragma unroll
    for (int i = 0; i < 4; i++) {
        float v = t[tx][ty + i*8];
        __nv_bfloat16 h = __float2bfloat16(v);
        __nv_bfloat16 l = __float2bfloat16(v - __bfloat162float(h));
        size_t idx = (size_t)(n0 + ty + i*8) * ND + k0 + tx;
        Ohi[idx] = h; Olo[idx] = l;
    }
}

// ---------------------------------------------------------------------------
// HMMA split-bf16 GEMM, all-cp.async. CTA 256M x 128N, BK=64, 512 threads.
// ---------------------------------------------------------------------------
#define GBUF   98304
#define G_AHI  0
#define G_ALO  32768
#define G_BHI  65536
#define G_BLO  81920
#define GEMM_SMEM (2 * GBUF)

__global__ __launch_bounds__(512, 1) void gemm_mma_kernel(float* __restrict__ Cout, int mode)
{
    extern __shared__ char smc[];
    const uint32_t sb = smem_u32(smc);
    const int tid  = threadIdx.x;
    const int wid  = tid >> 5, lane = tid & 31;
    const int z    = blockIdx.z;

    const __nv_bfloat16 *Ahi_g, *Alo_g, *Whi, *Wlo;
    __nv_bfloat16 *Ohi = 0, *Olo = 0;
    float osc = 1.f;
    if (mode == 0) {
        Ahi_g = g_Xhi + ((size_t)z << 22);
        Alo_g = g_Xlo + ((size_t)z << 22);
        Whi = g_Whi + ((size_t)z << 20);
        Wlo = g_Wlo + ((size_t)z << 20);
        Ohi = (z == 0) ? g_Qhi : (z == 1) ? g_Khi : g_Vhi;
        Olo = (z == 0) ? g_Qlo : (z == 1) ? g_Klo : g_Vlo;
        if (z == 0) osc = 0.125f * 1.44269504f;   // fold log2(e) for exp2 softmax
    } else {
        Ahi_g = g_AOhi; Alo_g = g_AOlo;
        Whi = g_Whi + ((size_t)3 << 20);
        Wlo = g_Wlo + ((size_t)3 << 20);
    }
    const int bM = blockIdx.y * 256, bN = blockIdx.x * 128;
    const int warp_m = (wid & 7) * 32, warp_n = (wid >> 3) * 64;

    float acc[16][4];
    #pragma unroll
    for (int i = 0; i < 16; i++)
        #pragma unroll
        for (int j = 0; j < 4; j++) acc[i][j] = 0.f;

    auto cpStage = [&](int s, int buf) {
        uint32_t base = sb + buf * GBUF;
        #pragma unroll
        for (int l = 0; l < 12; l++) {
            int f = tid + l * 512;
            const __nv_bfloat16* src;
            uint32_t dst;
            if (f < 4096) {
                int arr = f >> 11;
                int r = (f >> 3) & 255, c = f & 7;
                src = (arr ? Alo_g : Ahi_g) + (size_t)(bM + r) * ND + s * 64 + c * 8;
                dst = base + (arr ? G_ALO : G_AHI) + r * 128 + ((c * 16) ^ ((r & 7) * 16));
            } else {
                int g = f - 4096;
                int arr = g >> 10;
                int r = (g >> 3) & 127, c = g & 7;
                src = (arr ? Wlo : Whi) + (size_t)(bN + r) * ND + s * 64 + c * 8;
                dst = base + (arr ? G_BLO : G_BHI) + r * 128 + ((c * 16) ^ ((r & 7) * 16));
            }
            cpasync16(dst, src);
        }
        CP_COMMIT();
    };

    cpStage(0, 0);

    for (int s = 0; s < 16; s++) {
        const int buf = s & 1;
        if (s + 1 < 16) { cpStage(s + 1, buf ^ 1); CP_WAIT1(); }
        else            { CP_WAIT0(); }
        __syncthreads();

        const uint32_t aHi = sb + buf * GBUF + G_AHI;
        const uint32_t aLo = sb + buf * GBUF + G_ALO;
        const uint32_t bHi = sb + buf * GBUF + G_BHI;
        const uint32_t bLo = sb + buf * GBUF + G_BLO;

        #pragma unroll
        for (int kk = 0; kk < 4; kk++) {
            const int k0 = kk * 16;
            uint32_t ah[2][4], al[2][4];
            #pragma unroll
            for (int mt = 0; mt < 2; mt++) {
                int row = warp_m + mt * 16 + (lane & 15);
                uint32_t off = row * 128 + ((k0 * 2 + (lane >> 4) * 16) ^ ((row & 7) * 16));
                LDSM_X4(ah[mt][0], ah[mt][1], ah[mt][2], ah[mt][3], aHi + off);
                LDSM_X4(al[mt][0], al[mt][1], al[mt][2], al[mt][3], aLo + off);
            }
            #pragma unroll
            for (int h = 0; h < 2; h++) {
                uint32_t bh[4][2], bl[4][2];
                #pragma unroll
                for (int p = 0; p < 2; p++) {
                    int n = warp_n + h * 32 + p * 16 + (lane & 7) + ((lane >> 4) << 3);
                    uint32_t off = n * 128 + ((k0 * 2 + ((lane >> 3) & 1) * 16) ^ ((n & 7) * 16));
                    LDSM_X4(bh[p*2][0], bh[p*2][1], bh[p*2+1][0], bh[p*2+1][1], bHi + off);
                    LDSM_X4(bl[p*2][0], bl[p*2][1], bl[p*2+1][0], bl[p*2+1][1], bLo + off);
                }
                #pragma unroll
                for (int mt = 0; mt < 2; mt++)
                    #pragma unroll
                    for (int nt = 0; nt < 4; nt++)
                        MMA_BF16(acc[mt*8 + h*4 + nt], ah[mt], bh[nt]);
                #pragma unroll
                for (int mt = 0; mt < 2; mt++)
                    #pragma unroll
                    for (int nt = 0; nt < 4; nt++)
                        MMA_BF16(acc[mt*8 + h*4 + nt], ah[mt], bl[nt]);
                #pragma unroll
                for (int mt = 0; mt < 2; mt++)
                    #pragma unroll
                    for (int nt = 0; nt < 4; nt++)
                        MMA_BF16(acc[mt*8 + h*4 + nt], al[mt], bh[nt]);
            }
        }
        __syncthreads();
    }

    #pragma unroll
    for (int mt = 0; mt < 2; mt++)
        #pragma unroll
        for (int nt = 0; nt < 8; nt++) {
            int m0 = bM + warp_m + mt * 16 + (lane >> 2);
            int n  = bN + warp_n + nt * 8 + (lane & 3) * 2;
            float* a4 = acc[mt*8+nt];
            if (mode == 0) {
                int h = n >> 6, dh = n & 63;
                int b0 = m0 >> 11, s0 = m0 & 2047;
                int m1 = m0 + 8, b1 = m1 >> 11, s1 = m1 & 2047;
                size_t i0 = ((size_t)(b0 * NH + h) * NS + s0) * NDH + dh;
                size_t i1 = ((size_t)(b1 * NH + h) * NS + s1) * NDH + dh;
                uint32_t h0, l0, h1, l1;
                split2(a4[0] * osc, a4[1] * osc, h0, l0);
                split2(a4[2] * osc, a4[3] * osc, h1, l1);
                *(uint32_t*)(Ohi + i0) = h0; *(uint32_t*)(Olo + i0) = l0;
                *(uint32_t*)(Ohi + i1) = h1; *(uint32_t*)(Olo + i1) = l1;
            } else {
                *(float2*)(Cout + (size_t)m0 * ND + n)       = make_float2(a4[0], a4[1]);
                *(float2*)(Cout + (size_t)(m0 + 8) * ND + n) = make_float2(a4[2], a4[3]);
            }
        }
}

// ---------------------------------------------------------------------------
// Flash attention on HMMA, split-bf16, KV block = 128, exp2-domain softmax.
// CTA = 128 q x 128 k, 8 warps (warp = 16q), double-buffered K/V hi/lo (128KB).
// ---------------------------------------------------------------------------
#define ATT_BUF  65536
#define ATT_SMEM (2 * ATT_BUF)

__global__ __launch_bounds__(256, 1) void attn_mma_kernel(const int* __restrict__ valid_lens)
{
    extern __shared__ char smc[];
    const uint32_t sb = smem_u32(smc);
    const int tid = threadIdx.x, wid = tid >> 5, lane = tid & 31;
    const int qb = blockIdx.x, bh = blockIdx.y;
    const int bb = bh >> 4, head = bh & 15;
    const int vlen = valid_lens[bb];
    const int nkb  = (vlen + 127) >> 7;

    const size_t hbase = (size_t)bh * NS * NDH;
    const __nv_bfloat16 *Qhi = g_Qhi + hbase, *Qlo = g_Qlo + hbase;
    const __nv_bfloat16 *Khi = g_Khi + hbase, *Klo = g_Klo + hbase;
    const __nv_bfloat16 *Vhi = g_Vhi + hbase, *Vlo = g_Vlo + hbase;

    const int r = lane >> 2, c2 = (lane & 3) * 2;

    uint32_t qh[4][4], ql[4][4];
    {
        const int q0 = qb * 128 + wid * 16;
        #pragma unroll
        for (int t = 0; t < 4; t++) {
            int k0 = t * 16;
            qh[t][0] = *(const uint32_t*)(Qhi + (size_t)(q0 + r    ) * NDH + k0 + c2);
            qh[t][1] = *(const uint32_t*)(Qhi + (size_t)(q0 + r + 8) * NDH + k0 + c2);
            qh[t][2] = *(const uint32_t*)(Qhi + (size_t)(q0 + r    ) * NDH + k0 + c2 + 8);
            qh[t][3] = *(const uint32_t*)(Qhi + (size_t)(q0 + r + 8) * NDH + k0 + c2 + 8);
            ql[t][0] = *(const uint32_t*)(Qlo + (size_t)(q0 + r    ) * NDH + k0 + c2);
            ql[t][1] = *(const uint32_t*)(Qlo + (size_t)(q0 + r + 8) * NDH + k0 + c2);
            ql[t][2] = *(const uint32_t*)(Qlo + (size_t)(q0 + r    ) * NDH + k0 + c2 + 8);
            ql[t][3] = *(const uint32_t*)(Qlo + (size_t)(q0 + r + 8) * NDH + k0 + c2 + 8);
        }
    }

    float m_i[2] = {-1e30f, -1e30f}, l_i[2] = {0.f, 0.f};
    float o[8][4];
    #pragma unroll
    for (int i = 0; i < 8; i++)
        #pragma unroll
        for (int j = 0; j < 4; j++) o[i][j] = 0.f;

    // stage = 64KB: Khi|Klo|Vhi|Vlo 16KB each, 128 rows x 128B
    auto cpKV = [&](int kb, int buf) {
        #pragma unroll
        for (int l = 0; l < 16; l++) {
            int f   = tid + l * 256;
            int arr = f >> 10;
            int rr  = (f >> 3) & 127;
            int cc  = f & 7;
            const __nv_bfloat16* srcb =
                (arr == 0) ? Khi : (arr == 1) ? Klo : (arr == 2) ? Vhi : Vlo;
            const void* src = srcb + (size_t)(kb * 128 + rr) * NDH + cc * 8;
            uint32_t dst = sb + buf * ATT_BUF + arr * 16384
                         + rr * 128 + ((cc * 16) ^ ((rr & 7) * 16));
            cpasync16(dst, src);
        }
        CP_COMMIT();
    };

    cpKV(0, 0);

    for (int kb = 0; kb < nkb; kb++) {
        const int buf = kb & 1;
        CP_WAIT0();
        __syncthreads();
        if (kb + 1 < nkb) cpKV(kb + 1, buf ^ 1);

        const uint32_t kHi = sb + buf * ATT_BUF;
        const uint32_t kLo = kHi + 16384;
        const uint32_t vHi = kHi + 32768;
        const uint32_t vLo = kHi + 49152;

        // ---- S = Q K^T over 128 cols (3-pass split) ----
        float s[16][4];
        #pragma unroll
        for (int i = 0; i < 16; i++)
            #pragma unroll
            for (int j = 0; j < 4; j++) s[i][j] = 0.f;

        #pragma unroll
        for (int t = 0; t < 4; t++) {
            #pragma unroll
            for (int nh = 0; nh < 2; nh++) {
                uint32_t kh[4][2], kl[4][2];
                #pragma unroll
                for (int p = 0; p < 2; p++) {
                    int n = nh * 64 + p * 16 + (lane & 7) + ((lane >> 4) << 3);
                    uint32_t off = n * 128 + ((t * 32 + ((lane >> 3) & 1) * 16) ^ ((n & 7) * 16));
                    LDSM_X4(kh[p*2][0], kh[p*2][1], kh[p*2+1][0], kh[p*2+1][1], kHi + off);
                    LDSM_X4(kl[p*2][0], kl[p*2][1], kl[p*2+1][0], kl[p*2+1][1], kLo + off);
                }
                float (*sg)[4] = &s[nh * 8];
                #pragma unroll
                for (int nt = 0; nt < 4; nt++)
                    MMA_BF16(sg[nt*2? nt : nt], qh[t], kh[nt]);   // placeholder order fixed below
                // NOTE: fragment p*2, p*2+1 cover n-tiles nh*8 + p*2(+1)? handled below
                #pragma unroll
                for (int nt = 0; nt < 4; nt++)
                    MMA_BF16(sg[nt], ql[t], kh[nt]);
                #pragma unroll
                for (int nt = 0; nt < 4; nt++)
                    MMA_BF16(sg[nt], qh[t], kl[nt]);
            }
        }
        // The kh/kl arrays hold 4 n-tiles (32 cols); loop structure above covers
        // 64 cols per nh via p=0..1 giving tiles (nh*8 + p*2, nh*8 + p*2 + 1),
        // i.e. sg[0..3] maps tiles nh*8..nh*8+3. 64 cols = 8 tiles needs p to 4.
        // -- corrected below by a second pass over upper 32 cols:
        #pragma unroll
        for (int t = 0; t < 4; t++) {
            #pragma unroll
            for (int nh = 0; nh < 2; nh++) {
                uint32_t kh[4][2], kl[4][2];
                #pragma unroll
                for (int p = 0; p < 2; p++) {
                    int n = nh * 64 + 32 + p * 16 + (lane & 7) + ((lane >> 4) << 3);
                    uint32_t off = n * 128 + ((t * 32 + ((lane >> 3) & 1) * 16) ^ ((n & 7) * 16));
                    LDSM_X4(kh[p*2][0], kh[p*2][1], kh[p*2+1][0], kh[p*2+1][1], kHi + off);
                    LDSM_X4(kl[p*2][0], kl[p*2][1], kl[p*2+1][0], kl[p*2+1][1], kLo + off);
                }
                float (*sg)[4] = &s[nh * 8 + 4];
                #pragma unroll
                for (int nt = 0; nt < 4; nt++)
                    MMA_BF16(sg[nt], qh[t], kh[nt]);
                #pragma unroll
                for (int nt = 0; nt < 4; nt++)
                    MMA_BF16(sg[nt], ql[t], kh[nt]);
                #pragma unroll
                for (int nt = 0; nt < 4; nt++)
                    MMA_BF16(sg[nt], qh[t], kl[nt]);
            }
        }

        // ---- mask tail columns ----
        if (kb == nkb - 1) {
            int cb = kb * 128 + c2;
            #pragma unroll
            for (int nt = 0; nt < 16; nt++) {
                int c0g = cb + nt * 8;
                if (c0g     >= vlen) { s[nt][0] = -1e30f; s[nt][2] = -1e30f; }
                if (c0g + 1 >= vlen) { s[nt][1] = -1e30f; s[nt][3] = -1e30f; }
            }
        }

        // ---- online softmax (base-2 domain) ----
        float mx0 = -1e30f, mx1 = -1e30f;
        #pragma unroll
        for (int nt = 0; nt < 16; nt++) {
            mx0 = fmaxf(mx0, fmaxf(s[nt][0], s[nt][1]));
            mx1 = fmaxf(mx1, fmaxf(s[nt][2], s[nt][3]));
        }
        mx0 = fmaxf(mx0, __shfl_xor_sync(0xffffffffu, mx0, 1));
        mx0 = fmaxf(mx0, __shfl_xor_sync(0xffffffffu, mx0, 2));
        mx1 = fmaxf(mx1, __shfl_xor_sync(0xffffffffu, mx1, 1));
        mx1 = fmaxf(mx1, __shfl_xor_sync(0xffffffffu, mx1, 2));

        float mn0 = fmaxf(m_i[0], mx0), mn1 = fmaxf(m_i[1], mx1);
        float a0 = ex2f(m_i[0] - mn0), a1 = ex2f(m_i[1] - mn1);
        m_i[0] = mn0; m_i[1] = mn1;

        float sum0 = 0.f, sum1 = 0.f;
        #pragma unroll
        for (int nt = 0; nt < 16; nt++) {
            s[nt][0] = ex2f(s[nt][0] - mn0); sum0 += s[nt][0];
            s[nt][1] = ex2f(s[nt][1] - mn0); sum0 += s[nt][1];
            s[nt][2] = ex2f(s[nt][2] - mn1); sum1 += s[nt][2];
            s[nt][3] = ex2f(s[nt][3] - mn1); sum1 += s[nt][3];
        }
        sum0 += __shfl_xor_sync(0xffffffffu, sum0, 1);
        sum0 += __shfl_xor_sync(0xffffffffu, sum0, 2);
        sum1 += __shfl_xor_sync(0xffffffffu, sum1, 1);
        sum1 += __shfl_xor_sync(0xffffffffu, sum1, 2);
        l_i[0] = l_i[0] * a0 + sum0;
        l_i[1] = l_i[1] * a1 + sum1;
        #pragma unroll
        for (int nt = 0; nt < 8; nt++) {
            o[nt][0] *= a0; o[nt][1] *= a0;
            o[nt][2] *= a1; o[nt][3] *= a1;
        }

        // ---- O += P V (k = 128, 8 k-chunks of 16) ----
        #pragma unroll
        for (int kc = 0; kc < 8; kc++) {
            uint32_t ph[4], pl[4];
            split2(s[2*kc  ][0], s[2*kc  ][1], ph[0], pl[0]);
            split2(s[2*kc  ][2], s[2*kc  ][3], ph[1], pl[1]);
            split2(s[2*kc+1][0], s[2*kc+1][1], ph[2], pl[2]);
            split2(s[2*kc+1][2], s[2*kc+1][3], ph[3], pl[3]);

            uint32_t vh[8][2], vl[8][2];
            #pragma unroll
            for (int p = 0; p < 4; p++) {
                int rowb = kc * 16 + (lane & 15);
                uint32_t off = rowb * 128 + ((p * 32 + (lane >> 4) * 16) ^ ((rowb & 7) * 16));
                LDSM_X4_T(vh[p*2][0], vh[p*2][1], vh[p*2+1][0], vh[p*2+1][1], vHi + off);
                LDSM_X4_T(vl[p*2][0], vl[p*2][1], vl[p*2+1][0], vl[p*2+1][1], vLo + off);
            }
            #pragma unroll
            for (int nt = 0; nt < 8; nt++)
                MMA_BF16(o[nt], ph, vh[nt]);
            #pragma unroll
            for (int nt = 0; nt < 8; nt++)
                MMA_BF16(o[nt], pl, vh[nt]);
            #pragma unroll
            for (int nt = 0; nt < 8; nt++)
                MMA_BF16(o[nt], ph, vl[nt]);
        }
    }

    // epilogue: write split bf16 [B*S][D]
    const float inv0 = 1.f / l_i[0], inv1 = 1.f / l_i[1];
    const int row0 = qb * 128 + wid * 16 + r;
    const size_t base0 = (size_t)(bb * NS + row0    ) * ND + head * 64;
    const size_t base1 = (size_t)(bb * NS + row0 + 8) * ND + head * 64;
    #pragma unroll
    for (int nt = 0; nt < 8; nt++) {
        uint32_t h0, l0, h1, l1;
        split2(o[nt][0] * inv0, o[nt][1] * inv0, h0, l0);
        split2(o[nt][2] * inv1, o[nt][3] * inv1, h1, l1);
        *(uint32_t*)(g_AOhi + base0 + nt * 8 + c2) = h0;
        *(uint32_t*)(g_AOlo + base0 + nt * 8 + c2) = l0;
        *(uint32_t*)(g_AOhi + base1 + nt * 8 + c2) = h1;
        *(uint32_t*)(g_AOlo + base1 + nt * 8 + c2) = l1;
    }
}

// ---------------------------------------------------------------------------
extern "C" void kernel_launch(void* const* d_in, const int* in_sizes, int n_in,
                              void* d_out, int out_size)
{
    const float* q  = (const float*)d_in[0];
    const float* k  = (const float*)d_in[1];
    const float* v  = (const float*)d_in[2];
    const int*   vl = (const int*)  d_in[3];
    const float* Wq = (const float*)d_in[4];
    const float* Wk = (const float*)d_in[5];
    const float* Wv = (const float*)d_in[6];
    const float* Wo = (const float*)d_in[7];
    float* out = (float*)d_out;

    cudaFuncSetAttribute(gemm_mma_kernel, cudaFuncAttributeMaxDynamicSharedMemorySize,
                         GEMM_SMEM);
    cudaFuncSetAttribute(attn_mma_kernel, cudaFuncAttributeMaxDynamicSharedMemorySize,
                         ATT_SMEM);

    splitx_kernel<<<dim3(4096, 3), 256>>>(q, k, v);
    wsplit_kernel<<<dim3(32, 32, 4), 256>>>(Wq, Wk, Wv, Wo);

    gemm_mma_kernel<<<dim3(ND / 128, (NB * NS) / 256, 3), 512, GEMM_SMEM>>>(out, 0);

    attn_mma_kernel<<<dim3(NS / 128, NB * NH), 256, ATT_SMEM>>>(vl);

    gemm_mma_kernel<<<dim3(ND / 128, (NB * NS) / 256, 1), 512, GEMM_SMEM>>>(out, 1);
}

// round 8
// speedup vs baseline: 1.0647x; 1.0647x over previous
#include <cuda_runtime.h>
#include <cuda_bf16.h>
#include <cuda_fp16.h>
#include <stdint.h>

#define NB  2
#define NS  2048
#define ND  1024
#define NH  16
#define NDH 64

// Scratch (allocation-free rule: __device__ globals).
__device__ __nv_bfloat16 g_Whi[4u << 20];     // 4 x W^T hi: [n][k] k-major
__device__ __nv_bfloat16 g_Wlo[4u << 20];     // 4 x W^T lo
__device__ __nv_bfloat16 g_Xhi[3u << 22], g_Xlo[3u << 22];   // split Xq/Xk/Xv [4096][1024]
__device__ __nv_bfloat16 g_AOhi[1u << 22], g_AOlo[1u << 22]; // split attn out [4096][1024]
// Q/K split bf16, V split fp16, head-major [B,H,S,DH]
__device__ __nv_bfloat16 g_Qhi[NB*NH*NS*NDH], g_Qlo[NB*NH*NS*NDH];
__device__ __nv_bfloat16 g_Khi[NB*NH*NS*NDH], g_Klo[NB*NH*NS*NDH];
__device__ __half        g_Vh16[NB*NH*NS*NDH], g_Vl16[NB*NH*NS*NDH];

// ---------------------------------------------------------------------------
// helpers
// ---------------------------------------------------------------------------
__device__ __forceinline__ uint32_t smem_u32(const void* p) {
    uint32_t a;
    asm("{ .reg .u64 t; cvta.to.shared.u64 t, %1; cvt.u32.u64 %0, t; }" : "=r"(a) : "l"(p));
    return a;
}
__device__ __forceinline__ void cpasync16(uint32_t dst, const void* src) {
    asm volatile("cp.async.cg.shared.global [%0], [%1], 16;" :: "r"(dst), "l"(src));
}
#define CP_COMMIT() asm volatile("cp.async.commit_group;" ::: "memory")
#define CP_WAIT0()  asm volatile("cp.async.wait_group 0;" ::: "memory")
#define CP_WAIT1()  asm volatile("cp.async.wait_group 1;" ::: "memory")

#define LDSM_X4(r0, r1, r2, r3, addr)                                          \
    asm volatile("ldmatrix.sync.aligned.m8n8.x4.shared.b16 {%0,%1,%2,%3}, [%4];" \
        : "=r"(r0), "=r"(r1), "=r"(r2), "=r"(r3) : "r"(addr))
#define LDSM_X4_T(r0, r1, r2, r3, addr)                                        \
    asm volatile("ldmatrix.sync.aligned.m8n8.x4.trans.shared.b16 {%0,%1,%2,%3}, [%4];" \
        : "=r"(r0), "=r"(r1), "=r"(r2), "=r"(r3) : "r"(addr))

#define MMA_BF16(d, a, b)                                                      \
    asm volatile("mma.sync.aligned.m16n8k16.row.col.f32.bf16.bf16.f32 "        \
        "{%0,%1,%2,%3},{%4,%5,%6,%7},{%8,%9},{%0,%1,%2,%3};"                   \
        : "+f"((d)[0]), "+f"((d)[1]), "+f"((d)[2]), "+f"((d)[3])               \
        : "r"((a)[0]), "r"((a)[1]), "r"((a)[2]), "r"((a)[3]),                  \
          "r"((b)[0]), "r"((b)[1]))

#define MMA_F16(d, a, b)                                                       \
    asm volatile("mma.sync.aligned.m16n8k16.row.col.f32.f16.f16.f32 "          \
        "{%0,%1,%2,%3},{%4,%5,%6,%7},{%8,%9},{%0,%1,%2,%3};"                   \
        : "+f"((d)[0]), "+f"((d)[1]), "+f"((d)[2]), "+f"((d)[3])               \
        : "r"((a)[0]), "r"((a)[1]), "r"((a)[2]), "r"((a)[3]),                  \
          "r"((b)[0]), "r"((b)[1]))

__device__ __forceinline__ float ex2f(float x) {
    float y; asm("ex2.approx.f32 %0, %1;" : "=f"(y) : "f"(x)); return y;
}
__device__ __forceinline__ uint32_t h2pack(float a, float b) {
    __half2 h = __floats2half2_rn(a, b);
    return *(uint32_t*)&h;
}

__device__ __forceinline__ void split2(float a, float b, uint32_t& hi, uint32_t& lo) {
    __nv_bfloat16 ha = __float2bfloat16(a), hb = __float2bfloat16(b);
    float ra = a - __bfloat162float(ha), rb = b - __bfloat162float(hb);
    hi = (uint32_t)__bfloat16_as_ushort(ha) | ((uint32_t)__bfloat16_as_ushort(hb) << 16);
    __nv_bfloat16 la = __float2bfloat16(ra), lb = __float2bfloat16(rb);
    lo = (uint32_t)__bfloat16_as_ushort(la) | ((uint32_t)__bfloat16_as_ushort(lb) << 16);
}
__device__ __forceinline__ void splitH2(float a, float b, uint32_t& hi, uint32_t& lo) {
    __half ha = __float2half_rn(a), hb = __float2half_rn(b);
    float ra = a - __half2float(ha), rb = b - __half2float(hb);
    __half2 h = __halves2half2(ha, hb);
    __half2 l = __floats2half2_rn(ra, rb);
    hi = *(uint32_t*)&h; lo = *(uint32_t*)&l;
}

// ---------------------------------------------------------------------------
// X split: fp32 -> bf16 hi/lo, row-major passthrough.
// ---------------------------------------------------------------------------
__global__ __launch_bounds__(256) void splitx_kernel(
    const float* __restrict__ X0, const float* __restrict__ X1,
    const float* __restrict__ X2)
{
    const int z = blockIdx.y;
    const float* X = (z == 0) ? X0 : (z == 1) ? X1 : X2;
    __nv_bfloat16* Ohi = g_Xhi + ((size_t)z << 22);
    __nv_bfloat16* Olo = g_Xlo + ((size_t)z << 22);
    size_t idx = (size_t)blockIdx.x * 256 + threadIdx.x;
    float4 v = *((const float4*)X + idx);
    uint2 hi, lo;
    split2(v.x, v.y, hi.x, lo.x);
    split2(v.z, v.w, hi.y, lo.y);
    *((uint2*)Ohi + idx) = hi;
    *((uint2*)Olo + idx) = lo;
}

// ---------------------------------------------------------------------------
// W transpose + split. Out[n][k] = W[k][n].
// ---------------------------------------------------------------------------
__global__ __launch_bounds__(256) void wsplit_kernel(
    const float* __restrict__ W0, const float* __restrict__ W1,
    const float* __restrict__ W2, const float* __restrict__ W3)
{
    __shared__ float t[32][33];
    const float* W = (blockIdx.z == 0) ? W0 : (blockIdx.z == 1) ? W1 :
                     (blockIdx.z == 2) ? W2 : W3;
    __nv_bfloat16* Ohi = g_Whi + ((size_t)blockIdx.z << 20);
    __nv_bfloat16* Olo = g_Wlo + ((size_t)blockIdx.z << 20);

    int tx = threadIdx.x & 31, ty = threadIdx.x >> 5;
    int n0 = blockIdx.x * 32, k0 = blockIdx.y * 32;

    #pragma unroll
    for (int i = 0; i < 4; i++)
        t[ty + i*8][tx] = W[(size_t)(k0 + ty + i*8) * ND + n0 + tx];
    __syncthreads();
    #pragma unroll
    for (int i = 0; i < 4; i++) {
        float v = t[tx][ty + i*8];
        __nv_bfloat16 h = __float2bfloat16(v);
        __nv_bfloat16 l = __float2bfloat16(v - __bfloat162float(h));
        size_t idx = (size_t)(n0 + ty + i*8) * ND + k0 + tx;
        Ohi[idx] = h; Olo[idx] = l;
    }
}

// ---------------------------------------------------------------------------
// HMMA split-bf16 GEMM, all-cp.async. CTA 256M x 128N, BK=64, 512 threads.
// mode 0: z=0 -> Q (bf16 split, scaled 0.125*log2e), z=1 -> K (bf16 split),
//         z=2 -> V (fp16 split). mode 1: fp32 out.
// ---------------------------------------------------------------------------
#define GBUF   98304
#define G_AHI  0
#define G_ALO  32768
#define G_BHI  65536
#define G_BLO  81920
#define GEMM_SMEM (2 * GBUF)

__global__ __launch_bounds__(512, 1) void gemm_mma_kernel(float* __restrict__ Cout, int mode)
{
    extern __shared__ char smc[];
    const uint32_t sb = smem_u32(smc);
    const int tid  = threadIdx.x;
    const int wid  = tid >> 5, lane = tid & 31;
    const int z    = blockIdx.z;

    const __nv_bfloat16 *Ahi_g, *Alo_g, *Whi, *Wlo;
    void *Ohi = 0, *Olo = 0;
    float osc = 1.f;
    if (mode == 0) {
        Ahi_g = g_Xhi + ((size_t)z << 22);
        Alo_g = g_Xlo + ((size_t)z << 22);
        Whi = g_Whi + ((size_t)z << 20);
        Wlo = g_Wlo + ((size_t)z << 20);
        Ohi = (z == 0) ? (void*)g_Qhi : (z == 1) ? (void*)g_Khi : (void*)g_Vh16;
        Olo = (z == 0) ? (void*)g_Qlo : (z == 1) ? (void*)g_Klo : (void*)g_Vl16;
        if (z == 0) osc = 0.125f * 1.44269504f;   // fold log2(e) for exp2 softmax
    } else {
        Ahi_g = g_AOhi; Alo_g = g_AOlo;
        Whi = g_Whi + ((size_t)3 << 20);
        Wlo = g_Wlo + ((size_t)3 << 20);
    }
    const int bM = blockIdx.y * 256, bN = blockIdx.x * 128;
    const int warp_m = (wid & 7) * 32, warp_n = (wid >> 3) * 64;

    float acc[16][4];
    #pragma unroll
    for (int i = 0; i < 16; i++)
        #pragma unroll
        for (int j = 0; j < 4; j++) acc[i][j] = 0.f;

    auto cpStage = [&](int s, int buf) {
        uint32_t base = sb + buf * GBUF;
        #pragma unroll
        for (int l = 0; l < 12; l++) {
            int f = tid + l * 512;
            const __nv_bfloat16* src;
            uint32_t dst;
            if (f < 4096) {
                int arr = f >> 11;
                int r = (f >> 3) & 255, c = f & 7;
                src = (arr ? Alo_g : Ahi_g) + (size_t)(bM + r) * ND + s * 64 + c * 8;
                dst = base + (arr ? G_ALO : G_AHI) + r * 128 + ((c * 16) ^ ((r & 7) * 16));
            } else {
                int g = f - 4096;
                int arr = g >> 10;
                int r = (g >> 3) & 127, c = g & 7;
                src = (arr ? Wlo : Whi) + (size_t)(bN + r) * ND + s * 64 + c * 8;
                dst = base + (arr ? G_BLO : G_BHI) + r * 128 + ((c * 16) ^ ((r & 7) * 16));
            }
            cpasync16(dst, src);
        }
        CP_COMMIT();
    };

    cpStage(0, 0);

    for (int s = 0; s < 16; s++) {
        const int buf = s & 1;
        if (s + 1 < 16) { cpStage(s + 1, buf ^ 1); CP_WAIT1(); }
        else            { CP_WAIT0(); }
        __syncthreads();

        const uint32_t aHi = sb + buf * GBUF + G_AHI;
        const uint32_t aLo = sb + buf * GBUF + G_ALO;
        const uint32_t bHi = sb + buf * GBUF + G_BHI;
        const uint32_t bLo = sb + buf * GBUF + G_BLO;

        #pragma unroll
        for (int kk = 0; kk < 4; kk++) {
            const int k0 = kk * 16;
            uint32_t ah[2][4], al[2][4];
            #pragma unroll
            for (int mt = 0; mt < 2; mt++) {
                int row = warp_m + mt * 16 + (lane & 15);
                uint32_t off = row * 128 + ((k0 * 2 + (lane >> 4) * 16) ^ ((row & 7) * 16));
                LDSM_X4(ah[mt][0], ah[mt][1], ah[mt][2], ah[mt][3], aHi + off);
                LDSM_X4(al[mt][0], al[mt][1], al[mt][2], al[mt][3], aLo + off);
            }
            #pragma unroll
            for (int h = 0; h < 2; h++) {
                uint32_t bh[4][2], bl[4][2];
                #pragma unroll
                for (int p = 0; p < 2; p++) {
                    int n = warp_n + h * 32 + p * 16 + (lane & 7) + ((lane >> 4) << 3);
                    uint32_t off = n * 128 + ((k0 * 2 + ((lane >> 3) & 1) * 16) ^ ((n & 7) * 16));
                    LDSM_X4(bh[p*2][0], bh[p*2][1], bh[p*2+1][0], bh[p*2+1][1], bHi + off);
                    LDSM_X4(bl[p*2][0], bl[p*2][1], bl[p*2+1][0], bl[p*2+1][1], bLo + off);
                }
                #pragma unroll
                for (int mt = 0; mt < 2; mt++)
                    #pragma unroll
                    for (int nt = 0; nt < 4; nt++)
                        MMA_BF16(acc[mt*8 + h*4 + nt], ah[mt], bh[nt]);
                #pragma unroll
                for (int mt = 0; mt < 2; mt++)
                    #pragma unroll
                    for (int nt = 0; nt < 4; nt++)
                        MMA_BF16(acc[mt*8 + h*4 + nt], ah[mt], bl[nt]);
                #pragma unroll
                for (int mt = 0; mt < 2; mt++)
                    #pragma unroll
                    for (int nt = 0; nt < 4; nt++)
                        MMA_BF16(acc[mt*8 + h*4 + nt], al[mt], bh[nt]);
            }
        }
        __syncthreads();
    }

    #pragma unroll
    for (int mt = 0; mt < 2; mt++)
        #pragma unroll
        for (int nt = 0; nt < 8; nt++) {
            int m0 = bM + warp_m + mt * 16 + (lane >> 2);
            int n  = bN + warp_n + nt * 8 + (lane & 3) * 2;
            float* a4 = acc[mt*8+nt];
            if (mode == 0) {
                int h = n >> 6, dh = n & 63;
                int b0 = m0 >> 11, s0 = m0 & 2047;
                int m1 = m0 + 8, b1 = m1 >> 11, s1 = m1 & 2047;
                size_t i0 = ((size_t)(b0 * NH + h) * NS + s0) * NDH + dh;
                size_t i1 = ((size_t)(b1 * NH + h) * NS + s1) * NDH + dh;
                uint32_t h0, l0, h1, l1;
                if (z == 2) {
                    splitH2(a4[0], a4[1], h0, l0);
                    splitH2(a4[2], a4[3], h1, l1);
                } else {
                    split2(a4[0] * osc, a4[1] * osc, h0, l0);
                    split2(a4[2] * osc, a4[3] * osc, h1, l1);
                }
                *(uint32_t*)((uint16_t*)Ohi + i0) = h0; *(uint32_t*)((uint16_t*)Olo + i0) = l0;
                *(uint32_t*)((uint16_t*)Ohi + i1) = h1; *(uint32_t*)((uint16_t*)Olo + i1) = l1;
            } else {
                *(float2*)(Cout + (size_t)m0 * ND + n)       = make_float2(a4[0], a4[1]);
                *(float2*)(Cout + (size_t)(m0 + 8) * ND + n) = make_float2(a4[2], a4[3]);
            }
        }
}

// ---------------------------------------------------------------------------
// Flash attention on HMMA. QK: 3-pass split-bf16. PV: 2-pass fp16 (P single
// fp16, V fp16 hi/lo). exp2-domain softmax (Q pre-scaled by 0.125*log2e).
// CTA = 128 q x 64 k, 8 warps, double-buffered K/V (64KB).
// ---------------------------------------------------------------------------
#define ATT_BUF  32768
#define ATT_SMEM (2 * ATT_BUF)

__global__ __launch_bounds__(256, 1) void attn_mma_kernel(const int* __restrict__ valid_lens)
{
    extern __shared__ char smc[];
    const uint32_t sb = smem_u32(smc);
    const int tid = threadIdx.x, wid = tid >> 5, lane = tid & 31;
    const int qb = blockIdx.x, bh = blockIdx.y;
    const int bb = bh >> 4, head = bh & 15;
    const int vlen = valid_lens[bb];
    const int nkb  = (vlen + 63) >> 6;

    const size_t hbase = (size_t)bh * NS * NDH;
    const __nv_bfloat16 *Qhi = g_Qhi + hbase, *Qlo = g_Qlo + hbase;
    const __nv_bfloat16 *Khi = g_Khi + hbase, *Klo = g_Klo + hbase;
    const __half        *Vh16 = g_Vh16 + hbase, *Vl16 = g_Vl16 + hbase;

    const int r = lane >> 2, c2 = (lane & 3) * 2;

    uint32_t qh[4][4], ql[4][4];
    {
        const int q0 = qb * 128 + wid * 16;
        #pragma unroll
        for (int t = 0; t < 4; t++) {
            int k0 = t * 16;
            qh[t][0] = *(const uint32_t*)(Qhi + (size_t)(q0 + r    ) * NDH + k0 + c2);
            qh[t][1] = *(const uint32_t*)(Qhi + (size_t)(q0 + r + 8) * NDH + k0 + c2);
            qh[t][2] = *(const uint32_t*)(Qhi + (size_t)(q0 + r    ) * NDH + k0 + c2 + 8);
            qh[t][3] = *(const uint32_t*)(Qhi + (size_t)(q0 + r + 8) * NDH + k0 + c2 + 8);
            ql[t][0] = *(const uint32_t*)(Qlo + (size_t)(q0 + r    ) * NDH + k0 + c2);
            ql[t][1] = *(const uint32_t*)(Qlo + (size_t)(q0 + r + 8) * NDH + k0 + c2);
            ql[t][2] = *(const uint32_t*)(Qlo + (size_t)(q0 + r    ) * NDH + k0 + c2 + 8);
            ql[t][3] = *(const uint32_t*)(Qlo + (size_t)(q0 + r + 8) * NDH + k0 + c2 + 8);
        }
    }

    float m_i[2] = {-1e30f, -1e30f}, l_i[2] = {0.f, 0.f};
    float o[8][4];
    #pragma unroll
    for (int i = 0; i < 8; i++)
        #pragma unroll
        for (int j = 0; j < 4; j++) o[i][j] = 0.f;

    auto cpKV = [&](int kb, int buf) {
        #pragma unroll
        for (int l = 0; l < 8; l++) {
            int f   = tid + l * 256;
            int arr = f >> 9;                 // 0:Khi 1:Klo 2:Vh16 3:Vl16
            int rr  = (f >> 3) & 63;
            int cc  = f & 7;
            const void* src;
            if (arr == 0)      src = Khi  + (size_t)(kb * 64 + rr) * NDH + cc * 8;
            else if (arr == 1) src = Klo  + (size_t)(kb * 64 + rr) * NDH + cc * 8;
            else if (arr == 2) src = Vh16 + (size_t)(kb * 64 + rr) * NDH + cc * 8;
            else               src = Vl16 + (size_t)(kb * 64 + rr) * NDH + cc * 8;
            uint32_t dst = sb + buf * ATT_BUF + arr * 8192
                         + rr * 128 + ((cc * 16) ^ ((rr & 7) * 16));
            cpasync16(dst, src);
        }
        CP_COMMIT();
    };

    cpKV(0, 0);

    for (int kb = 0; kb < nkb; kb++) {
        const int buf = kb & 1;
        CP_WAIT0();
        __syncthreads();
        if (kb + 1 < nkb) cpKV(kb + 1, buf ^ 1);

        const uint32_t kHi = sb + buf * ATT_BUF;
        const uint32_t kLo = kHi + 8192;
        const uint32_t vHi = kHi + 16384;
        const uint32_t vLo = kHi + 24576;

        // ---- S = Q K^T (3-pass split-bf16) ----
        float s[8][4];
        #pragma unroll
        for (int i = 0; i < 8; i++)
            #pragma unroll
            for (int j = 0; j < 4; j++) s[i][j] = 0.f;

        #pragma unroll
        for (int t = 0; t < 4; t++) {
            uint32_t kh[8][2], kl[8][2];
            #pragma unroll
            for (int p = 0; p < 4; p++) {
                int n = p * 16 + (lane & 7) + ((lane >> 4) << 3);
                uint32_t off = n * 128 + ((t * 32 + ((lane >> 3) & 1) * 16) ^ ((n & 7) * 16));
                LDSM_X4(kh[p*2][0], kh[p*2][1], kh[p*2+1][0], kh[p*2+1][1], kHi + off);
                LDSM_X4(kl[p*2][0], kl[p*2][1], kl[p*2+1][0], kl[p*2+1][1], kLo + off);
            }
            #pragma unroll
            for (int nt = 0; nt < 8; nt++)
                MMA_BF16(s[nt], qh[t], kh[nt]);
            #pragma unroll
            for (int nt = 0; nt < 8; nt++)
                MMA_BF16(s[nt], ql[t], kh[nt]);
            #pragma unroll
            for (int nt = 0; nt < 8; nt++)
                MMA_BF16(s[nt], qh[t], kl[nt]);
        }

        if (kb == nkb - 1) {
            int cb = kb * 64 + c2;
            #pragma unroll
            for (int nt = 0; nt < 8; nt++) {
                int c0g = cb + nt * 8;
                if (c0g     >= vlen) { s[nt][0] = -1e30f; s[nt][2] = -1e30f; }
                if (c0g + 1 >= vlen) { s[nt][1] = -1e30f; s[nt][3] = -1e30f; }
            }
        }

        // ---- online softmax (base-2 domain) ----
        float mx0 = -1e30f, mx1 = -1e30f;
        #pragma unroll
        for (int nt = 0; nt < 8; nt++) {
            mx0 = fmaxf(mx0, fmaxf(s[nt][0], s[nt][1]));
            mx1 = fmaxf(mx1, fmaxf(s[nt][2], s[nt][3]));
        }
        mx0 = fmaxf(mx0, __shfl_xor_sync(0xffffffffu, mx0, 1));
        mx0 = fmaxf(mx0, __shfl_xor_sync(0xffffffffu, mx0, 2));
        mx1 = fmaxf(mx1, __shfl_xor_sync(0xffffffffu, mx1, 1));
        mx1 = fmaxf(mx1, __shfl_xor_sync(0xffffffffu, mx1, 2));

        float mn0 = fmaxf(m_i[0], mx0), mn1 = fmaxf(m_i[1], mx1);
        float a0 = ex2f(m_i[0] - mn0), a1 = ex2f(m_i[1] - mn1);
        m_i[0] = mn0; m_i[1] = mn1;

        float sum0 = 0.f, sum1 = 0.f;
        #pragma unroll
        for (int nt = 0; nt < 8; nt++) {
            s[nt][0] = ex2f(s[nt][0] - mn0); sum0 += s[nt][0];
            s[nt][1] = ex2f(s[nt][1] - mn0); sum0 += s[nt][1];
            s[nt][2] = ex2f(s[nt][2] - mn1); sum1 += s[nt][2];
            s[nt][3] = ex2f(s[nt][3] - mn1); sum1 += s[nt][3];
        }
        sum0 += __shfl_xor_sync(0xffffffffu, sum0, 1);
        sum0 += __shfl_xor_sync(0xffffffffu, sum0, 2);
        sum1 += __shfl_xor_sync(0xffffffffu, sum1, 1);
        sum1 += __shfl_xor_sync(0xffffffffu, sum1, 2);
        l_i[0] = l_i[0] * a0 + sum0;
        l_i[1] = l_i[1] * a1 + sum1;
        #pragma unroll
        for (int nt = 0; nt < 8; nt++) {
            o[nt][0] *= a0; o[nt][1] *= a0;
            o[nt][2] *= a1; o[nt][3] *= a1;
        }

        // ---- O += P V (2-pass fp16: P single, V hi/lo) ----
        #pragma unroll
        for (int t = 0; t < 4; t++) {
            uint32_t ph[4];
            ph[0] = h2pack(s[2*t  ][0], s[2*t  ][1]);
            ph[1] = h2pack(s[2*t  ][2], s[2*t  ][3]);
            ph[2] = h2pack(s[2*t+1][0], s[2*t+1][1]);
            ph[3] = h2pack(s[2*t+1][2], s[2*t+1][3]);

            uint32_t vh[8][2], vl[8][2];
            #pragma unroll
            for (int p = 0; p < 4; p++) {
                int rowb = t * 16 + (lane & 15);
                uint32_t off = rowb * 128 + ((p * 32 + (lane >> 4) * 16) ^ ((rowb & 7) * 16));
                LDSM_X4_T(vh[p*2][0], vh[p*2][1], vh[p*2+1][0], vh[p*2+1][1], vHi + off);
                LDSM_X4_T(vl[p*2][0], vl[p*2][1], vl[p*2+1][0], vl[p*2+1][1], vLo + off);
            }
            #pragma unroll
            for (int nt = 0; nt < 8; nt++)
                MMA_F16(o[nt], ph, vh[nt]);
            #pragma unroll
            for (int nt = 0; nt < 8; nt++)
                MMA_F16(o[nt], ph, vl[nt]);
        }
    }

    // epilogue: write split bf16 [B*S][D] for the Wo GEMM
    const float inv0 = 1.f / l_i[0], inv1 = 1.f / l_i[1];
    const int row0 = qb * 128 + wid * 16 + r;
    const size_t base0 = (size_t)(bb * NS + row0    ) * ND + head * 64;
    const size_t base1 = (size_t)(bb * NS + row0 + 8) * ND + head * 64;
    #pragma unroll
    for (int nt = 0; nt < 8; nt++) {
        uint32_t h0, l0, h1, l1;
        split2(o[nt][0] * inv0, o[nt][1] * inv0, h0, l0);
        split2(o[nt][2] * inv1, o[nt][3] * inv1, h1, l1);
        *(uint32_t*)(g_AOhi + base0 + nt * 8 + c2) = h0;
        *(uint32_t*)(g_AOlo + base0 + nt * 8 + c2) = l0;
        *(uint32_t*)(g_AOhi + base1 + nt * 8 + c2) = h1;
        *(uint32_t*)(g_AOlo + base1 + nt * 8 + c2) = l1;
    }
}

// ---------------------------------------------------------------------------
extern "C" void kernel_launch(void* const* d_in, const int* in_sizes, int n_in,
                              void* d_out, int out_size)
{
    const float* q  = (const float*)d_in[0];
    const float* k  = (const float*)d_in[1];
    const float* v  = (const float*)d_in[2];
    const int*   vl = (const int*)  d_in[3];
    const float* Wq = (const float*)d_in[4];
    const float* Wk = (const float*)d_in[5];
    const float* Wv = (const float*)d_in[6];
    const float* Wo = (const float*)d_in[7];
    float* out = (float*)d_out;

    cudaFuncSetAttribute(gemm_mma_kernel, cudaFuncAttributeMaxDynamicSharedMemorySize,
                         GEMM_SMEM);
    cudaFuncSetAttribute(attn_mma_kernel, cudaFuncAttributeMaxDynamicSharedMemorySize,
                         ATT_SMEM);

    splitx_kernel<<<dim3(4096, 3), 256>>>(q, k, v);
    wsplit_kernel<<<dim3(32, 32, 4), 256>>>(Wq, Wk, Wv, Wo);

    gemm_mma_kernel<<<dim3(ND / 128, (NB * NS) / 256, 3), 512, GEMM_SMEM>>>(out, 0);

    attn_mma_kernel<<<dim3(NS / 128, NB * NH), 256, ATT_SMEM>>>(vl);

    gemm_mma_kernel<<<dim3(ND / 128, (NB * NS) / 256, 1), 512, GEMM_SMEM>>>(out, 1);
}

// round 9
// speedup vs baseline: 1.1533x; 1.0832x over previous
#include <cuda_runtime.h>
#include <cuda_bf16.h>
#include <cuda_fp16.h>
#include <stdint.h>

#define NB  2
#define NS  2048
#define ND  1024
#define NH  16
#define NDH 64

// Scratch (allocation-free rule: __device__ globals).
__device__ __nv_bfloat16 g_Whi[4u << 20];     // 4 x W^T hi: [n][k] k-major
__device__ __nv_bfloat16 g_Wlo[4u << 20];     // 4 x W^T lo
__device__ __nv_bfloat16 g_Xhi[3u << 22], g_Xlo[3u << 22];   // split Xq/Xk/Xv [4096][1024]
__device__ __nv_bfloat16 g_AOhi[1u << 22], g_AOlo[1u << 22]; // split attn out [4096][1024]
// head-major [B,H,S,DH]: Q split fp16 hi/lo, K single fp16, V single fp16
__device__ __half g_Qh16[NB*NH*NS*NDH], g_Ql16[NB*NH*NS*NDH];
__device__ __half g_K16 [NB*NH*NS*NDH];
__device__ __half g_V16 [NB*NH*NS*NDH];

// ---------------------------------------------------------------------------
// helpers
// ---------------------------------------------------------------------------
__device__ __forceinline__ uint32_t smem_u32(const void* p) {
    uint32_t a;
    asm("{ .reg .u64 t; cvta.to.shared.u64 t, %1; cvt.u32.u64 %0, t; }" : "=r"(a) : "l"(p));
    return a;
}
__device__ __forceinline__ void cpasync16(uint32_t dst, const void* src) {
    asm volatile("cp.async.cg.shared.global [%0], [%1], 16;" :: "r"(dst), "l"(src));
}
#define CP_COMMIT() asm volatile("cp.async.commit_group;" ::: "memory")
#define CP_WAIT0()  asm volatile("cp.async.wait_group 0;" ::: "memory")
#define CP_WAIT1()  asm volatile("cp.async.wait_group 1;" ::: "memory")

#define LDSM_X4(r0, r1, r2, r3, addr)                                          \
    asm volatile("ldmatrix.sync.aligned.m8n8.x4.shared.b16 {%0,%1,%2,%3}, [%4];" \
        : "=r"(r0), "=r"(r1), "=r"(r2), "=r"(r3) : "r"(addr))
#define LDSM_X4_T(r0, r1, r2, r3, addr)                                        \
    asm volatile("ldmatrix.sync.aligned.m8n8.x4.trans.shared.b16 {%0,%1,%2,%3}, [%4];" \
        : "=r"(r0), "=r"(r1), "=r"(r2), "=r"(r3) : "r"(addr))

#define MMA_BF16(d, a, b)                                                      \
    asm volatile("mma.sync.aligned.m16n8k16.row.col.f32.bf16.bf16.f32 "        \
        "{%0,%1,%2,%3},{%4,%5,%6,%7},{%8,%9},{%0,%1,%2,%3};"                   \
        : "+f"((d)[0]), "+f"((d)[1]), "+f"((d)[2]), "+f"((d)[3])               \
        : "r"((a)[0]), "r"((a)[1]), "r"((a)[2]), "r"((a)[3]),                  \
          "r"((b)[0]), "r"((b)[1]))

#define MMA_F16(d, a, b)                                                       \
    asm volatile("mma.sync.aligned.m16n8k16.row.col.f32.f16.f16.f32 "          \
        "{%0,%1,%2,%3},{%4,%5,%6,%7},{%8,%9},{%0,%1,%2,%3};"                   \
        : "+f"((d)[0]), "+f"((d)[1]), "+f"((d)[2]), "+f"((d)[3])               \
        : "r"((a)[0]), "r"((a)[1]), "r"((a)[2]), "r"((a)[3]),                  \
          "r"((b)[0]), "r"((b)[1]))

__device__ __forceinline__ float ex2f(float x) {
    float y; asm("ex2.approx.f32 %0, %1;" : "=f"(y) : "f"(x)); return y;
}
__device__ __forceinline__ uint32_t h2pack(float a, float b) {
    __half2 h = __floats2half2_rn(a, b);
    return *(uint32_t*)&h;
}

__device__ __forceinline__ void split2(float a, float b, uint32_t& hi, uint32_t& lo) {
    __nv_bfloat16 ha = __float2bfloat16(a), hb = __float2bfloat16(b);
    float ra = a - __bfloat162float(ha), rb = b - __bfloat162float(hb);
    hi = (uint32_t)__bfloat16_as_ushort(ha) | ((uint32_t)__bfloat16_as_ushort(hb) << 16);
    __nv_bfloat16 la = __float2bfloat16(ra), lb = __float2bfloat16(rb);
    lo = (uint32_t)__bfloat16_as_ushort(la) | ((uint32_t)__bfloat16_as_ushort(lb) << 16);
}
__device__ __forceinline__ void splitH2(float a, float b, uint32_t& hi, uint32_t& lo) {
    __half ha = __float2half_rn(a), hb = __float2half_rn(b);
    float ra = a - __half2float(ha), rb = b - __half2float(hb);
    __half2 h = __halves2half2(ha, hb);
    __half2 l = __floats2half2_rn(ra, rb);
    hi = *(uint32_t*)&h; lo = *(uint32_t*)&l;
}

// ---------------------------------------------------------------------------
// X split: fp32 -> bf16 hi/lo, row-major passthrough.
// ---------------------------------------------------------------------------
__global__ __launch_bounds__(256) void splitx_kernel(
    const float* __restrict__ X0, const float* __restrict__ X1,
    const float* __restrict__ X2)
{
    const int z = blockIdx.y;
    const float* X = (z == 0) ? X0 : (z == 1) ? X1 : X2;
    __nv_bfloat16* Ohi = g_Xhi + ((size_t)z << 22);
    __nv_bfloat16* Olo = g_Xlo + ((size_t)z << 22);
    size_t idx = (size_t)blockIdx.x * 256 + threadIdx.x;
    float4 v = *((const float4*)X + idx);
    uint2 hi, lo;
    split2(v.x, v.y, hi.x, lo.x);
    split2(v.z, v.w, hi.y, lo.y);
    *((uint2*)Ohi + idx) = hi;
    *((uint2*)Olo + idx) = lo;
}

// ---------------------------------------------------------------------------
// W transpose + split. Out[n][k] = W[k][n].
// ---------------------------------------------------------------------------
__global__ __launch_bounds__(256) void wsplit_kernel(
    const float* __restrict__ W0, const float* __restrict__ W1,
    const float* __restrict__ W2, const float* __restrict__ W3)
{
    __shared__ float t[32][33];
    const float* W = (blockIdx.z == 0) ? W0 : (blockIdx.z == 1) ? W1 :
                     (blockIdx.z == 2) ? W2 : W3;
    __nv_bfloat16* Ohi = g_Whi + ((size_t)blockIdx.z << 20);
    __nv_bfloat16* Olo = g_Wlo + ((size_t)blockIdx.z << 20);

    int tx = threadIdx.x & 31, ty = threadIdx.x >> 5;
    int n0 = blockIdx.x * 32, k0 = blockIdx.y * 32;

    #pragma unroll
    for (int i = 0; i < 4; i++)
        t[ty + i*8][tx] = W[(size_t)(k0 + ty + i*8) * ND + n0 + tx];
    __syncthreads();
    #pragma unroll
    for (int i = 0; i < 4; i++) {
        float v = t[tx][ty + i*8];
        __nv_bfloat16 h = __float2bfloat16(v);
        __nv_bfloat16 l = __float2bfloat16(v - __bfloat162float(h));
        size_t idx = (size_t)(n0 + ty + i*8) * ND + k0 + tx;
        Ohi[idx] = h; Olo[idx] = l;
    }
}

// ---------------------------------------------------------------------------
// HMMA split-bf16 GEMM, all-cp.async. CTA 256M x 128N, BK=64, 512 threads.
// mode 0: z=0 -> Q (fp16 hi/lo, scaled 0.125*log2e), z=1 -> K (single fp16),
//         z=2 -> V (single fp16). mode 1: fp32 out.
// ---------------------------------------------------------------------------
#define GBUF   98304
#define G_AHI  0
#define G_ALO  32768
#define G_BHI  65536
#define G_BLO  81920
#define GEMM_SMEM (2 * GBUF)

__global__ __launch_bounds__(512, 1) void gemm_mma_kernel(float* __restrict__ Cout, int mode)
{
    extern __shared__ char smc[];
    const uint32_t sb = smem_u32(smc);
    const int tid  = threadIdx.x;
    const int wid  = tid >> 5, lane = tid & 31;
    const int z    = blockIdx.z;

    const __nv_bfloat16 *Ahi_g, *Alo_g, *Whi, *Wlo;
    float osc = 1.f;
    if (mode == 0) {
        Ahi_g = g_Xhi + ((size_t)z << 22);
        Alo_g = g_Xlo + ((size_t)z << 22);
        Whi = g_Whi + ((size_t)z << 20);
        Wlo = g_Wlo + ((size_t)z << 20);
        if (z == 0) osc = 0.125f * 1.44269504f;   // fold log2(e) for exp2 softmax
    } else {
        Ahi_g = g_AOhi; Alo_g = g_AOlo;
        Whi = g_Whi + ((size_t)3 << 20);
        Wlo = g_Wlo + ((size_t)3 << 20);
    }
    const int bM = blockIdx.y * 256, bN = blockIdx.x * 128;
    const int warp_m = (wid & 7) * 32, warp_n = (wid >> 3) * 64;

    float acc[16][4];
    #pragma unroll
    for (int i = 0; i < 16; i++)
        #pragma unroll
        for (int j = 0; j < 4; j++) acc[i][j] = 0.f;

    auto cpStage = [&](int s, int buf) {
        uint32_t base = sb + buf * GBUF;
        #pragma unroll
        for (int l = 0; l < 12; l++) {
            int f = tid + l * 512;
            const __nv_bfloat16* src;
            uint32_t dst;
            if (f < 4096) {
                int arr = f >> 11;
                int r = (f >> 3) & 255, c = f & 7;
                src = (arr ? Alo_g : Ahi_g) + (size_t)(bM + r) * ND + s * 64 + c * 8;
                dst = base + (arr ? G_ALO : G_AHI) + r * 128 + ((c * 16) ^ ((r & 7) * 16));
            } else {
                int g = f - 4096;
                int arr = g >> 10;
                int r = (g >> 3) & 127, c = g & 7;
                src = (arr ? Wlo : Whi) + (size_t)(bN + r) * ND + s * 64 + c * 8;
                dst = base + (arr ? G_BLO : G_BHI) + r * 128 + ((c * 16) ^ ((r & 7) * 16));
            }
            cpasync16(dst, src);
        }
        CP_COMMIT();
    };

    cpStage(0, 0);

    for (int s = 0; s < 16; s++) {
        const int buf = s & 1;
        if (s + 1 < 16) { cpStage(s + 1, buf ^ 1); CP_WAIT1(); }
        else            { CP_WAIT0(); }
        __syncthreads();

        const uint32_t aHi = sb + buf * GBUF + G_AHI;
        const uint32_t aLo = sb + buf * GBUF + G_ALO;
        const uint32_t bHi = sb + buf * GBUF + G_BHI;
        const uint32_t bLo = sb + buf * GBUF + G_BLO;

        #pragma unroll
        for (int kk = 0; kk < 4; kk++) {
            const int k0 = kk * 16;
            uint32_t ah[2][4], al[2][4];
            #pragma unroll
            for (int mt = 0; mt < 2; mt++) {
                int row = warp_m + mt * 16 + (lane & 15);
                uint32_t off = row * 128 + ((k0 * 2 + (lane >> 4) * 16) ^ ((row & 7) * 16));
                LDSM_X4(ah[mt][0], ah[mt][1], ah[mt][2], ah[mt][3], aHi + off);
                LDSM_X4(al[mt][0], al[mt][1], al[mt][2], al[mt][3], aLo + off);
            }
            #pragma unroll
            for (int h = 0; h < 2; h++) {
                uint32_t bh[4][2], bl[4][2];
                #pragma unroll
                for (int p = 0; p < 2; p++) {
                    int n = warp_n + h * 32 + p * 16 + (lane & 7) + ((lane >> 4) << 3);
                    uint32_t off = n * 128 + ((k0 * 2 + ((lane >> 3) & 1) * 16) ^ ((n & 7) * 16));
                    LDSM_X4(bh[p*2][0], bh[p*2][1], bh[p*2+1][0], bh[p*2+1][1], bHi + off);
                    LDSM_X4(bl[p*2][0], bl[p*2][1], bl[p*2+1][0], bl[p*2+1][1], bLo + off);
                }
                #pragma unroll
                for (int mt = 0; mt < 2; mt++)
                    #pragma unroll
                    for (int nt = 0; nt < 4; nt++)
                        MMA_BF16(acc[mt*8 + h*4 + nt], ah[mt], bh[nt]);
                #pragma unroll
                for (int mt = 0; mt < 2; mt++)
                    #pragma unroll
                    for (int nt = 0; nt < 4; nt++)
                        MMA_BF16(acc[mt*8 + h*4 + nt], ah[mt], bl[nt]);
                #pragma unroll
                for (int mt = 0; mt < 2; mt++)
                    #pragma unroll
                    for (int nt = 0; nt < 4; nt++)
                        MMA_BF16(acc[mt*8 + h*4 + nt], al[mt], bh[nt]);
            }
        }
        __syncthreads();
    }

    #pragma unroll
    for (int mt = 0; mt < 2; mt++)
        #pragma unroll
        for (int nt = 0; nt < 8; nt++) {
            int m0 = bM + warp_m + mt * 16 + (lane >> 2);
            int n  = bN + warp_n + nt * 8 + (lane & 3) * 2;
            float* a4 = acc[mt*8+nt];
            if (mode == 0) {
                int h = n >> 6, dh = n & 63;
                int b0 = m0 >> 11, s0 = m0 & 2047;
                int m1 = m0 + 8, b1 = m1 >> 11, s1 = m1 & 2047;
                size_t i0 = ((size_t)(b0 * NH + h) * NS + s0) * NDH + dh;
                size_t i1 = ((size_t)(b1 * NH + h) * NS + s1) * NDH + dh;
                if (z == 0) {           // Q: fp16 split, scaled
                    uint32_t h0, l0, h1, l1;
                    splitH2(a4[0] * osc, a4[1] * osc, h0, l0);
                    splitH2(a4[2] * osc, a4[3] * osc, h1, l1);
                    *(uint32_t*)(g_Qh16 + i0) = h0; *(uint32_t*)(g_Ql16 + i0) = l0;
                    *(uint32_t*)(g_Qh16 + i1) = h1; *(uint32_t*)(g_Ql16 + i1) = l1;
                } else {                // K or V: single fp16
                    __half* O = (z == 1) ? g_K16 : g_V16;
                    *(uint32_t*)(O + i0) = h2pack(a4[0], a4[1]);
                    *(uint32_t*)(O + i1) = h2pack(a4[2], a4[3]);
                }
            } else {
                *(float2*)(Cout + (size_t)m0 * ND + n)       = make_float2(a4[0], a4[1]);
                *(float2*)(Cout + (size_t)(m0 + 8) * ND + n) = make_float2(a4[2], a4[3]);
            }
        }
}

// ---------------------------------------------------------------------------
// Flash attention on HMMA, all-fp16 operands.
// QK: 2-pass (Q fp16 hi/lo split, K single fp16). PV: 1-pass (P, V single).
// exp2-domain softmax (Q pre-scaled by 0.125*log2e).
// CTA = 128 q x 64 k, 8 warps, double-buffered K/V (32KB total).
// ---------------------------------------------------------------------------
#define ATT_BUF  16384
#define ATT_SMEM (2 * ATT_BUF)

__global__ __launch_bounds__(256, 1) void attn_mma_kernel(const int* __restrict__ valid_lens)
{
    extern __shared__ char smc[];
    const uint32_t sb = smem_u32(smc);
    const int tid = threadIdx.x, wid = tid >> 5, lane = tid & 31;
    const int qb = blockIdx.x, bh = blockIdx.y;
    const int bb = bh >> 4, head = bh & 15;
    const int vlen = valid_lens[bb];
    const int nkb  = (vlen + 63) >> 6;

    const size_t hbase = (size_t)bh * NS * NDH;
    const __half *Qh = g_Qh16 + hbase, *Ql = g_Ql16 + hbase;
    const __half *K16 = g_K16 + hbase, *V16 = g_V16 + hbase;

    const int r = lane >> 2, c2 = (lane & 3) * 2;

    uint32_t qh[4][4], ql[4][4];
    {
        const int q0 = qb * 128 + wid * 16;
        #pragma unroll
        for (int t = 0; t < 4; t++) {
            int k0 = t * 16;
            qh[t][0] = *(const uint32_t*)(Qh + (size_t)(q0 + r    ) * NDH + k0 + c2);
            qh[t][1] = *(const uint32_t*)(Qh + (size_t)(q0 + r + 8) * NDH + k0 + c2);
            qh[t][2] = *(const uint32_t*)(Qh + (size_t)(q0 + r    ) * NDH + k0 + c2 + 8);
            qh[t][3] = *(const uint32_t*)(Qh + (size_t)(q0 + r + 8) * NDH + k0 + c2 + 8);
            ql[t][0] = *(const uint32_t*)(Ql + (size_t)(q0 + r    ) * NDH + k0 + c2);
            ql[t][1] = *(const uint32_t*)(Ql + (size_t)(q0 + r + 8) * NDH + k0 + c2);
            ql[t][2] = *(const uint32_t*)(Ql + (size_t)(q0 + r    ) * NDH + k0 + c2 + 8);
            ql[t][3] = *(const uint32_t*)(Ql + (size_t)(q0 + r + 8) * NDH + k0 + c2 + 8);
        }
    }

    float m_i[2] = {-1e30f, -1e30f}, l_i[2] = {0.f, 0.f};
    float o[8][4];
    #pragma unroll
    for (int i = 0; i < 8; i++)
        #pragma unroll
        for (int j = 0; j < 4; j++) o[i][j] = 0.f;

    // stage = 16KB: K 8KB | V 8KB, 64 rows x 128B each
    auto cpKV = [&](int kb, int buf) {
        #pragma unroll
        for (int l = 0; l < 4; l++) {
            int f   = tid + l * 256;
            int arr = f >> 9;                 // 0:K 1:V
            int rr  = (f >> 3) & 63;
            int cc  = f & 7;
            const void* src = (arr ? V16 : K16) + (size_t)(kb * 64 + rr) * NDH + cc * 8;
            uint32_t dst = sb + buf * ATT_BUF + arr * 8192
                         + rr * 128 + ((cc * 16) ^ ((rr & 7) * 16));
            cpasync16(dst, src);
        }
        CP_COMMIT();
    };

    cpKV(0, 0);

    for (int kb = 0; kb < nkb; kb++) {
        const int buf = kb & 1;
        CP_WAIT0();
        __syncthreads();
        if (kb + 1 < nkb) cpKV(kb + 1, buf ^ 1);

        const uint32_t kS = sb + buf * ATT_BUF;
        const uint32_t vS = kS + 8192;

        // ---- S = Q K^T (2-pass: Qh + Ql, K single) ----
        float s[8][4];
        #pragma unroll
        for (int i = 0; i < 8; i++)
            #pragma unroll
            for (int j = 0; j < 4; j++) s[i][j] = 0.f;

        #pragma unroll
        for (int t = 0; t < 4; t++) {
            uint32_t kf[8][2];
            #pragma unroll
            for (int p = 0; p < 4; p++) {
                int n = p * 16 + (lane & 7) + ((lane >> 4) << 3);
                uint32_t off = n * 128 + ((t * 32 + ((lane >> 3) & 1) * 16) ^ ((n & 7) * 16));
                LDSM_X4(kf[p*2][0], kf[p*2][1], kf[p*2+1][0], kf[p*2+1][1], kS + off);
            }
            #pragma unroll
            for (int nt = 0; nt < 8; nt++)
                MMA_F16(s[nt], qh[t], kf[nt]);
            #pragma unroll
            for (int nt = 0; nt < 8; nt++)
                MMA_F16(s[nt], ql[t], kf[nt]);
        }

        if (kb == nkb - 1) {
            int cb = kb * 64 + c2;
            #pragma unroll
            for (int nt = 0; nt < 8; nt++) {
                int c0g = cb + nt * 8;
                if (c0g     >= vlen) { s[nt][0] = -1e30f; s[nt][2] = -1e30f; }
                if (c0g + 1 >= vlen) { s[nt][1] = -1e30f; s[nt][3] = -1e30f; }
            }
        }

        // ---- online softmax (base-2 domain) ----
        float mx0 = -1e30f, mx1 = -1e30f;
        #pragma unroll
        for (int nt = 0; nt < 8; nt++) {
            mx0 = fmaxf(mx0, fmaxf(s[nt][0], s[nt][1]));
            mx1 = fmaxf(mx1, fmaxf(s[nt][2], s[nt][3]));
        }
        mx0 = fmaxf(mx0, __shfl_xor_sync(0xffffffffu, mx0, 1));
        mx0 = fmaxf(mx0, __shfl_xor_sync(0xffffffffu, mx0, 2));
        mx1 = fmaxf(mx1, __shfl_xor_sync(0xffffffffu, mx1, 1));
        mx1 = fmaxf(mx1, __shfl_xor_sync(0xffffffffu, mx1, 2));

        float mn0 = fmaxf(m_i[0], mx0), mn1 = fmaxf(m_i[1], mx1);
        float a0 = ex2f(m_i[0] - mn0), a1 = ex2f(m_i[1] - mn1);
        m_i[0] = mn0; m_i[1] = mn1;

        float sum0 = 0.f, sum1 = 0.f;
        #pragma unroll
        for (int nt = 0; nt < 8; nt++) {
            s[nt][0] = ex2f(s[nt][0] - mn0); sum0 += s[nt][0];
            s[nt][1] = ex2f(s[nt][1] - mn0); sum0 += s[nt][1];
            s[nt][2] = ex2f(s[nt][2] - mn1); sum1 += s[nt][2];
            s[nt][3] = ex2f(s[nt][3] - mn1); sum1 += s[nt][3];
        }
        sum0 += __shfl_xor_sync(0xffffffffu, sum0, 1);
        sum0 += __shfl_xor_sync(0xffffffffu, sum0, 2);
        sum1 += __shfl_xor_sync(0xffffffffu, sum1, 1);
        sum1 += __shfl_xor_sync(0xffffffffu, sum1, 2);
        l_i[0] = l_i[0] * a0 + sum0;
        l_i[1] = l_i[1] * a1 + sum1;
        #pragma unroll
        for (int nt = 0; nt < 8; nt++) {
            o[nt][0] *= a0; o[nt][1] *= a0;
            o[nt][2] *= a1; o[nt][3] *= a1;
        }

        // ---- O += P V (1-pass: P single fp16, V single fp16) ----
        #pragma unroll
        for (int t = 0; t < 4; t++) {
            uint32_t ph[4];
            ph[0] = h2pack(s[2*t  ][0], s[2*t  ][1]);
            ph[1] = h2pack(s[2*t  ][2], s[2*t  ][3]);
            ph[2] = h2pack(s[2*t+1][0], s[2*t+1][1]);
            ph[3] = h2pack(s[2*t+1][2], s[2*t+1][3]);

            uint32_t vf[8][2];
            #pragma unroll
            for (int p = 0; p < 4; p++) {
                int rowb = t * 16 + (lane & 15);
                uint32_t off = rowb * 128 + ((p * 32 + (lane >> 4) * 16) ^ ((rowb & 7) * 16));
                LDSM_X4_T(vf[p*2][0], vf[p*2][1], vf[p*2+1][0], vf[p*2+1][1], vS + off);
            }
            #pragma unroll
            for (int nt = 0; nt < 8; nt++)
                MMA_F16(o[nt], ph, vf[nt]);
        }
    }

    // epilogue: write split bf16 [B*S][D] for the Wo GEMM
    const float inv0 = 1.f / l_i[0], inv1 = 1.f / l_i[1];
    const int row0 = qb * 128 + wid * 16 + r;
    const size_t base0 = (size_t)(bb * NS + row0    ) * ND + head * 64;
    const size_t base1 = (size_t)(bb * NS + row0 + 8) * ND + head * 64;
    #pragma unroll
    for (int nt = 0; nt < 8; nt++) {
        uint32_t h0, l0, h1, l1;
        split2(o[nt][0] * inv0, o[nt][1] * inv0, h0, l0);
        split2(o[nt][2] * inv1, o[nt][3] * inv1, h1, l1);
        *(uint32_t*)(g_AOhi + base0 + nt * 8 + c2) = h0;
        *(uint32_t*)(g_AOlo + base0 + nt * 8 + c2) = l0;
        *(uint32_t*)(g_AOhi + base1 + nt * 8 + c2) = h1;
        *(uint32_t*)(g_AOlo + base1 + nt * 8 + c2) = l1;
    }
}

// ---------------------------------------------------------------------------
extern "C" void kernel_launch(void* const* d_in, const int* in_sizes, int n_in,
                              void* d_out, int out_size)
{
    const float* q  = (const float*)d_in[0];
    const float* k  = (const float*)d_in[1];
    const float* v  = (const float*)d_in[2];
    const int*   vl = (const int*)  d_in[3];
    const float* Wq = (const float*)d_in[4];
    const float* Wk = (const float*)d_in[5];
    const float* Wv = (const float*)d_in[6];
    const float* Wo = (const float*)d_in[7];
    float* out = (float*)d_out;

    cudaFuncSetAttribute(gemm_mma_kernel, cudaFuncAttributeMaxDynamicSharedMemorySize,
                         GEMM_SMEM);
    cudaFuncSetAttribute(attn_mma_kernel, cudaFuncAttributeMaxDynamicSharedMemorySize,
                         ATT_SMEM);

    splitx_kernel<<<dim3(4096, 3), 256>>>(q, k, v);
    wsplit_kernel<<<dim3(32, 32, 4), 256>>>(Wq, Wk, Wv, Wo);

    gemm_mma_kernel<<<dim3(ND / 128, (NB * NS) / 256, 3), 512, GEMM_SMEM>>>(out, 0);

    attn_mma_kernel<<<dim3(NS / 128, NB * NH), 256, ATT_SMEM>>>(vl);

    gemm_mma_kernel<<<dim3(ND / 128, (NB * NS) / 256, 1), 512, GEMM_SMEM>>>(out, 1);
}

// round 10
// speedup vs baseline: 1.5383x; 1.3338x over previous
#include <cuda_runtime.h>
#include <cuda_bf16.h>
#include <cuda_fp16.h>
#include <stdint.h>

#define NB  2
#define NS  2048
#define ND  1024
#define NH  16
#define NDH 64

// Scratch (allocation-free rule: __device__ globals).
__device__ __half g_Wh16[4u << 20], g_Wl16[4u << 20];  // 4 x W^T fp16 hi/lo: [n][k]
__device__ __half g_X16 [3u << 22];                    // single-fp16 Xq/Xk/Xv [4096][1024]
__device__ __half g_AO16[1u << 22];                    // single-fp16 attn out [4096][1024]
// head-major [B,H,S,DH]: Q split fp16 hi/lo, K single fp16, V single fp16
__device__ __half g_Qh16[NB*NH*NS*NDH], g_Ql16[NB*NH*NS*NDH];
__device__ __half g_K16 [NB*NH*NS*NDH];
__device__ __half g_V16 [NB*NH*NS*NDH];

// ---------------------------------------------------------------------------
// helpers
// ---------------------------------------------------------------------------
__device__ __forceinline__ uint32_t smem_u32(const void* p) {
    uint32_t a;
    asm("{ .reg .u64 t; cvta.to.shared.u64 t, %1; cvt.u32.u64 %0, t; }" : "=r"(a) : "l"(p));
    return a;
}
__device__ __forceinline__ void cpasync16(uint32_t dst, const void* src) {
    asm volatile("cp.async.cg.shared.global [%0], [%1], 16;" :: "r"(dst), "l"(src));
}
#define CP_COMMIT() asm volatile("cp.async.commit_group;" ::: "memory")
#define CP_WAIT0()  asm volatile("cp.async.wait_group 0;" ::: "memory")
#define CP_WAIT1()  asm volatile("cp.async.wait_group 1;" ::: "memory")

#define LDSM_X4(r0, r1, r2, r3, addr)                                          \
    asm volatile("ldmatrix.sync.aligned.m8n8.x4.shared.b16 {%0,%1,%2,%3}, [%4];" \
        : "=r"(r0), "=r"(r1), "=r"(r2), "=r"(r3) : "r"(addr))
#define LDSM_X4_T(r0, r1, r2, r3, addr)                                        \
    asm volatile("ldmatrix.sync.aligned.m8n8.x4.trans.shared.b16 {%0,%1,%2,%3}, [%4];" \
        : "=r"(r0), "=r"(r1), "=r"(r2), "=r"(r3) : "r"(addr))

#define MMA_F16(d, a, b)                                                       \
    asm volatile("mma.sync.aligned.m16n8k16.row.col.f32.f16.f16.f32 "          \
        "{%0,%1,%2,%3},{%4,%5,%6,%7},{%8,%9},{%0,%1,%2,%3};"                   \
        : "+f"((d)[0]), "+f"((d)[1]), "+f"((d)[2]), "+f"((d)[3])               \
        : "r"((a)[0]), "r"((a)[1]), "r"((a)[2]), "r"((a)[3]),                  \
          "r"((b)[0]), "r"((b)[1]))

__device__ __forceinline__ float ex2f(float x) {
    float y; asm("ex2.approx.f32 %0, %1;" : "=f"(y) : "f"(x)); return y;
}
__device__ __forceinline__ uint32_t h2pack(float a, float b) {
    __half2 h = __floats2half2_rn(a, b);
    return *(uint32_t*)&h;
}
__device__ __forceinline__ void splitH2(float a, float b, uint32_t& hi, uint32_t& lo) {
    __half ha = __float2half_rn(a), hb = __float2half_rn(b);
    float ra = a - __half2float(ha), rb = b - __half2float(hb);
    __half2 h = __halves2half2(ha, hb);
    __half2 l = __floats2half2_rn(ra, rb);
    hi = *(uint32_t*)&h; lo = *(uint32_t*)&l;
}

// ---------------------------------------------------------------------------
// X convert: fp32 -> single fp16, row-major passthrough.
// ---------------------------------------------------------------------------
__global__ __launch_bounds__(256) void cvtx_kernel(
    const float* __restrict__ X0, const float* __restrict__ X1,
    const float* __restrict__ X2)
{
    const int z = blockIdx.y;
    const float* X = (z == 0) ? X0 : (z == 1) ? X1 : X2;
    __half* O = g_X16 + ((size_t)z << 22);
    size_t idx = (size_t)blockIdx.x * 256 + threadIdx.x;   // float4 index
    float4 v = *((const float4*)X + idx);
    uint2 o;
    o.x = h2pack(v.x, v.y);
    o.y = h2pack(v.z, v.w);
    *((uint2*)O + idx) = o;
}

// ---------------------------------------------------------------------------
// W transpose + fp32 -> fp16 hi/lo. Out[n][k] = W[k][n].
// ---------------------------------------------------------------------------
__global__ __launch_bounds__(256) void wsplit_kernel(
    const float* __restrict__ W0, const float* __restrict__ W1,
    const float* __restrict__ W2, const float* __restrict__ W3)
{
    __shared__ float t[32][33];
    const float* W = (blockIdx.z == 0) ? W0 : (blockIdx.z == 1) ? W1 :
                     (blockIdx.z == 2) ? W2 : W3;
    __half* Ohi = g_Wh16 + ((size_t)blockIdx.z << 20);
    __half* Olo = g_Wl16 + ((size_t)blockIdx.z << 20);

    int tx = threadIdx.x & 31, ty = threadIdx.x >> 5;
    int n0 = blockIdx.x * 32, k0 = blockIdx.y * 32;

    #pragma unroll
    for (int i = 0; i < 4; i++)
        t[ty + i*8][tx] = W[(size_t)(k0 + ty + i*8) * ND + n0 + tx];
    __syncthreads();
    #pragma unroll
    for (int i = 0; i < 4; i++) {
        float v = t[tx][ty + i*8];
        __half h = __float2half_rn(v);
        __half l = __float2half_rn(v - __half2float(h));
        size_t idx = (size_t)(n0 + ty + i*8) * ND + k0 + tx;
        Ohi[idx] = h; Olo[idx] = l;
    }
}

// ---------------------------------------------------------------------------
// HMMA 2-pass fp16 GEMM: D = A * (Wh + Wl). A single fp16, W split hi/lo.
// CTA 256M x 128N, BK=64, 512 threads = 16 warps (8m x 2n), double-buffered.
// mode 0: z=0 -> Q (fp16 split out, scaled 0.125*log2e), z=1 -> K, z=2 -> V.
// mode 1: A = g_AO16, fp32 out.
// ---------------------------------------------------------------------------
#define GBUF   65536
#define G_A    0
#define G_WH   32768
#define G_WL   49152
#define GEMM_SMEM (2 * GBUF)   // 128 KB

__global__ __launch_bounds__(512, 1) void gemm_mma_kernel(float* __restrict__ Cout, int mode)
{
    extern __shared__ char smc[];
    const uint32_t sb = smem_u32(smc);
    const int tid  = threadIdx.x;
    const int wid  = tid >> 5, lane = tid & 31;
    const int z    = blockIdx.z;

    const __half *A_g, *Whi, *Wlo;
    float osc = 1.f;
    if (mode == 0) {
        A_g = g_X16 + ((size_t)z << 22);
        Whi = g_Wh16 + ((size_t)z << 20);
        Wlo = g_Wl16 + ((size_t)z << 20);
        if (z == 0) osc = 0.125f * 1.44269504f;   // fold log2(e) for exp2 softmax
    } else {
        A_g = g_AO16;
        Whi = g_Wh16 + ((size_t)3 << 20);
        Wlo = g_Wl16 + ((size_t)3 << 20);
    }
    const int bM = blockIdx.y * 256, bN = blockIdx.x * 128;
    const int warp_m = (wid & 7) * 32, warp_n = (wid >> 3) * 64;

    float acc[16][4];
    #pragma unroll
    for (int i = 0; i < 16; i++)
        #pragma unroll
        for (int j = 0; j < 4; j++) acc[i][j] = 0.f;

    auto cpStage = [&](int s, int buf) {
        uint32_t base = sb + buf * GBUF;
        #pragma unroll
        for (int l = 0; l < 8; l++) {
            int f = tid + l * 512;
            const __half* src;
            uint32_t dst;
            if (f < 2048) {                     // A: 256 rows x 8 chunks
                int r = f >> 3, c = f & 7;
                src = A_g + (size_t)(bM + r) * ND + s * 64 + c * 8;
                dst = base + G_A + r * 128 + ((c * 16) ^ ((r & 7) * 16));
            } else {                            // W hi/lo: 128 rows x 8 chunks each
                int g = f - 2048;
                int arr = g >> 10;
                int r = (g >> 3) & 127, c = g & 7;
                src = (arr ? Wlo : Whi) + (size_t)(bN + r) * ND + s * 64 + c * 8;
                dst = base + (arr ? G_WL : G_WH) + r * 128 + ((c * 16) ^ ((r & 7) * 16));
            }
            cpasync16(dst, src);
        }
        CP_COMMIT();
    };

    cpStage(0, 0);

    for (int s = 0; s < 16; s++) {
        const int buf = s & 1;
        if (s + 1 < 16) { cpStage(s + 1, buf ^ 1); CP_WAIT1(); }
        else            { CP_WAIT0(); }
        __syncthreads();

        const uint32_t aS = sb + buf * GBUF + G_A;
        const uint32_t wH = sb + buf * GBUF + G_WH;
        const uint32_t wL = sb + buf * GBUF + G_WL;

        #pragma unroll
        for (int kk = 0; kk < 4; kk++) {
            const int k0 = kk * 16;
            uint32_t af[2][4];
            #pragma unroll
            for (int mt = 0; mt < 2; mt++) {
                int row = warp_m + mt * 16 + (lane & 15);
                uint32_t off = row * 128 + ((k0 * 2 + (lane >> 4) * 16) ^ ((row & 7) * 16));
                LDSM_X4(af[mt][0], af[mt][1], af[mt][2], af[mt][3], aS + off);
            }
            #pragma unroll
            for (int h = 0; h < 2; h++) {
                uint32_t bh[4][2], bl[4][2];
                #pragma unroll
                for (int p = 0; p < 2; p++) {
                    int n = warp_n + h * 32 + p * 16 + (lane & 7) + ((lane >> 4) << 3);
                    uint32_t off = n * 128 + ((k0 * 2 + ((lane >> 3) & 1) * 16) ^ ((n & 7) * 16));
                    LDSM_X4(bh[p*2][0], bh[p*2][1], bh[p*2+1][0], bh[p*2+1][1], wH + off);
                    LDSM_X4(bl[p*2][0], bl[p*2][1], bl[p*2+1][0], bl[p*2+1][1], wL + off);
                }
                #pragma unroll
                for (int mt = 0; mt < 2; mt++)
                    #pragma unroll
                    for (int nt = 0; nt < 4; nt++)
                        MMA_F16(acc[mt*8 + h*4 + nt], af[mt], bh[nt]);
                #pragma unroll
                for (int mt = 0; mt < 2; mt++)
                    #pragma unroll
                    for (int nt = 0; nt < 4; nt++)
                        MMA_F16(acc[mt*8 + h*4 + nt], af[mt], bl[nt]);
            }
        }
        __syncthreads();
    }

    #pragma unroll
    for (int mt = 0; mt < 2; mt++)
        #pragma unroll
        for (int nt = 0; nt < 8; nt++) {
            int m0 = bM + warp_m + mt * 16 + (lane >> 2);
            int n  = bN + warp_n + nt * 8 + (lane & 3) * 2;
            float* a4 = acc[mt*8+nt];
            if (mode == 0) {
                int h = n >> 6, dh = n & 63;
                int b0 = m0 >> 11, s0 = m0 & 2047;
                int m1 = m0 + 8, b1 = m1 >> 11, s1 = m1 & 2047;
                size_t i0 = ((size_t)(b0 * NH + h) * NS + s0) * NDH + dh;
                size_t i1 = ((size_t)(b1 * NH + h) * NS + s1) * NDH + dh;
                if (z == 0) {           // Q: fp16 split, scaled
                    uint32_t h0, l0, h1, l1;
                    splitH2(a4[0] * osc, a4[1] * osc, h0, l0);
                    splitH2(a4[2] * osc, a4[3] * osc, h1, l1);
                    *(uint32_t*)(g_Qh16 + i0) = h0; *(uint32_t*)(g_Ql16 + i0) = l0;
                    *(uint32_t*)(g_Qh16 + i1) = h1; *(uint32_t*)(g_Ql16 + i1) = l1;
                } else {                // K or V: single fp16
                    __half* O = (z == 1) ? g_K16 : g_V16;
                    *(uint32_t*)(O + i0) = h2pack(a4[0], a4[1]);
                    *(uint32_t*)(O + i1) = h2pack(a4[2], a4[3]);
                }
            } else {
                *(float2*)(Cout + (size_t)m0 * ND + n)       = make_float2(a4[0], a4[1]);
                *(float2*)(Cout + (size_t)(m0 + 8) * ND + n) = make_float2(a4[2], a4[3]);
            }
        }
}

// ---------------------------------------------------------------------------
// Flash attention on HMMA, all-fp16 operands.
// QK: 2-pass (Q fp16 hi/lo, K single). PV: 1-pass (P, V single).
// exp2-domain softmax. CTA = 128 q x 64 k, 8 warps, double-buffered (32KB).
// Epilogue: single fp16 to g_AO16.
// ---------------------------------------------------------------------------
#define ATT_BUF  16384
#define ATT_SMEM (2 * ATT_BUF)

__global__ __launch_bounds__(256, 1) void attn_mma_kernel(const int* __restrict__ valid_lens)
{
    extern __shared__ char smc[];
    const uint32_t sb = smem_u32(smc);
    const int tid = threadIdx.x, wid = tid >> 5, lane = tid & 31;
    const int qb = blockIdx.x, bh = blockIdx.y;
    const int bb = bh >> 4, head = bh & 15;
    const int vlen = valid_lens[bb];
    const int nkb  = (vlen + 63) >> 6;

    const size_t hbase = (size_t)bh * NS * NDH;
    const __half *Qh = g_Qh16 + hbase, *Ql = g_Ql16 + hbase;
    const __half *K16 = g_K16 + hbase, *V16 = g_V16 + hbase;

    const int r = lane >> 2, c2 = (lane & 3) * 2;

    uint32_t qh[4][4], ql[4][4];
    {
        const int q0 = qb * 128 + wid * 16;
        #pragma unroll
        for (int t = 0; t < 4; t++) {
            int k0 = t * 16;
            qh[t][0] = *(const uint32_t*)(Qh + (size_t)(q0 + r    ) * NDH + k0 + c2);
            qh[t][1] = *(const uint32_t*)(Qh + (size_t)(q0 + r + 8) * NDH + k0 + c2);
            qh[t][2] = *(const uint32_t*)(Qh + (size_t)(q0 + r    ) * NDH + k0 + c2 + 8);
            qh[t][3] = *(const uint32_t*)(Qh + (size_t)(q0 + r + 8) * NDH + k0 + c2 + 8);
            ql[t][0] = *(const uint32_t*)(Ql + (size_t)(q0 + r    ) * NDH + k0 + c2);
            ql[t][1] = *(const uint32_t*)(Ql + (size_t)(q0 + r + 8) * NDH + k0 + c2);
            ql[t][2] = *(const uint32_t*)(Ql + (size_t)(q0 + r    ) * NDH + k0 + c2 + 8);
            ql[t][3] = *(const uint32_t*)(Ql + (size_t)(q0 + r + 8) * NDH + k0 + c2 + 8);
        }
    }

    float m_i[2] = {-1e30f, -1e30f}, l_i[2] = {0.f, 0.f};
    float o[8][4];
    #pragma unroll
    for (int i = 0; i < 8; i++)
        #pragma unroll
        for (int j = 0; j < 4; j++) o[i][j] = 0.f;

    auto cpKV = [&](int kb, int buf) {
        #pragma unroll
        for (int l = 0; l < 4; l++) {
            int f   = tid + l * 256;
            int arr = f >> 9;                 // 0:K 1:V
            int rr  = (f >> 3) & 63;
            int cc  = f & 7;
            const void* src = (arr ? V16 : K16) + (size_t)(kb * 64 + rr) * NDH + cc * 8;
            uint32_t dst = sb + buf * ATT_BUF + arr * 8192
                         + rr * 128 + ((cc * 16) ^ ((rr & 7) * 16));
            cpasync16(dst, src);
        }
        CP_COMMIT();
    };

    cpKV(0, 0);

    for (int kb = 0; kb < nkb; kb++) {
        const int buf = kb & 1;
        CP_WAIT0();
        __syncthreads();
        if (kb + 1 < nkb) cpKV(kb + 1, buf ^ 1);

        const uint32_t kS = sb + buf * ATT_BUF;
        const uint32_t vS = kS + 8192;

        // ---- S = Q K^T (2-pass) ----
        float s[8][4];
        #pragma unroll
        for (int i = 0; i < 8; i++)
            #pragma unroll
            for (int j = 0; j < 4; j++) s[i][j] = 0.f;

        #pragma unroll
        for (int t = 0; t < 4; t++) {
            uint32_t kf[8][2];
            #pragma unroll
            for (int p = 0; p < 4; p++) {
                int n = p * 16 + (lane & 7) + ((lane >> 4) << 3);
                uint32_t off = n * 128 + ((t * 32 + ((lane >> 3) & 1) * 16) ^ ((n & 7) * 16));
                LDSM_X4(kf[p*2][0], kf[p*2][1], kf[p*2+1][0], kf[p*2+1][1], kS + off);
            }
            #pragma unroll
            for (int nt = 0; nt < 8; nt++)
                MMA_F16(s[nt], qh[t], kf[nt]);
            #pragma unroll
            for (int nt = 0; nt < 8; nt++)
                MMA_F16(s[nt], ql[t], kf[nt]);
        }

        if (kb == nkb - 1) {
            int cb = kb * 64 + c2;
            #pragma unroll
            for (int nt = 0; nt < 8; nt++) {
                int c0g = cb + nt * 8;
                if (c0g     >= vlen) { s[nt][0] = -1e30f; s[nt][2] = -1e30f; }
                if (c0g + 1 >= vlen) { s[nt][1] = -1e30f; s[nt][3] = -1e30f; }
            }
        }

        // ---- online softmax (base-2 domain) ----
        float mx0 = -1e30f, mx1 = -1e30f;
        #pragma unroll
        for (int nt = 0; nt < 8; nt++) {
            mx0 = fmaxf(mx0, fmaxf(s[nt][0], s[nt][1]));
            mx1 = fmaxf(mx1, fmaxf(s[nt][2], s[nt][3]));
        }
        mx0 = fmaxf(mx0, __shfl_xor_sync(0xffffffffu, mx0, 1));
        mx0 = fmaxf(mx0, __shfl_xor_sync(0xffffffffu, mx0, 2));
        mx1 = fmaxf(mx1, __shfl_xor_sync(0xffffffffu, mx1, 1));
        mx1 = fmaxf(mx1, __shfl_xor_sync(0xffffffffu, mx1, 2));

        float mn0 = fmaxf(m_i[0], mx0), mn1 = fmaxf(m_i[1], mx1);
        float a0 = ex2f(m_i[0] - mn0), a1 = ex2f(m_i[1] - mn1);
        m_i[0] = mn0; m_i[1] = mn1;

        float sum0 = 0.f, sum1 = 0.f;
        #pragma unroll
        for (int nt = 0; nt < 8; nt++) {
            s[nt][0] = ex2f(s[nt][0] - mn0); sum0 += s[nt][0];
            s[nt][1] = ex2f(s[nt][1] - mn0); sum0 += s[nt][1];
            s[nt][2] = ex2f(s[nt][2] - mn1); sum1 += s[nt][2];
            s[nt][3] = ex2f(s[nt][3] - mn1); sum1 += s[nt][3];
        }
        sum0 += __shfl_xor_sync(0xffffffffu, sum0, 1);
        sum0 += __shfl_xor_sync(0xffffffffu, sum0, 2);
        sum1 += __shfl_xor_sync(0xffffffffu, sum1, 1);
        sum1 += __shfl_xor_sync(0xffffffffu, sum1, 2);
        l_i[0] = l_i[0] * a0 + sum0;
        l_i[1] = l_i[1] * a1 + sum1;
        #pragma unroll
        for (int nt = 0; nt < 8; nt++) {
            o[nt][0] *= a0; o[nt][1] *= a0;
            o[nt][2] *= a1; o[nt][3] *= a1;
        }

        // ---- O += P V (1-pass) ----
        #pragma unroll
        for (int t = 0; t < 4; t++) {
            uint32_t ph[4];
            ph[0] = h2pack(s[2*t  ][0], s[2*t  ][1]);
            ph[1] = h2pack(s[2*t  ][2], s[2*t  ][3]);
            ph[2] = h2pack(s[2*t+1][0], s[2*t+1][1]);
            ph[3] = h2pack(s[2*t+1][2], s[2*t+1][3]);

            uint32_t vf[8][2];
            #pragma unroll
            for (int p = 0; p < 4; p++) {
                int rowb = t * 16 + (lane & 15);
                uint32_t off = rowb * 128 + ((p * 32 + (lane >> 4) * 16) ^ ((rowb & 7) * 16));
                LDSM_X4_T(vf[p*2][0], vf[p*2][1], vf[p*2+1][0], vf[p*2+1][1], vS + off);
            }
            #pragma unroll
            for (int nt = 0; nt < 8; nt++)
                MMA_F16(o[nt], ph, vf[nt]);
        }
    }

    // epilogue: single fp16 to g_AO16 [B*S][D]
    const float inv0 = 1.f / l_i[0], inv1 = 1.f / l_i[1];
    const int row0 = qb * 128 + wid * 16 + r;
    const size_t base0 = (size_t)(bb * NS + row0    ) * ND + head * 64;
    const size_t base1 = (size_t)(bb * NS + row0 + 8) * ND + head * 64;
    #pragma unroll
    for (int nt = 0; nt < 8; nt++) {
        *(uint32_t*)(g_AO16 + base0 + nt * 8 + c2) = h2pack(o[nt][0] * inv0, o[nt][1] * inv0);
        *(uint32_t*)(g_AO16 + base1 + nt * 8 + c2) = h2pack(o[nt][2] * inv1, o[nt][3] * inv1);
    }
}

// ---------------------------------------------------------------------------
extern "C" void kernel_launch(void* const* d_in, const int* in_sizes, int n_in,
                              void* d_out, int out_size)
{
    const float* q  = (const float*)d_in[0];
    const float* k  = (const float*)d_in[1];
    const float* v  = (const float*)d_in[2];
    const int*   vl = (const int*)  d_in[3];
    const float* Wq = (const float*)d_in[4];
    const float* Wk = (const float*)d_in[5];
    const float* Wv = (const float*)d_in[6];
    const float* Wo = (const float*)d_in[7];
    float* out = (float*)d_out;

    cudaFuncSetAttribute(gemm_mma_kernel, cudaFuncAttributeMaxDynamicSharedMemorySize,
                         GEMM_SMEM);
    cudaFuncSetAttribute(attn_mma_kernel, cudaFuncAttributeMaxDynamicSharedMemorySize,
                         ATT_SMEM);

    cvtx_kernel<<<dim3(4096, 3), 256>>>(q, k, v);
    wsplit_kernel<<<dim3(32, 32, 4), 256>>>(Wq, Wk, Wv, Wo);

    gemm_mma_kernel<<<dim3(ND / 128, (NB * NS) / 256, 3), 512, GEMM_SMEM>>>(out, 0);

    attn_mma_kernel<<<dim3(NS / 128, NB * NH), 256, ATT_SMEM>>>(vl);

    gemm_mma_kernel<<<dim3(ND / 128, (NB * NS) / 256, 1), 512, GEMM_SMEM>>>(out, 1);
}

// round 12
// speedup vs baseline: 1.5718x; 1.0218x over previous
#include <cuda_runtime.h>
#include <cuda_bf16.h>
#include <cuda_fp16.h>
#include <stdint.h>

#define NB  2
#define NS  2048
#define ND  1024
#define NH  16
#define NDH 64

// Scratch (allocation-free rule: __device__ globals).
__device__ __half g_Wh16[4u << 20], g_Wl16[4u << 20];  // 4 x W^T fp16 hi/lo: [n][k]
__device__ __half g_X16 [3u << 22];                    // single-fp16 Xq/Xk/Xv [4096][1024]
__device__ __half g_AO16[1u << 22];                    // single-fp16 attn out [4096][1024]
// head-major [B,H,S,DH]: Q/K/V all single fp16 (Q pre-scaled by 0.125*log2e)
__device__ __half g_Q16[NB*NH*NS*NDH];
__device__ __half g_K16[NB*NH*NS*NDH];
__device__ __half g_V16[NB*NH*NS*NDH];

// ---------------------------------------------------------------------------
// helpers
// ---------------------------------------------------------------------------
__device__ __forceinline__ uint32_t smem_u32(const void* p) {
    uint32_t a;
    asm("{ .reg .u64 t; cvta.to.shared.u64 t, %1; cvt.u32.u64 %0, t; }" : "=r"(a) : "l"(p));
    return a;
}
__device__ __forceinline__ void cpasync16(uint32_t dst, const void* src) {
    asm volatile("cp.async.cg.shared.global [%0], [%1], 16;" :: "r"(dst), "l"(src));
}
#define CP_COMMIT() asm volatile("cp.async.commit_group;" ::: "memory")
#define CP_WAIT0()  asm volatile("cp.async.wait_group 0;" ::: "memory")
#define CP_WAIT1()  asm volatile("cp.async.wait_group 1;" ::: "memory")

#define LDSM_X4(r0, r1, r2, r3, addr)                                          \
    asm volatile("ldmatrix.sync.aligned.m8n8.x4.shared.b16 {%0,%1,%2,%3}, [%4];" \
        : "=r"(r0), "=r"(r1), "=r"(r2), "=r"(r3) : "r"(addr))
#define LDSM_X4_T(r0, r1, r2, r3, addr)                                        \
    asm volatile("ldmatrix.sync.aligned.m8n8.x4.trans.shared.b16 {%0,%1,%2,%3}, [%4];" \
        : "=r"(r0), "=r"(r1), "=r"(r2), "=r"(r3) : "r"(addr))

#define MMA_F16(d, a, b)                                                       \
    asm volatile("mma.sync.aligned.m16n8k16.row.col.f32.f16.f16.f32 "          \
        "{%0,%1,%2,%3},{%4,%5,%6,%7},{%8,%9},{%0,%1,%2,%3};"                   \
        : "+f"((d)[0]), "+f"((d)[1]), "+f"((d)[2]), "+f"((d)[3])               \
        : "r"((a)[0]), "r"((a)[1]), "r"((a)[2]), "r"((a)[3]),                  \
          "r"((b)[0]), "r"((b)[1]))

__device__ __forceinline__ float ex2f(float x) {
    float y; asm("ex2.approx.f32 %0, %1;" : "=f"(y) : "f"(x)); return y;
}
__device__ __forceinline__ uint32_t h2pack(float a, float b) {
    __half2 h = __floats2half2_rn(a, b);
    return *(uint32_t*)&h;
}

// ---------------------------------------------------------------------------
// Prep: z 0..2 -> X fp32->fp16 convert (grid.x = 4096);
//       z 3..6 -> W transpose + fp16 hi/lo (only grid.x < 1024 valid!).
// ---------------------------------------------------------------------------
__global__ __launch_bounds__(256) void prep_kernel(
    const float* __restrict__ X0, const float* __restrict__ X1,
    const float* __restrict__ X2,
    const float* __restrict__ W0, const float* __restrict__ W1,
    const float* __restrict__ W2, const float* __restrict__ W3)
{
    const int z = blockIdx.z;
    if (z < 3) {
        const float* X = (z == 0) ? X0 : (z == 1) ? X1 : X2;
        __half* O = g_X16 + ((size_t)z << 22);
        size_t idx = (size_t)blockIdx.x * 256 + threadIdx.x;
        float4 v = *((const float4*)X + idx);
        uint2 o;
        o.x = h2pack(v.x, v.y);
        o.y = h2pack(v.z, v.w);
        *((uint2*)O + idx) = o;
    } else {
        if (blockIdx.x >= 1024) return;   // only 32x32 = 1024 W tiles (BUGFIX)
        __shared__ float t[32][33];
        int wz = z - 3;
        const float* W = (wz == 0) ? W0 : (wz == 1) ? W1 : (wz == 2) ? W2 : W3;
        __half* Ohi = g_Wh16 + ((size_t)wz << 20);
        __half* Olo = g_Wl16 + ((size_t)wz << 20);
        int tx = threadIdx.x & 31, ty = threadIdx.x >> 5;
        int n0 = (blockIdx.x & 31) * 32, k0 = (blockIdx.x >> 5) * 32;
        #pragma unroll
        for (int i = 0; i < 4; i++)
            t[ty + i*8][tx] = W[(size_t)(k0 + ty + i*8) * ND + n0 + tx];
        __syncthreads();
        #pragma unroll
        for (int i = 0; i < 4; i++) {
            float v = t[tx][ty + i*8];
            __half h = __float2half_rn(v);
            __half l = __float2half_rn(v - __half2float(h));
            size_t idx = (size_t)(n0 + ty + i*8) * ND + k0 + tx;
            Ohi[idx] = h; Olo[idx] = l;
        }
    }
}

// ---------------------------------------------------------------------------
// HMMA 2-pass fp16 GEMM: D = A * (Wh + Wl). A single fp16, W split hi/lo.
// CTA 256M x 128N, BK=64, 512 threads, double-buffered.
// mode 0: z=0 -> Q (single fp16, scaled 0.125*log2e), z=1 -> K, z=2 -> V.
// mode 1: A = g_AO16, fp32 out.
// ---------------------------------------------------------------------------
#define GBUF   65536
#define G_A    0
#define G_WH   32768
#define G_WL   49152
#define GEMM_SMEM (2 * GBUF)   // 128 KB

__global__ __launch_bounds__(512, 1) void gemm_mma_kernel(float* __restrict__ Cout, int mode)
{
    extern __shared__ char smc[];
    const uint32_t sb = smem_u32(smc);
    const int tid  = threadIdx.x;
    const int wid  = tid >> 5, lane = tid & 31;
    const int z    = blockIdx.z;

    const __half *A_g, *Whi, *Wlo;
    float osc = 1.f;
    if (mode == 0) {
        A_g = g_X16 + ((size_t)z << 22);
        Whi = g_Wh16 + ((size_t)z << 20);
        Wlo = g_Wl16 + ((size_t)z << 20);
        if (z == 0) osc = 0.125f * 1.44269504f;
    } else {
        A_g = g_AO16;
        Whi = g_Wh16 + ((size_t)3 << 20);
        Wlo = g_Wl16 + ((size_t)3 << 20);
    }
    const int bM = blockIdx.y * 256, bN = blockIdx.x * 128;
    const int warp_m = (wid & 7) * 32, warp_n = (wid >> 3) * 64;

    float acc[16][4];
    #pragma unroll
    for (int i = 0; i < 16; i++)
        #pragma unroll
        for (int j = 0; j < 4; j++) acc[i][j] = 0.f;

    auto cpStage = [&](int s, int buf) {
        uint32_t base = sb + buf * GBUF;
        #pragma unroll
        for (int l = 0; l < 8; l++) {
            int f = tid + l * 512;
            const __half* src;
            uint32_t dst;
            if (f < 2048) {
                int r = f >> 3, c = f & 7;
                src = A_g + (size_t)(bM + r) * ND + s * 64 + c * 8;
                dst = base + G_A + r * 128 + ((c * 16) ^ ((r & 7) * 16));
            } else {
                int g = f - 2048;
                int arr = g >> 10;
                int r = (g >> 3) & 127, c = g & 7;
                src = (arr ? Wlo : Whi) + (size_t)(bN + r) * ND + s * 64 + c * 8;
                dst = base + (arr ? G_WL : G_WH) + r * 128 + ((c * 16) ^ ((r & 7) * 16));
            }
            cpasync16(dst, src);
        }
        CP_COMMIT();
    };

    cpStage(0, 0);

    for (int s = 0; s < 16; s++) {
        const int buf = s & 1;
        if (s + 1 < 16) { cpStage(s + 1, buf ^ 1); CP_WAIT1(); }
        else            { CP_WAIT0(); }
        __syncthreads();

        const uint32_t aS = sb + buf * GBUF + G_A;
        const uint32_t wH = sb + buf * GBUF + G_WH;
        const uint32_t wL = sb + buf * GBUF + G_WL;

        #pragma unroll
        for (int kk = 0; kk < 4; kk++) {
            const int k0 = kk * 16;
            uint32_t af[2][4];
            #pragma unroll
            for (int mt = 0; mt < 2; mt++) {
                int row = warp_m + mt * 16 + (lane & 15);
                uint32_t off = row * 128 + ((k0 * 2 + (lane >> 4) * 16) ^ ((row & 7) * 16));
                LDSM_X4(af[mt][0], af[mt][1], af[mt][2], af[mt][3], aS + off);
            }
            #pragma unroll
            for (int h = 0; h < 2; h++) {
                uint32_t bh[4][2], bl[4][2];
                #pragma unroll
                for (int p = 0; p < 2; p++) {
                    int n = warp_n + h * 32 + p * 16 + (lane & 7) + ((lane >> 4) << 3);
                    uint32_t off = n * 128 + ((k0 * 2 + ((lane >> 3) & 1) * 16) ^ ((n & 7) * 16));
                    LDSM_X4(bh[p*2][0], bh[p*2][1], bh[p*2+1][0], bh[p*2+1][1], wH + off);
                    LDSM_X4(bl[p*2][0], bl[p*2][1], bl[p*2+1][0], bl[p*2+1][1], wL + off);
                }
                #pragma unroll
                for (int mt = 0; mt < 2; mt++)
                    #pragma unroll
                    for (int nt = 0; nt < 4; nt++)
                        MMA_F16(acc[mt*8 + h*4 + nt], af[mt], bh[nt]);
                #pragma unroll
                for (int mt = 0; mt < 2; mt++)
                    #pragma unroll
                    for (int nt = 0; nt < 4; nt++)
                        MMA_F16(acc[mt*8 + h*4 + nt], af[mt], bl[nt]);
            }
        }
        __syncthreads();
    }

    #pragma unroll
    for (int mt = 0; mt < 2; mt++)
        #pragma unroll
        for (int nt = 0; nt < 8; nt++) {
            int m0 = bM + warp_m + mt * 16 + (lane >> 2);
            int n  = bN + warp_n + nt * 8 + (lane & 3) * 2;
            float* a4 = acc[mt*8+nt];
            if (mode == 0) {
                int h = n >> 6, dh = n & 63;
                int b0 = m0 >> 11, s0 = m0 & 2047;
                int m1 = m0 + 8, b1 = m1 >> 11, s1 = m1 & 2047;
                size_t i0 = ((size_t)(b0 * NH + h) * NS + s0) * NDH + dh;
                size_t i1 = ((size_t)(b1 * NH + h) * NS + s1) * NDH + dh;
                __half* O = (z == 0) ? g_Q16 : (z == 1) ? g_K16 : g_V16;
                *(uint32_t*)(O + i0) = h2pack(a4[0] * osc, a4[1] * osc);
                *(uint32_t*)(O + i1) = h2pack(a4[2] * osc, a4[3] * osc);
            } else {
                *(float2*)(Cout + (size_t)m0 * ND + n)       = make_float2(a4[0], a4[1]);
                *(float2*)(Cout + (size_t)(m0 + 8) * ND + n) = make_float2(a4[2], a4[3]);
            }
        }
}

// ---------------------------------------------------------------------------
// Flash attention on HMMA, all single-fp16 operands (Q,K,V,P).
// QK: 1-pass. PV: 1-pass. exp2-domain softmax.
// CTA = 128 q x 64 k, 8 warps, double-buffered K/V (32KB).
// ---------------------------------------------------------------------------
#define ATT_BUF  16384
#define ATT_SMEM (2 * ATT_BUF)

__global__ __launch_bounds__(256, 1) void attn_mma_kernel(const int* __restrict__ valid_lens)
{
    extern __shared__ char smc[];
    const uint32_t sb = smem_u32(smc);
    const int tid = threadIdx.x, wid = tid >> 5, lane = tid & 31;
    const int qb = blockIdx.x, bh = blockIdx.y;
    const int bb = bh >> 4, head = bh & 15;
    const int vlen = valid_lens[bb];
    const int nkb  = (vlen + 63) >> 6;

    const size_t hbase = (size_t)bh * NS * NDH;
    const __half *Q16 = g_Q16 + hbase;
    const __half *K16 = g_K16 + hbase, *V16 = g_V16 + hbase;

    const int r = lane >> 2, c2 = (lane & 3) * 2;

    uint32_t qf[4][4];
    {
        const int q0 = qb * 128 + wid * 16;
        #pragma unroll
        for (int t = 0; t < 4; t++) {
            int k0 = t * 16;
            qf[t][0] = *(const uint32_t*)(Q16 + (size_t)(q0 + r    ) * NDH + k0 + c2);
            qf[t][1] = *(const uint32_t*)(Q16 + (size_t)(q0 + r + 8) * NDH + k0 + c2);
            qf[t][2] = *(const uint32_t*)(Q16 + (size_t)(q0 + r    ) * NDH + k0 + c2 + 8);
            qf[t][3] = *(const uint32_t*)(Q16 + (size_t)(q0 + r + 8) * NDH + k0 + c2 + 8);
        }
    }

    float m_i[2] = {-1e30f, -1e30f}, l_i[2] = {0.f, 0.f};
    float o[8][4];
    #pragma unroll
    for (int i = 0; i < 8; i++)
        #pragma unroll
        for (int j = 0; j < 4; j++) o[i][j] = 0.f;

    auto cpKV = [&](int kb, int buf) {
        #pragma unroll
        for (int l = 0; l < 4; l++) {
            int f   = tid + l * 256;
            int arr = f >> 9;                 // 0:K 1:V
            int rr  = (f >> 3) & 63;
            int cc  = f & 7;
            const void* src = (arr ? V16 : K16) + (size_t)(kb * 64 + rr) * NDH + cc * 8;
            uint32_t dst = sb + buf * ATT_BUF + arr * 8192
                         + rr * 128 + ((cc * 16) ^ ((rr & 7) * 16));
            cpasync16(dst, src);
        }
        CP_COMMIT();
    };

    cpKV(0, 0);

    for (int kb = 0; kb < nkb; kb++) {
        const int buf = kb & 1;
        CP_WAIT0();
        __syncthreads();
        if (kb + 1 < nkb) cpKV(kb + 1, buf ^ 1);

        const uint32_t kS = sb + buf * ATT_BUF;
        const uint32_t vS = kS + 8192;

        // ---- S = Q K^T (1-pass fp16) ----
        float s[8][4];
        #pragma unroll
        for (int i = 0; i < 8; i++)
            #pragma unroll
            for (int j = 0; j < 4; j++) s[i][j] = 0.f;

        #pragma unroll
        for (int t = 0; t < 4; t++) {
            uint32_t kf[8][2];
            #pragma unroll
            for (int p = 0; p < 4; p++) {
                int n = p * 16 + (lane & 7) + ((lane >> 4) << 3);
                uint32_t off = n * 128 + ((t * 32 + ((lane >> 3) & 1) * 16) ^ ((n & 7) * 16));
                LDSM_X4(kf[p*2][0], kf[p*2][1], kf[p*2+1][0], kf[p*2+1][1], kS + off);
            }
            #pragma unroll
            for (int nt = 0; nt < 8; nt++)
                MMA_F16(s[nt], qf[t], kf[nt]);
        }

        if (kb == nkb - 1) {
            int cb = kb * 64 + c2;
            #pragma unroll
            for (int nt = 0; nt < 8; nt++) {
                int c0g = cb + nt * 8;
                if (c0g     >= vlen) { s[nt][0] = -1e30f; s[nt][2] = -1e30f; }
                if (c0g + 1 >= vlen) { s[nt][1] = -1e30f; s[nt][3] = -1e30f; }
            }
        }

        // ---- online softmax (base-2 domain) ----
        float mx0 = -1e30f, mx1 = -1e30f;
        #pragma unroll
        for (int nt = 0; nt < 8; nt++) {
            mx0 = fmaxf(mx0, fmaxf(s[nt][0], s[nt][1]));
            mx1 = fmaxf(mx1, fmaxf(s[nt][2], s[nt][3]));
        }
        mx0 = fmaxf(mx0, __shfl_xor_sync(0xffffffffu, mx0, 1));
        mx0 = fmaxf(mx0, __shfl_xor_sync(0xffffffffu, mx0, 2));
        mx1 = fmaxf(mx1, __shfl_xor_sync(0xffffffffu, mx1, 1));
        mx1 = fmaxf(mx1, __shfl_xor_sync(0xffffffffu, mx1, 2));

        float mn0 = fmaxf(m_i[0], mx0), mn1 = fmaxf(m_i[1], mx1);
        float a0 = ex2f(m_i[0] - mn0), a1 = ex2f(m_i[1] - mn1);
        m_i[0] = mn0; m_i[1] = mn1;

        float sum0 = 0.f, sum1 = 0.f;
        #pragma unroll
        for (int nt = 0; nt < 8; nt++) {
            s[nt][0] = ex2f(s[nt][0] - mn0); sum0 += s[nt][0];
            s[nt][1] = ex2f(s[nt][1] - mn0); sum0 += s[nt][1];
            s[nt][2] = ex2f(s[nt][2] - mn1); sum1 += s[nt][2];
            s[nt][3] = ex2f(s[nt][3] - mn1); sum1 += s[nt][3];
        }
        sum0 += __shfl_xor_sync(0xffffffffu, sum0, 1);
        sum0 += __shfl_xor_sync(0xffffffffu, sum0, 2);
        sum1 += __shfl_xor_sync(0xffffffffu, sum1, 1);
        sum1 += __shfl_xor_sync(0xffffffffu, sum1, 2);
        l_i[0] = l_i[0] * a0 + sum0;
        l_i[1] = l_i[1] * a1 + sum1;
        #pragma unroll
        for (int nt = 0; nt < 8; nt++) {
            o[nt][0] *= a0; o[nt][1] *= a0;
            o[nt][2] *= a1; o[nt][3] *= a1;
        }

        // ---- O += P V (1-pass) ----
        #pragma unroll
        for (int t = 0; t < 4; t++) {
            uint32_t ph[4];
            ph[0] = h2pack(s[2*t  ][0], s[2*t  ][1]);
            ph[1] = h2pack(s[2*t  ][2], s[2*t  ][3]);
            ph[2] = h2pack(s[2*t+1][0], s[2*t+1][1]);
            ph[3] = h2pack(s[2*t+1][2], s[2*t+1][3]);

            uint32_t vf[8][2];
            #pragma unroll
            for (int p = 0; p < 4; p++) {
                int rowb = t * 16 + (lane & 15);
                uint32_t off = rowb * 128 + ((p * 32 + (lane >> 4) * 16) ^ ((rowb & 7) * 16));
                LDSM_X4_T(vf[p*2][0], vf[p*2][1], vf[p*2+1][0], vf[p*2+1][1], vS + off);
            }
            #pragma unroll
            for (int nt = 0; nt < 8; nt++)
                MMA_F16(o[nt], ph, vf[nt]);
        }
    }

    // epilogue: single fp16 to g_AO16 [B*S][D]
    const float inv0 = 1.f / l_i[0], inv1 = 1.f / l_i[1];
    const int row0 = qb * 128 + wid * 16 + r;
    const size_t base0 = (size_t)(bb * NS + row0    ) * ND + head * 64;
    const size_t base1 = (size_t)(bb * NS + row0 + 8) * ND + head * 64;
    #pragma unroll
    for (int nt = 0; nt < 8; nt++) {
        *(uint32_t*)(g_AO16 + base0 + nt * 8 + c2) = h2pack(o[nt][0] * inv0, o[nt][1] * inv0);
        *(uint32_t*)(g_AO16 + base1 + nt * 8 + c2) = h2pack(o[nt][2] * inv1, o[nt][3] * inv1);
    }
}

// ---------------------------------------------------------------------------
extern "C" void kernel_launch(void* const* d_in, const int* in_sizes, int n_in,
                              void* d_out, int out_size)
{
    const float* q  = (const float*)d_in[0];
    const float* k  = (const float*)d_in[1];
    const float* v  = (const float*)d_in[2];
    const int*   vl = (const int*)  d_in[3];
    const float* Wq = (const float*)d_in[4];
    const float* Wk = (const float*)d_in[5];
    const float* Wv = (const float*)d_in[6];
    const float* Wo = (const float*)d_in[7];
    float* out = (float*)d_out;

    cudaFuncSetAttribute(gemm_mma_kernel, cudaFuncAttributeMaxDynamicSharedMemorySize,
                         GEMM_SMEM);
    cudaFuncSetAttribute(attn_mma_kernel, cudaFuncAttributeMaxDynamicSharedMemorySize,
                         ATT_SMEM);

    // prep: z<3 X convert (grid.x=4096 chunks), z>=3 W split (first 1024 blocks)
    prep_kernel<<<dim3(4096, 1, 7), 256>>>(q, k, v, Wq, Wk, Wv, Wo);

    gemm_mma_kernel<<<dim3(ND / 128, (NB * NS) / 256, 3), 512, GEMM_SMEM>>>(out, 0);

    attn_mma_kernel<<<dim3(NS / 128, NB * NH), 256, ATT_SMEM>>>(vl);

    gemm_mma_kernel<<<dim3(ND / 128, (NB * NS) / 256, 1), 512, GEMM_SMEM>>>(out, 1);
}

// round 13
// speedup vs baseline: 1.5830x; 1.0071x over previous
#include <cuda_runtime.h>
#include <cuda_bf16.h>
#include <cuda_fp16.h>
#include <stdint.h>

#define NB  2
#define NS  2048
#define ND  1024
#define NH  16
#define NDH 64

// Scratch (allocation-free rule: __device__ globals).
__device__ __half g_Wh16[4u << 20], g_Wl16[4u << 20];  // 4 x W^T fp16 hi/lo: [n][k]
__device__ __half g_X16 [3u << 22];                    // single-fp16 Xq/Xk/Xv [4096][1024]
__device__ __half g_AO16[1u << 22];                    // single-fp16 attn out [4096][1024]
// head-major [B,H,S,DH]: Q/K/V all single fp16 (Q pre-scaled by 0.125*log2e)
__device__ __half g_Q16[NB*NH*NS*NDH];
__device__ __half g_K16[NB*NH*NS*NDH];
__device__ __half g_V16[NB*NH*NS*NDH];

// ---------------------------------------------------------------------------
// helpers
// ---------------------------------------------------------------------------
__device__ __forceinline__ uint32_t smem_u32(const void* p) {
    uint32_t a;
    asm("{ .reg .u64 t; cvta.to.shared.u64 t, %1; cvt.u32.u64 %0, t; }" : "=r"(a) : "l"(p));
    return a;
}
__device__ __forceinline__ void cpasync16(uint32_t dst, const void* src) {
    asm volatile("cp.async.cg.shared.global [%0], [%1], 16;" :: "r"(dst), "l"(src));
}
#define CP_COMMIT() asm volatile("cp.async.commit_group;" ::: "memory")
#define CP_WAIT0()  asm volatile("cp.async.wait_group 0;" ::: "memory")
#define CP_WAIT1()  asm volatile("cp.async.wait_group 1;" ::: "memory")

#define LDSM_X4(r0, r1, r2, r3, addr)                                          \
    asm volatile("ldmatrix.sync.aligned.m8n8.x4.shared.b16 {%0,%1,%2,%3}, [%4];" \
        : "=r"(r0), "=r"(r1), "=r"(r2), "=r"(r3) : "r"(addr))
#define LDSM_X4_T(r0, r1, r2, r3, addr)                                        \
    asm volatile("ldmatrix.sync.aligned.m8n8.x4.trans.shared.b16 {%0,%1,%2,%3}, [%4];" \
        : "=r"(r0), "=r"(r1), "=r"(r2), "=r"(r3) : "r"(addr))

#define MMA_F16(d, a, b)                                                       \
    asm volatile("mma.sync.aligned.m16n8k16.row.col.f32.f16.f16.f32 "          \
        "{%0,%1,%2,%3},{%4,%5,%6,%7},{%8,%9},{%0,%1,%2,%3};"                   \
        : "+f"((d)[0]), "+f"((d)[1]), "+f"((d)[2]), "+f"((d)[3])               \
        : "r"((a)[0]), "r"((a)[1]), "r"((a)[2]), "r"((a)[3]),                  \
          "r"((b)[0]), "r"((b)[1]))

__device__ __forceinline__ float ex2f(float x) {
    float y; asm("ex2.approx.f32 %0, %1;" : "=f"(y) : "f"(x)); return y;
}
__device__ __forceinline__ uint32_t h2pack(float a, float b) {
    __half2 h = __floats2half2_rn(a, b);
    return *(uint32_t*)&h;
}

// ---------------------------------------------------------------------------
// Prep: z 0..2 -> X fp32->fp16 convert (grid.x = 4096);
//       z 3..6 -> W transpose + fp16 hi/lo (only grid.x < 1024 valid).
// ---------------------------------------------------------------------------
__global__ __launch_bounds__(256) void prep_kernel(
    const float* __restrict__ X0, const float* __restrict__ X1,
    const float* __restrict__ X2,
    const float* __restrict__ W0, const float* __restrict__ W1,
    const float* __restrict__ W2, const float* __restrict__ W3)
{
    const int z = blockIdx.z;
    if (z < 3) {
        const float* X = (z == 0) ? X0 : (z == 1) ? X1 : X2;
        __half* O = g_X16 + ((size_t)z << 22);
        size_t idx = (size_t)blockIdx.x * 256 + threadIdx.x;
        float4 v = *((const float4*)X + idx);
        uint2 o;
        o.x = h2pack(v.x, v.y);
        o.y = h2pack(v.z, v.w);
        *((uint2*)O + idx) = o;
    } else {
        if (blockIdx.x >= 1024) return;   // only 32x32 = 1024 W tiles
        __shared__ float t[32][33];
        int wz = z - 3;
        const float* W = (wz == 0) ? W0 : (wz == 1) ? W1 : (wz == 2) ? W2 : W3;
        __half* Ohi = g_Wh16 + ((size_t)wz << 20);
        __half* Olo = g_Wl16 + ((size_t)wz << 20);
        int tx = threadIdx.x & 31, ty = threadIdx.x >> 5;
        int n0 = (blockIdx.x & 31) * 32, k0 = (blockIdx.x >> 5) * 32;
        #pragma unroll
        for (int i = 0; i < 4; i++)
            t[ty + i*8][tx] = W[(size_t)(k0 + ty + i*8) * ND + n0 + tx];
        __syncthreads();
        #pragma unroll
        for (int i = 0; i < 4; i++) {
            float v = t[tx][ty + i*8];
            __half h = __float2half_rn(v);
            __half l = __float2half_rn(v - __half2float(h));
            size_t idx = (size_t)(n0 + ty + i*8) * ND + k0 + tx;
            Ohi[idx] = h; Olo[idx] = l;
        }
    }
}

// ---------------------------------------------------------------------------
// HMMA 2-pass fp16 GEMM: D = A * (Wh + Wl). A single fp16, W split hi/lo.
// CTA 128M x 128N, BK=64, 256 threads (8 warps, 32m x 64n each),
// double-buffered 2 x 48KB = 96KB -> 2 CTAs/SM (barrier-bubble overlap).
// mode 0: z=0 -> Q (single fp16, scaled 0.125*log2e), z=1 -> K, z=2 -> V.
// mode 1: A = g_AO16, fp32 out.
// ---------------------------------------------------------------------------
#define GBUF   49152
#define G_A    0
#define G_WH   16384
#define G_WL   32768
#define GEMM_SMEM (2 * GBUF)   // 96 KB

__global__ __launch_bounds__(256, 2) void gemm_mma_kernel(float* __restrict__ Cout, int mode)
{
    extern __shared__ char smc[];
    const uint32_t sb = smem_u32(smc);
    const int tid  = threadIdx.x;
    const int wid  = tid >> 5, lane = tid & 31;
    const int z    = blockIdx.z;

    const __half *A_g, *Whi, *Wlo;
    float osc = 1.f;
    if (mode == 0) {
        A_g = g_X16 + ((size_t)z << 22);
        Whi = g_Wh16 + ((size_t)z << 20);
        Wlo = g_Wl16 + ((size_t)z << 20);
        if (z == 0) osc = 0.125f * 1.44269504f;
    } else {
        A_g = g_AO16;
        Whi = g_Wh16 + ((size_t)3 << 20);
        Wlo = g_Wl16 + ((size_t)3 << 20);
    }
    const int bM = blockIdx.y * 128, bN = blockIdx.x * 128;
    const int warp_m = (wid & 3) * 32, warp_n = (wid >> 2) * 64;

    float acc[16][4];
    #pragma unroll
    for (int i = 0; i < 16; i++)
        #pragma unroll
        for (int j = 0; j < 4; j++) acc[i][j] = 0.f;

    // Stage = 48KB: A 128x64 fp16 (16KB) | Wh 16KB | Wl 16KB.
    // 3072 cp.async of 16B; 12 per thread.
    auto cpStage = [&](int s, int buf) {
        uint32_t base = sb + buf * GBUF;
        #pragma unroll
        for (int l = 0; l < 12; l++) {
            int f = tid + l * 256;
            const __half* src;
            uint32_t dst;
            if (f < 1024) {                     // A: 128 rows x 8 chunks
                int r = f >> 3, c = f & 7;
                src = A_g + (size_t)(bM + r) * ND + s * 64 + c * 8;
                dst = base + G_A + r * 128 + ((c * 16) ^ ((r & 7) * 16));
            } else {                            // W hi/lo: 128 rows x 8 chunks each
                int g = f - 1024;
                int arr = g >> 10;
                int r = (g >> 3) & 127, c = g & 7;
                src = (arr ? Wlo : Whi) + (size_t)(bN + r) * ND + s * 64 + c * 8;
                dst = base + (arr ? G_WL : G_WH) + r * 128 + ((c * 16) ^ ((r & 7) * 16));
            }
            cpasync16(dst, src);
        }
        CP_COMMIT();
    };

    cpStage(0, 0);

    for (int s = 0; s < 16; s++) {
        const int buf = s & 1;
        if (s + 1 < 16) { cpStage(s + 1, buf ^ 1); CP_WAIT1(); }
        else            { CP_WAIT0(); }
        __syncthreads();

        const uint32_t aS = sb + buf * GBUF + G_A;
        const uint32_t wH = sb + buf * GBUF + G_WH;
        const uint32_t wL = sb + buf * GBUF + G_WL;

        #pragma unroll
        for (int kk = 0; kk < 4; kk++) {
            const int k0 = kk * 16;
            uint32_t af[2][4];
            #pragma unroll
            for (int mt = 0; mt < 2; mt++) {
                int row = warp_m + mt * 16 + (lane & 15);
                uint32_t off = row * 128 + ((k0 * 2 + (lane >> 4) * 16) ^ ((row & 7) * 16));
                LDSM_X4(af[mt][0], af[mt][1], af[mt][2], af[mt][3], aS + off);
            }
            #pragma unroll
            for (int h = 0; h < 2; h++) {
                uint32_t bh[4][2], bl[4][2];
                #pragma unroll
                for (int p = 0; p < 2; p++) {
                    int n = warp_n + h * 32 + p * 16 + (lane & 7) + ((lane >> 4) << 3);
                    uint32_t off = n * 128 + ((k0 * 2 + ((lane >> 3) & 1) * 16) ^ ((n & 7) * 16));
                    LDSM_X4(bh[p*2][0], bh[p*2][1], bh[p*2+1][0], bh[p*2+1][1], wH + off);
                    LDSM_X4(bl[p*2][0], bl[p*2][1], bl[p*2+1][0], bl[p*2+1][1], wL + off);
                }
                #pragma unroll
                for (int mt = 0; mt < 2; mt++)
                    #pragma unroll
                    for (int nt = 0; nt < 4; nt++)
                        MMA_F16(acc[mt*8 + h*4 + nt], af[mt], bh[nt]);
                #pragma unroll
                for (int mt = 0; mt < 2; mt++)
                    #pragma unroll
                    for (int nt = 0; nt < 4; nt++)
                        MMA_F16(acc[mt*8 + h*4 + nt], af[mt], bl[nt]);
            }
        }
        __syncthreads();
    }

    #pragma unroll
    for (int mt = 0; mt < 2; mt++)
        #pragma unroll
        for (int nt = 0; nt < 8; nt++) {
            int m0 = bM + warp_m + mt * 16 + (lane >> 2);
            int n  = bN + warp_n + nt * 8 + (lane & 3) * 2;
            float* a4 = acc[mt*8+nt];
            if (mode == 0) {
                int h = n >> 6, dh = n & 63;
                int b0 = m0 >> 11, s0 = m0 & 2047;
                int m1 = m0 + 8, b1 = m1 >> 11, s1 = m1 & 2047;
                size_t i0 = ((size_t)(b0 * NH + h) * NS + s0) * NDH + dh;
                size_t i1 = ((size_t)(b1 * NH + h) * NS + s1) * NDH + dh;
                __half* O = (z == 0) ? g_Q16 : (z == 1) ? g_K16 : g_V16;
                *(uint32_t*)(O + i0) = h2pack(a4[0] * osc, a4[1] * osc);
                *(uint32_t*)(O + i1) = h2pack(a4[2] * osc, a4[3] * osc);
            } else {
                *(float2*)(Cout + (size_t)m0 * ND + n)       = make_float2(a4[0], a4[1]);
                *(float2*)(Cout + (size_t)(m0 + 8) * ND + n) = make_float2(a4[2], a4[3]);
            }
        }
}

// ---------------------------------------------------------------------------
// Flash attention on HMMA, all single-fp16 operands (Q,K,V,P).
// QK: 1-pass. PV: 1-pass. exp2-domain softmax.
// CTA = 128 q x 64 k, 8 warps, double-buffered K/V (32KB).
// ---------------------------------------------------------------------------
#define ATT_BUF  16384
#define ATT_SMEM (2 * ATT_BUF)

__global__ __launch_bounds__(256, 1) void attn_mma_kernel(const int* __restrict__ valid_lens)
{
    extern __shared__ char smc[];
    const uint32_t sb = smem_u32(smc);
    const int tid = threadIdx.x, wid = tid >> 5, lane = tid & 31;
    const int qb = blockIdx.x, bh = blockIdx.y;
    const int bb = bh >> 4, head = bh & 15;
    const int vlen = valid_lens[bb];
    const int nkb  = (vlen + 63) >> 6;

    const size_t hbase = (size_t)bh * NS * NDH;
    const __half *Q16 = g_Q16 + hbase;
    const __half *K16 = g_K16 + hbase, *V16 = g_V16 + hbase;

    const int r = lane >> 2, c2 = (lane & 3) * 2;

    uint32_t qf[4][4];
    {
        const int q0 = qb * 128 + wid * 16;
        #pragma unroll
        for (int t = 0; t < 4; t++) {
            int k0 = t * 16;
            qf[t][0] = *(const uint32_t*)(Q16 + (size_t)(q0 + r    ) * NDH + k0 + c2);
            qf[t][1] = *(const uint32_t*)(Q16 + (size_t)(q0 + r + 8) * NDH + k0 + c2);
            qf[t][2] = *(const uint32_t*)(Q16 + (size_t)(q0 + r    ) * NDH + k0 + c2 + 8);
            qf[t][3] = *(const uint32_t*)(Q16 + (size_t)(q0 + r + 8) * NDH + k0 + c2 + 8);
        }
    }

    float m_i[2] = {-1e30f, -1e30f}, l_i[2] = {0.f, 0.f};
    float o[8][4];
    #pragma unroll
    for (int i = 0; i < 8; i++)
        #pragma unroll
        for (int j = 0; j < 4; j++) o[i][j] = 0.f;

    auto cpKV = [&](int kb, int buf) {
        #pragma unroll
        for (int l = 0; l < 4; l++) {
            int f   = tid + l * 256;
            int arr = f >> 9;                 // 0:K 1:V
            int rr  = (f >> 3) & 63;
            int cc  = f & 7;
            const void* src = (arr ? V16 : K16) + (size_t)(kb * 64 + rr) * NDH + cc * 8;
            uint32_t dst = sb + buf * ATT_BUF + arr * 8192
                         + rr * 128 + ((cc * 16) ^ ((rr & 7) * 16));
            cpasync16(dst, src);
        }
        CP_COMMIT();
    };

    cpKV(0, 0);

    for (int kb = 0; kb < nkb; kb++) {
        const int buf = kb & 1;
        CP_WAIT0();
        __syncthreads();
        if (kb + 1 < nkb) cpKV(kb + 1, buf ^ 1);

        const uint32_t kS = sb + buf * ATT_BUF;
        const uint32_t vS = kS + 8192;

        // ---- S = Q K^T (1-pass fp16) ----
        float s[8][4];
        #pragma unroll
        for (int i = 0; i < 8; i++)
            #pragma unroll
            for (int j = 0; j < 4; j++) s[i][j] = 0.f;

        #pragma unroll
        for (int t = 0; t < 4; t++) {
            uint32_t kf[8][2];
            #pragma unroll
            for (int p = 0; p < 4; p++) {
                int n = p * 16 + (lane & 7) + ((lane >> 4) << 3);
                uint32_t off = n * 128 + ((t * 32 + ((lane >> 3) & 1) * 16) ^ ((n & 7) * 16));
                LDSM_X4(kf[p*2][0], kf[p*2][1], kf[p*2+1][0], kf[p*2+1][1], kS + off);
            }
            #pragma unroll
            for (int nt = 0; nt < 8; nt++)
                MMA_F16(s[nt], qf[t], kf[nt]);
        }

        if (kb == nkb - 1) {
            int cb = kb * 64 + c2;
            #pragma unroll
            for (int nt = 0; nt < 8; nt++) {
                int c0g = cb + nt * 8;
                if (c0g     >= vlen) { s[nt][0] = -1e30f; s[nt][2] = -1e30f; }
                if (c0g + 1 >= vlen) { s[nt][1] = -1e30f; s[nt][3] = -1e30f; }
            }
        }

        // ---- online softmax (base-2 domain) ----
        float mx0 = -1e30f, mx1 = -1e30f;
        #pragma unroll
        for (int nt = 0; nt < 8; nt++) {
            mx0 = fmaxf(mx0, fmaxf(s[nt][0], s[nt][1]));
            mx1 = fmaxf(mx1, fmaxf(s[nt][2], s[nt][3]));
        }
        mx0 = fmaxf(mx0, __shfl_xor_sync(0xffffffffu, mx0, 1));
        mx0 = fmaxf(mx0, __shfl_xor_sync(0xffffffffu, mx0, 2));
        mx1 = fmaxf(mx1, __shfl_xor_sync(0xffffffffu, mx1, 1));
        mx1 = fmaxf(mx1, __shfl_xor_sync(0xffffffffu, mx1, 2));

        float mn0 = fmaxf(m_i[0], mx0), mn1 = fmaxf(m_i[1], mx1);
        float a0 = ex2f(m_i[0] - mn0), a1 = ex2f(m_i[1] - mn1);
        m_i[0] = mn0; m_i[1] = mn1;

        float sum0 = 0.f, sum1 = 0.f;
        #pragma unroll
        for (int nt = 0; nt < 8; nt++) {
            s[nt][0] = ex2f(s[nt][0] - mn0); sum0 += s[nt][0];
            s[nt][1] = ex2f(s[nt][1] - mn0); sum0 += s[nt][1];
            s[nt][2] = ex2f(s[nt][2] - mn1); sum1 += s[nt][2];
            s[nt][3] = ex2f(s[nt][3] - mn1); sum1 += s[nt][3];
        }
        sum0 += __shfl_xor_sync(0xffffffffu, sum0, 1);
        sum0 += __shfl_xor_sync(0xffffffffu, sum0, 2);
        sum1 += __shfl_xor_sync(0xffffffffu, sum1, 1);
        sum1 += __shfl_xor_sync(0xffffffffu, sum1, 2);
        l_i[0] = l_i[0] * a0 + sum0;
        l_i[1] = l_i[1] * a1 + sum1;
        #pragma unroll
        for (int nt = 0; nt < 8; nt++) {
            o[nt][0] *= a0; o[nt][1] *= a0;
            o[nt][2] *= a1; o[nt][3] *= a1;
        }

        // ---- O += P V (1-pass) ----
        #pragma unroll
        for (int t = 0; t < 4; t++) {
            uint32_t ph[4];
            ph[0] = h2pack(s[2*t  ][0], s[2*t  ][1]);
            ph[1] = h2pack(s[2*t  ][2], s[2*t  ][3]);
            ph[2] = h2pack(s[2*t+1][0], s[2*t+1][1]);
            ph[3] = h2pack(s[2*t+1][2], s[2*t+1][3]);

            uint32_t vf[8][2];
            #pragma unroll
            for (int p = 0; p < 4; p++) {
                int rowb = t * 16 + (lane & 15);
                uint32_t off = rowb * 128 + ((p * 32 + (lane >> 4) * 16) ^ ((rowb & 7) * 16));
                LDSM_X4_T(vf[p*2][0], vf[p*2][1], vf[p*2+1][0], vf[p*2+1][1], vS + off);
            }
            #pragma unroll
            for (int nt = 0; nt < 8; nt++)
                MMA_F16(o[nt], ph, vf[nt]);
        }
    }

    // epilogue: single fp16 to g_AO16 [B*S][D]
    const float inv0 = 1.f / l_i[0], inv1 = 1.f / l_i[1];
    const int row0 = qb * 128 + wid * 16 + r;
    const size_t base0 = (size_t)(bb * NS + row0    ) * ND + head * 64;
    const size_t base1 = (size_t)(bb * NS + row0 + 8) * ND + head * 64;
    #pragma unroll
    for (int nt = 0; nt < 8; nt++) {
        *(uint32_t*)(g_AO16 + base0 + nt * 8 + c2) = h2pack(o[nt][0] * inv0, o[nt][1] * inv0);
        *(uint32_t*)(g_AO16 + base1 + nt * 8 + c2) = h2pack(o[nt][2] * inv1, o[nt][3] * inv1);
    }
}

// ---------------------------------------------------------------------------
extern "C" void kernel_launch(void* const* d_in, const int* in_sizes, int n_in,
                              void* d_out, int out_size)
{
    const float* q  = (const float*)d_in[0];
    const float* k  = (const float*)d_in[1];
    const float* v  = (const float*)d_in[2];
    const int*   vl = (const int*)  d_in[3];
    const float* Wq = (const float*)d_in[4];
    const float* Wk = (const float*)d_in[5];
    const float* Wv = (const float*)d_in[6];
    const float* Wo = (const float*)d_in[7];
    float* out = (float*)d_out;

    cudaFuncSetAttribute(gemm_mma_kernel, cudaFuncAttributeMaxDynamicSharedMemorySize,
                         GEMM_SMEM);
    cudaFuncSetAttribute(attn_mma_kernel, cudaFuncAttributeMaxDynamicSharedMemorySize,
                         ATT_SMEM);

    // prep: z<3 X convert (grid.x=4096 chunks), z>=3 W split (first 1024 blocks)
    prep_kernel<<<dim3(4096, 1, 7), 256>>>(q, k, v, Wq, Wk, Wv, Wo);

    // 128x128 tiles: grid (8, 32, z)
    gemm_mma_kernel<<<dim3(ND / 128, (NB * NS) / 128, 3), 256, GEMM_SMEM>>>(out, 0);

    attn_mma_kernel<<<dim3(NS / 128, NB * NH), 256, ATT_SMEM>>>(vl);

    gemm_mma_kernel<<<dim3(ND / 128, (NB * NS) / 128, 1), 256, GEMM_SMEM>>>(out, 1);
}

// round 14
// speedup vs baseline: 2.3164x; 1.4633x over previous
#include <cuda_runtime.h>
#include <cuda_bf16.h>
#include <cuda_fp16.h>
#include <stdint.h>

#define NB  2
#define NS  2048
#define ND  1024
#define NH  16
#define NDH 64

// Scratch (allocation-free rule: __device__ globals).
__device__ __half g_W16 [4u << 20];                    // 4 x W^T single fp16: [n][k]
__device__ __half g_X16 [3u << 22];                    // single-fp16 Xq/Xk/Xv [4096][1024]
__device__ __half g_AO16[1u << 22];                    // single-fp16 attn out [4096][1024]
// head-major [B,H,S,DH]: Q/K/V all single fp16 (Q pre-scaled by 0.125*log2e)
__device__ __half g_Q16[NB*NH*NS*NDH];
__device__ __half g_K16[NB*NH*NS*NDH];
__device__ __half g_V16[NB*NH*NS*NDH];

// ---------------------------------------------------------------------------
// helpers
// ---------------------------------------------------------------------------
__device__ __forceinline__ uint32_t smem_u32(const void* p) {
    uint32_t a;
    asm("{ .reg .u64 t; cvta.to.shared.u64 t, %1; cvt.u32.u64 %0, t; }" : "=r"(a) : "l"(p));
    return a;
}
__device__ __forceinline__ void cpasync16(uint32_t dst, const void* src) {
    asm volatile("cp.async.cg.shared.global [%0], [%1], 16;" :: "r"(dst), "l"(src));
}
#define CP_COMMIT() asm volatile("cp.async.commit_group;" ::: "memory")
#define CP_WAIT0()  asm volatile("cp.async.wait_group 0;" ::: "memory")
#define CP_WAIT1()  asm volatile("cp.async.wait_group 1;" ::: "memory")

#define LDSM_X4(r0, r1, r2, r3, addr)                                          \
    asm volatile("ldmatrix.sync.aligned.m8n8.x4.shared.b16 {%0,%1,%2,%3}, [%4];" \
        : "=r"(r0), "=r"(r1), "=r"(r2), "=r"(r3) : "r"(addr))
#define LDSM_X4_T(r0, r1, r2, r3, addr)                                        \
    asm volatile("ldmatrix.sync.aligned.m8n8.x4.trans.shared.b16 {%0,%1,%2,%3}, [%4];" \
        : "=r"(r0), "=r"(r1), "=r"(r2), "=r"(r3) : "r"(addr))

#define MMA_F16(d, a, b)                                                       \
    asm volatile("mma.sync.aligned.m16n8k16.row.col.f32.f16.f16.f32 "          \
        "{%0,%1,%2,%3},{%4,%5,%6,%7},{%8,%9},{%0,%1,%2,%3};"                   \
        : "+f"((d)[0]), "+f"((d)[1]), "+f"((d)[2]), "+f"((d)[3])               \
        : "r"((a)[0]), "r"((a)[1]), "r"((a)[2]), "r"((a)[3]),                  \
          "r"((b)[0]), "r"((b)[1]))

__device__ __forceinline__ float ex2f(float x) {
    float y; asm("ex2.approx.f32 %0, %1;" : "=f"(y) : "f"(x)); return y;
}
__device__ __forceinline__ uint32_t h2pack(float a, float b) {
    __half2 h = __floats2half2_rn(a, b);
    return *(uint32_t*)&h;
}

// ---------------------------------------------------------------------------
// Prep: z 0..2 -> X fp32->fp16 convert (grid.x = 4096);
//       z 3..6 -> W transpose + fp16 convert (only grid.x < 1024 valid).
// ---------------------------------------------------------------------------
__global__ __launch_bounds__(256) void prep_kernel(
    const float* __restrict__ X0, const float* __restrict__ X1,
    const float* __restrict__ X2,
    const float* __restrict__ W0, const float* __restrict__ W1,
    const float* __restrict__ W2, const float* __restrict__ W3)
{
    const int z = blockIdx.z;
    if (z < 3) {
        const float* X = (z == 0) ? X0 : (z == 1) ? X1 : X2;
        __half* O = g_X16 + ((size_t)z << 22);
        size_t idx = (size_t)blockIdx.x * 256 + threadIdx.x;
        float4 v = *((const float4*)X + idx);
        uint2 o;
        o.x = h2pack(v.x, v.y);
        o.y = h2pack(v.z, v.w);
        *((uint2*)O + idx) = o;
    } else {
        if (blockIdx.x >= 1024) return;   // only 32x32 = 1024 W tiles
        __shared__ float t[32][33];
        int wz = z - 3;
        const float* W = (wz == 0) ? W0 : (wz == 1) ? W1 : (wz == 2) ? W2 : W3;
        __half* O = g_W16 + ((size_t)wz << 20);
        int tx = threadIdx.x & 31, ty = threadIdx.x >> 5;
        int n0 = (blockIdx.x & 31) * 32, k0 = (blockIdx.x >> 5) * 32;
        #pragma unroll
        for (int i = 0; i < 4; i++)
            t[ty + i*8][tx] = W[(size_t)(k0 + ty + i*8) * ND + n0 + tx];
        __syncthreads();
        #pragma unroll
        for (int i = 0; i < 4; i++) {
            float v = t[tx][ty + i*8];
            O[(size_t)(n0 + ty + i*8) * ND + k0 + tx] = __float2half_rn(v);
        }
    }
}

// ---------------------------------------------------------------------------
// HMMA single-pass fp16 GEMM: D = A * W. Both single fp16.
// CTA 128M x 128N, BK=64, 256 threads (8 warps, 32m x 64n each),
// double-buffered 2 x 32KB = 64KB -> 2 CTAs/SM.
// mode 0: z=0 -> Q (single fp16, scaled 0.125*log2e), z=1 -> K, z=2 -> V.
// mode 1: A = g_AO16, fp32 out.
// ---------------------------------------------------------------------------
#define GBUF   32768
#define G_A    0
#define G_W    16384
#define GEMM_SMEM (2 * GBUF)   // 64 KB

__global__ __launch_bounds__(256, 2) void gemm_mma_kernel(float* __restrict__ Cout, int mode)
{
    extern __shared__ char smc[];
    const uint32_t sb = smem_u32(smc);
    const int tid  = threadIdx.x;
    const int wid  = tid >> 5, lane = tid & 31;
    const int z    = blockIdx.z;

    const __half *A_g, *Wg;
    float osc = 1.f;
    if (mode == 0) {
        A_g = g_X16 + ((size_t)z << 22);
        Wg  = g_W16 + ((size_t)z << 20);
        if (z == 0) osc = 0.125f * 1.44269504f;
    } else {
        A_g = g_AO16;
        Wg  = g_W16 + ((size_t)3 << 20);
    }
    const int bM = blockIdx.y * 128, bN = blockIdx.x * 128;
    const int warp_m = (wid & 3) * 32, warp_n = (wid >> 2) * 64;

    float acc[16][4];
    #pragma unroll
    for (int i = 0; i < 16; i++)
        #pragma unroll
        for (int j = 0; j < 4; j++) acc[i][j] = 0.f;

    // Stage = 32KB: A 128x64 fp16 (16KB) | W 128x64 fp16 (16KB).
    // 2048 cp.async of 16B; 8 per thread.
    auto cpStage = [&](int s, int buf) {
        uint32_t base = sb + buf * GBUF;
        #pragma unroll
        for (int l = 0; l < 8; l++) {
            int f = tid + l * 256;
            const __half* src;
            uint32_t dst;
            if (f < 1024) {                     // A: 128 rows x 8 chunks
                int r = f >> 3, c = f & 7;
                src = A_g + (size_t)(bM + r) * ND + s * 64 + c * 8;
                dst = base + G_A + r * 128 + ((c * 16) ^ ((r & 7) * 16));
            } else {                            // W: 128 rows x 8 chunks
                int g = f - 1024;
                int r = g >> 3, c = g & 7;
                src = Wg + (size_t)(bN + r) * ND + s * 64 + c * 8;
                dst = base + G_W + r * 128 + ((c * 16) ^ ((r & 7) * 16));
            }
            cpasync16(dst, src);
        }
        CP_COMMIT();
    };

    cpStage(0, 0);

    for (int s = 0; s < 16; s++) {
        const int buf = s & 1;
        if (s + 1 < 16) { cpStage(s + 1, buf ^ 1); CP_WAIT1(); }
        else            { CP_WAIT0(); }
        __syncthreads();

        const uint32_t aS = sb + buf * GBUF + G_A;
        const uint32_t wS = sb + buf * GBUF + G_W;

        #pragma unroll
        for (int kk = 0; kk < 4; kk++) {
            const int k0 = kk * 16;
            uint32_t af[2][4];
            #pragma unroll
            for (int mt = 0; mt < 2; mt++) {
                int row = warp_m + mt * 16 + (lane & 15);
                uint32_t off = row * 128 + ((k0 * 2 + (lane >> 4) * 16) ^ ((row & 7) * 16));
                LDSM_X4(af[mt][0], af[mt][1], af[mt][2], af[mt][3], aS + off);
            }
            uint32_t wf[8][2];
            #pragma unroll
            for (int p = 0; p < 4; p++) {
                int n = warp_n + p * 16 + (lane & 7) + ((lane >> 4) << 3);
                uint32_t off = n * 128 + ((k0 * 2 + ((lane >> 3) & 1) * 16) ^ ((n & 7) * 16));
                LDSM_X4(wf[p*2][0], wf[p*2][1], wf[p*2+1][0], wf[p*2+1][1], wS + off);
            }
            #pragma unroll
            for (int mt = 0; mt < 2; mt++)
                #pragma unroll
                for (int nt = 0; nt < 8; nt++)
                    MMA_F16(acc[mt*8 + nt], af[mt], wf[nt]);
        }
        __syncthreads();
    }

    #pragma unroll
    for (int mt = 0; mt < 2; mt++)
        #pragma unroll
        for (int nt = 0; nt < 8; nt++) {
            int m0 = bM + warp_m + mt * 16 + (lane >> 2);
            int n  = bN + warp_n + nt * 8 + (lane & 3) * 2;
            float* a4 = acc[mt*8+nt];
            if (mode == 0) {
                int h = n >> 6, dh = n & 63;
                int b0 = m0 >> 11, s0 = m0 & 2047;
                int m1 = m0 + 8, b1 = m1 >> 11, s1 = m1 & 2047;
                size_t i0 = ((size_t)(b0 * NH + h) * NS + s0) * NDH + dh;
                size_t i1 = ((size_t)(b1 * NH + h) * NS + s1) * NDH + dh;
                __half* O = (z == 0) ? g_Q16 : (z == 1) ? g_K16 : g_V16;
                *(uint32_t*)(O + i0) = h2pack(a4[0] * osc, a4[1] * osc);
                *(uint32_t*)(O + i1) = h2pack(a4[2] * osc, a4[3] * osc);
            } else {
                *(float2*)(Cout + (size_t)m0 * ND + n)       = make_float2(a4[0], a4[1]);
                *(float2*)(Cout + (size_t)(m0 + 8) * ND + n) = make_float2(a4[2], a4[3]);
            }
        }
}

// ---------------------------------------------------------------------------
// Flash attention on HMMA, all single-fp16 operands (Q,K,V,P).
// QK: 1-pass. PV: 1-pass. exp2-domain softmax.
// CTA = 128 q x 64 k, 8 warps, double-buffered K/V (32KB).
// ---------------------------------------------------------------------------
#define ATT_BUF  16384
#define ATT_SMEM (2 * ATT_BUF)

__global__ __launch_bounds__(256, 1) void attn_mma_kernel(const int* __restrict__ valid_lens)
{
    extern __shared__ char smc[];
    const uint32_t sb = smem_u32(smc);
    const int tid = threadIdx.x, wid = tid >> 5, lane = tid & 31;
    const int qb = blockIdx.x, bh = blockIdx.y;
    const int bb = bh >> 4, head = bh & 15;
    const int vlen = valid_lens[bb];
    const int nkb  = (vlen + 63) >> 6;

    const size_t hbase = (size_t)bh * NS * NDH;
    const __half *Q16 = g_Q16 + hbase;
    const __half *K16 = g_K16 + hbase, *V16 = g_V16 + hbase;

    const int r = lane >> 2, c2 = (lane & 3) * 2;

    uint32_t qf[4][4];
    {
        const int q0 = qb * 128 + wid * 16;
        #pragma unroll
        for (int t = 0; t < 4; t++) {
            int k0 = t * 16;
            qf[t][0] = *(const uint32_t*)(Q16 + (size_t)(q0 + r    ) * NDH + k0 + c2);
            qf[t][1] = *(const uint32_t*)(Q16 + (size_t)(q0 + r + 8) * NDH + k0 + c2);
            qf[t][2] = *(const uint32_t*)(Q16 + (size_t)(q0 + r    ) * NDH + k0 + c2 + 8);
            qf[t][3] = *(const uint32_t*)(Q16 + (size_t)(q0 + r + 8) * NDH + k0 + c2 + 8);
        }
    }

    float m_i[2] = {-1e30f, -1e30f}, l_i[2] = {0.f, 0.f};
    float o[8][4];
    #pragma unroll
    for (int i = 0; i < 8; i++)
        #pragma unroll
        for (int j = 0; j < 4; j++) o[i][j] = 0.f;

    auto cpKV = [&](int kb, int buf) {
        #pragma unroll
        for (int l = 0; l < 4; l++) {
            int f   = tid + l * 256;
            int arr = f >> 9;                 // 0:K 1:V
            int rr  = (f >> 3) & 63;
            int cc  = f & 7;
            const void* src = (arr ? V16 : K16) + (size_t)(kb * 64 + rr) * NDH + cc * 8;
            uint32_t dst = sb + buf * ATT_BUF + arr * 8192
                         + rr * 128 + ((cc * 16) ^ ((rr & 7) * 16));
            cpasync16(dst, src);
        }
        CP_COMMIT();
    };

    cpKV(0, 0);

    for (int kb = 0; kb < nkb; kb++) {
        const int buf = kb & 1;
        CP_WAIT0();
        __syncthreads();
        if (kb + 1 < nkb) cpKV(kb + 1, buf ^ 1);

        const uint32_t kS = sb + buf * ATT_BUF;
        const uint32_t vS = kS + 8192;

        // ---- S = Q K^T (1-pass fp16) ----
        float s[8][4];
        #pragma unroll
        for (int i = 0; i < 8; i++)
            #pragma unroll
            for (int j = 0; j < 4; j++) s[i][j] = 0.f;

        #pragma unroll
        for (int t = 0; t < 4; t++) {
            uint32_t kf[8][2];
            #pragma unroll
            for (int p = 0; p < 4; p++) {
                int n = p * 16 + (lane & 7) + ((lane >> 4) << 3);
                uint32_t off = n * 128 + ((t * 32 + ((lane >> 3) & 1) * 16) ^ ((n & 7) * 16));
                LDSM_X4(kf[p*2][0], kf[p*2][1], kf[p*2+1][0], kf[p*2+1][1], kS + off);
            }
            #pragma unroll
            for (int nt = 0; nt < 8; nt++)
                MMA_F16(s[nt], qf[t], kf[nt]);
        }

        if (kb == nkb - 1) {
            int cb = kb * 64 + c2;
            #pragma unroll
            for (int nt = 0; nt < 8; nt++) {
                int c0g = cb + nt * 8;
                if (c0g     >= vlen) { s[nt][0] = -1e30f; s[nt][2] = -1e30f; }
                if (c0g + 1 >= vlen) { s[nt][1] = -1e30f; s[nt][3] = -1e30f; }
            }
        }

        // ---- online softmax (base-2 domain) ----
        float mx0 = -1e30f, mx1 = -1e30f;
        #pragma unroll
        for (int nt = 0; nt < 8; nt++) {
            mx0 = fmaxf(mx0, fmaxf(s[nt][0], s[nt][1]));
            mx1 = fmaxf(mx1, fmaxf(s[nt][2], s[nt][3]));
        }
        mx0 = fmaxf(mx0, __shfl_xor_sync(0xffffffffu, mx0, 1));
        mx0 = fmaxf(mx0, __shfl_xor_sync(0xffffffffu, mx0, 2));
        mx1 = fmaxf(mx1, __shfl_xor_sync(0xffffffffu, mx1, 1));
        mx1 = fmaxf(mx1, __shfl_xor_sync(0xffffffffu, mx1, 2));

        float mn0 = fmaxf(m_i[0], mx0), mn1 = fmaxf(m_i[1], mx1);
        float a0 = ex2f(m_i[0] - mn0), a1 = ex2f(m_i[1] - mn1);
        m_i[0] = mn0; m_i[1] = mn1;

        float sum0 = 0.f, sum1 = 0.f;
        #pragma unroll
        for (int nt = 0; nt < 8; nt++) {
            s[nt][0] = ex2f(s[nt][0] - mn0); sum0 += s[nt][0];
            s[nt][1] = ex2f(s[nt][1] - mn0); sum0 += s[nt][1];
            s[nt][2] = ex2f(s[nt][2] - mn1); sum1 += s[nt][2];
            s[nt][3] = ex2f(s[nt][3] - mn1); sum1 += s[nt][3];
        }
        sum0 += __shfl_xor_sync(0xffffffffu, sum0, 1);
        sum0 += __shfl_xor_sync(0xffffffffu, sum0, 2);
        sum1 += __shfl_xor_sync(0xffffffffu, sum1, 1);
        sum1 += __shfl_xor_sync(0xffffffffu, sum1, 2);
        l_i[0] = l_i[0] * a0 + sum0;
        l_i[1] = l_i[1] * a1 + sum1;
        #pragma unroll
        for (int nt = 0; nt < 8; nt++) {
            o[nt][0] *= a0; o[nt][1] *= a0;
            o[nt][2] *= a1; o[nt][3] *= a1;
        }

        // ---- O += P V (1-pass) ----
        #pragma unroll
        for (int t = 0; t < 4; t++) {
            uint32_t ph[4];
            ph[0] = h2pack(s[2*t  ][0], s[2*t  ][1]);
            ph[1] = h2pack(s[2*t  ][2], s[2*t  ][3]);
            ph[2] = h2pack(s[2*t+1][0], s[2*t+1][1]);
            ph[3] = h2pack(s[2*t+1][2], s[2*t+1][3]);

            uint32_t vf[8][2];
            #pragma unroll
            for (int p = 0; p < 4; p++) {
                int rowb = t * 16 + (lane & 15);
                uint32_t off = rowb * 128 + ((p * 32 + (lane >> 4) * 16) ^ ((rowb & 7) * 16));
                LDSM_X4_T(vf[p*2][0], vf[p*2][1], vf[p*2+1][0], vf[p*2+1][1], vS + off);
            }
            #pragma unroll
            for (int nt = 0; nt < 8; nt++)
                MMA_F16(o[nt], ph, vf[nt]);
        }
    }

    // epilogue: single fp16 to g_AO16 [B*S][D]
    const float inv0 = 1.f / l_i[0], inv1 = 1.f / l_i[1];
    const int row0 = qb * 128 + wid * 16 + r;
    const size_t base0 = (size_t)(bb * NS + row0    ) * ND + head * 64;
    const size_t base1 = (size_t)(bb * NS + row0 + 8) * ND + head * 64;
    #pragma unroll
    for (int nt = 0; nt < 8; nt++) {
        *(uint32_t*)(g_AO16 + base0 + nt * 8 + c2) = h2pack(o[nt][0] * inv0, o[nt][1] * inv0);
        *(uint32_t*)(g_AO16 + base1 + nt * 8 + c2) = h2pack(o[nt][2] * inv1, o[nt][3] * inv1);
    }
}

// ---------------------------------------------------------------------------
extern "C" void kernel_launch(void* const* d_in, const int* in_sizes, int n_in,
                              void* d_out, int out_size)
{
    const float* q  = (const float*)d_in[0];
    const float* k  = (const float*)d_in[1];
    const float* v  = (const float*)d_in[2];
    const int*   vl = (const int*)  d_in[3];
    const float* Wq = (const float*)d_in[4];
    const float* Wk = (const float*)d_in[5];
    const float* Wv = (const float*)d_in[6];
    const float* Wo = (const float*)d_in[7];
    float* out = (float*)d_out;

    cudaFuncSetAttribute(gemm_mma_kernel, cudaFuncAttributeMaxDynamicSharedMemorySize,
                         GEMM_SMEM);
    cudaFuncSetAttribute(attn_mma_kernel, cudaFuncAttributeMaxDynamicSharedMemorySize,
                         ATT_SMEM);

    // prep: z<3 X convert (grid.x=4096 chunks), z>=3 W transpose+cvt (first 1024)
    prep_kernel<<<dim3(4096, 1, 7), 256>>>(q, k, v, Wq, Wk, Wv, Wo);

    gemm_mma_kernel<<<dim3(ND / 128, (NB * NS) / 128, 3), 256, GEMM_SMEM>>>(out, 0);

    attn_mma_kernel<<<dim3(NS / 128, NB * NH), 256, ATT_SMEM>>>(vl);

    gemm_mma_kernel<<<dim3(ND / 128, (NB * NS) / 128, 1), 256, GEMM_SMEM>>>(out, 1);
}

// round 15
// speedup vs baseline: 2.4470x; 1.0564x over previous
#include <cuda_runtime.h>
#include <cuda_bf16.h>
#include <cuda_fp16.h>
#include <stdint.h>

#define NB  2
#define NS  2048
#define ND  1024
#define NH  16
#define NDH 64

// Scratch (allocation-free rule: __device__ globals).
__device__ __half g_W16 [4u << 20];                    // 4 x W^T single fp16: [n][k]
__device__ __half g_X16 [3u << 22];                    // single-fp16 Xq/Xk/Xv [4096][1024]
__device__ __half g_AO16[1u << 22];                    // single-fp16 attn out [4096][1024]
// head-major [B,H,S,DH]: Q/K/V all single fp16 (Q pre-scaled by 0.125*log2e)
__device__ __half g_Q16[NB*NH*NS*NDH];
__device__ __half g_K16[NB*NH*NS*NDH];
__device__ __half g_V16[NB*NH*NS*NDH];

// ---------------------------------------------------------------------------
// helpers
// ---------------------------------------------------------------------------
__device__ __forceinline__ uint32_t smem_u32(const void* p) {
    uint32_t a;
    asm("{ .reg .u64 t; cvta.to.shared.u64 t, %1; cvt.u32.u64 %0, t; }" : "=r"(a) : "l"(p));
    return a;
}
__device__ __forceinline__ void cpasync16(uint32_t dst, const void* src) {
    asm volatile("cp.async.cg.shared.global [%0], [%1], 16;" :: "r"(dst), "l"(src));
}
#define CP_COMMIT() asm volatile("cp.async.commit_group;" ::: "memory")
#define CP_WAIT0()  asm volatile("cp.async.wait_group 0;" ::: "memory")
#define CP_WAIT1()  asm volatile("cp.async.wait_group 1;" ::: "memory")

#define LDSM_X4(r0, r1, r2, r3, addr)                                          \
    asm volatile("ldmatrix.sync.aligned.m8n8.x4.shared.b16 {%0,%1,%2,%3}, [%4];" \
        : "=r"(r0), "=r"(r1), "=r"(r2), "=r"(r3) : "r"(addr))
#define LDSM_X4_T(r0, r1, r2, r3, addr)                                        \
    asm volatile("ldmatrix.sync.aligned.m8n8.x4.trans.shared.b16 {%0,%1,%2,%3}, [%4];" \
        : "=r"(r0), "=r"(r1), "=r"(r2), "=r"(r3) : "r"(addr))

#define MMA_F16(d, a, b)                                                       \
    asm volatile("mma.sync.aligned.m16n8k16.row.col.f32.f16.f16.f32 "          \
        "{%0,%1,%2,%3},{%4,%5,%6,%7},{%8,%9},{%0,%1,%2,%3};"                   \
        : "+f"((d)[0]), "+f"((d)[1]), "+f"((d)[2]), "+f"((d)[3])               \
        : "r"((a)[0]), "r"((a)[1]), "r"((a)[2]), "r"((a)[3]),                  \
          "r"((b)[0]), "r"((b)[1]))

__device__ __forceinline__ float ex2f(float x) {
    float y; asm("ex2.approx.f32 %0, %1;" : "=f"(y) : "f"(x)); return y;
}
__device__ __forceinline__ uint32_t ex2h2(uint32_t x) {
    uint32_t y; asm("ex2.approx.f16x2 %0, %1;" : "=r"(y) : "r"(x)); return y;
}
__device__ __forceinline__ uint32_t h2pack(float a, float b) {
    __half2 h = __floats2half2_rn(a, b);
    return *(uint32_t*)&h;
}

// ---------------------------------------------------------------------------
// Prep: z 0..2 -> X fp32->fp16 convert (grid.x = 4096);
//       z 3..6 -> W transpose + fp16 convert (only grid.x < 1024 valid).
// ---------------------------------------------------------------------------
__global__ __launch_bounds__(256) void prep_kernel(
    const float* __restrict__ X0, const float* __restrict__ X1,
    const float* __restrict__ X2,
    const float* __restrict__ W0, const float* __restrict__ W1,
    const float* __restrict__ W2, const float* __restrict__ W3)
{
    const int z = blockIdx.z;
    if (z < 3) {
        const float* X = (z == 0) ? X0 : (z == 1) ? X1 : X2;
        __half* O = g_X16 + ((size_t)z << 22);
        size_t idx = (size_t)blockIdx.x * 256 + threadIdx.x;
        float4 v = *((const float4*)X + idx);
        uint2 o;
        o.x = h2pack(v.x, v.y);
        o.y = h2pack(v.z, v.w);
        *((uint2*)O + idx) = o;
    } else {
        if (blockIdx.x >= 1024) return;   // only 32x32 = 1024 W tiles
        __shared__ float t[32][33];
        int wz = z - 3;
        const float* W = (wz == 0) ? W0 : (wz == 1) ? W1 : (wz == 2) ? W2 : W3;
        __half* O = g_W16 + ((size_t)wz << 20);
        int tx = threadIdx.x & 31, ty = threadIdx.x >> 5;
        int n0 = (blockIdx.x & 31) * 32, k0 = (blockIdx.x >> 5) * 32;
        #pragma unroll
        for (int i = 0; i < 4; i++)
            t[ty + i*8][tx] = W[(size_t)(k0 + ty + i*8) * ND + n0 + tx];
        __syncthreads();
        #pragma unroll
        for (int i = 0; i < 4; i++) {
            float v = t[tx][ty + i*8];
            O[(size_t)(n0 + ty + i*8) * ND + k0 + tx] = __float2half_rn(v);
        }
    }
}

// ---------------------------------------------------------------------------
// HMMA single-pass fp16 GEMM: D = A * W. Both single fp16.
// CTA 128M x 128N, BK=64, 256 threads (8 warps, 32m x 64n each),
// double-buffered 2 x 32KB = 64KB -> 2 CTAs/SM.
// ---------------------------------------------------------------------------
#define GBUF   32768
#define G_A    0
#define G_W    16384
#define GEMM_SMEM (2 * GBUF)   // 64 KB

__global__ __launch_bounds__(256, 2) void gemm_mma_kernel(float* __restrict__ Cout, int mode)
{
    extern __shared__ char smc[];
    const uint32_t sb = smem_u32(smc);
    const int tid  = threadIdx.x;
    const int wid  = tid >> 5, lane = tid & 31;
    const int z    = blockIdx.z;

    const __half *A_g, *Wg;
    float osc = 1.f;
    if (mode == 0) {
        A_g = g_X16 + ((size_t)z << 22);
        Wg  = g_W16 + ((size_t)z << 20);
        if (z == 0) osc = 0.125f * 1.44269504f;
    } else {
        A_g = g_AO16;
        Wg  = g_W16 + ((size_t)3 << 20);
    }
    const int bM = blockIdx.y * 128, bN = blockIdx.x * 128;
    const int warp_m = (wid & 3) * 32, warp_n = (wid >> 2) * 64;

    float acc[16][4];
    #pragma unroll
    for (int i = 0; i < 16; i++)
        #pragma unroll
        for (int j = 0; j < 4; j++) acc[i][j] = 0.f;

    auto cpStage = [&](int s, int buf) {
        uint32_t base = sb + buf * GBUF;
        #pragma unroll
        for (int l = 0; l < 8; l++) {
            int f = tid + l * 256;
            const __half* src;
            uint32_t dst;
            if (f < 1024) {
                int r = f >> 3, c = f & 7;
                src = A_g + (size_t)(bM + r) * ND + s * 64 + c * 8;
                dst = base + G_A + r * 128 + ((c * 16) ^ ((r & 7) * 16));
            } else {
                int g = f - 1024;
                int r = g >> 3, c = g & 7;
                src = Wg + (size_t)(bN + r) * ND + s * 64 + c * 8;
                dst = base + G_W + r * 128 + ((c * 16) ^ ((r & 7) * 16));
            }
            cpasync16(dst, src);
        }
        CP_COMMIT();
    };

    cpStage(0, 0);

    for (int s = 0; s < 16; s++) {
        const int buf = s & 1;
        if (s + 1 < 16) { cpStage(s + 1, buf ^ 1); CP_WAIT1(); }
        else            { CP_WAIT0(); }
        __syncthreads();

        const uint32_t aS = sb + buf * GBUF + G_A;
        const uint32_t wS = sb + buf * GBUF + G_W;

        #pragma unroll
        for (int kk = 0; kk < 4; kk++) {
            const int k0 = kk * 16;
            uint32_t af[2][4];
            #pragma unroll
            for (int mt = 0; mt < 2; mt++) {
                int row = warp_m + mt * 16 + (lane & 15);
                uint32_t off = row * 128 + ((k0 * 2 + (lane >> 4) * 16) ^ ((row & 7) * 16));
                LDSM_X4(af[mt][0], af[mt][1], af[mt][2], af[mt][3], aS + off);
            }
            uint32_t wf[8][2];
            #pragma unroll
            for (int p = 0; p < 4; p++) {
                int n = warp_n + p * 16 + (lane & 7) + ((lane >> 4) << 3);
                uint32_t off = n * 128 + ((k0 * 2 + ((lane >> 3) & 1) * 16) ^ ((n & 7) * 16));
                LDSM_X4(wf[p*2][0], wf[p*2][1], wf[p*2+1][0], wf[p*2+1][1], wS + off);
            }
            #pragma unroll
            for (int mt = 0; mt < 2; mt++)
                #pragma unroll
                for (int nt = 0; nt < 8; nt++)
                    MMA_F16(acc[mt*8 + nt], af[mt], wf[nt]);
        }
        __syncthreads();
    }

    #pragma unroll
    for (int mt = 0; mt < 2; mt++)
        #pragma unroll
        for (int nt = 0; nt < 8; nt++) {
            int m0 = bM + warp_m + mt * 16 + (lane >> 2);
            int n  = bN + warp_n + nt * 8 + (lane & 3) * 2;
            float* a4 = acc[mt*8+nt];
            if (mode == 0) {
                int h = n >> 6, dh = n & 63;
                int b0 = m0 >> 11, s0 = m0 & 2047;
                int m1 = m0 + 8, b1 = m1 >> 11, s1 = m1 & 2047;
                size_t i0 = ((size_t)(b0 * NH + h) * NS + s0) * NDH + dh;
                size_t i1 = ((size_t)(b1 * NH + h) * NS + s1) * NDH + dh;
                __half* O = (z == 0) ? g_Q16 : (z == 1) ? g_K16 : g_V16;
                *(uint32_t*)(O + i0) = h2pack(a4[0] * osc, a4[1] * osc);
                *(uint32_t*)(O + i1) = h2pack(a4[2] * osc, a4[3] * osc);
            } else {
                *(float2*)(Cout + (size_t)m0 * ND + n)       = make_float2(a4[0], a4[1]);
                *(float2*)(Cout + (size_t)(m0 + 8) * ND + n) = make_float2(a4[2], a4[3]);
            }
        }
}

// ---------------------------------------------------------------------------
// Flash attention on HMMA, all single-fp16.
// QK 1-pass; softmax: fp32 max + f16x2 exp2; row-sums via ones-MMA (no shfl);
// PV 1-pass. 2 CTAs/SM.
// ---------------------------------------------------------------------------
#define ATT_BUF  16384
#define ATT_SMEM (2 * ATT_BUF)

__global__ __launch_bounds__(256, 2) void attn_mma_kernel(const int* __restrict__ valid_lens)
{
    extern __shared__ char smc[];
    const uint32_t sb = smem_u32(smc);
    const int tid = threadIdx.x, wid = tid >> 5, lane = tid & 31;
    const int qb = blockIdx.x, bh = blockIdx.y;
    const int bb = bh >> 4, head = bh & 15;
    const int vlen = valid_lens[bb];
    const int nkb  = (vlen + 63) >> 6;

    const size_t hbase = (size_t)bh * NS * NDH;
    const __half *Q16 = g_Q16 + hbase;
    const __half *K16 = g_K16 + hbase, *V16 = g_V16 + hbase;

    const int r = lane >> 2, c2 = (lane & 3) * 2;

    uint32_t qf[4][4];
    {
        const int q0 = qb * 128 + wid * 16;
        #pragma unroll
        for (int t = 0; t < 4; t++) {
            int k0 = t * 16;
            qf[t][0] = *(const uint32_t*)(Q16 + (size_t)(q0 + r    ) * NDH + k0 + c2);
            qf[t][1] = *(const uint32_t*)(Q16 + (size_t)(q0 + r + 8) * NDH + k0 + c2);
            qf[t][2] = *(const uint32_t*)(Q16 + (size_t)(q0 + r    ) * NDH + k0 + c2 + 8);
            qf[t][3] = *(const uint32_t*)(Q16 + (size_t)(q0 + r + 8) * NDH + k0 + c2 + 8);
        }
    }

    float m_i[2] = {-1e30f, -1e30f}, l_i[2] = {0.f, 0.f};
    float o[8][4];
    #pragma unroll
    for (int i = 0; i < 8; i++)
        #pragma unroll
        for (int j = 0; j < 4; j++) o[i][j] = 0.f;

    const uint32_t ONES[2] = {0x3C003C00u, 0x3C003C00u};   // fp16 1.0 x4

    auto cpKV = [&](int kb, int buf) {
        #pragma unroll
        for (int l = 0; l < 4; l++) {
            int f   = tid + l * 256;
            int arr = f >> 9;
            int rr  = (f >> 3) & 63;
            int cc  = f & 7;
            const void* src = (arr ? V16 : K16) + (size_t)(kb * 64 + rr) * NDH + cc * 8;
            uint32_t dst = sb + buf * ATT_BUF + arr * 8192
                         + rr * 128 + ((cc * 16) ^ ((rr & 7) * 16));
            cpasync16(dst, src);
        }
        CP_COMMIT();
    };

    cpKV(0, 0);

    for (int kb = 0; kb < nkb; kb++) {
        const int buf = kb & 1;
        CP_WAIT0();
        __syncthreads();
        if (kb + 1 < nkb) cpKV(kb + 1, buf ^ 1);

        const uint32_t kS = sb + buf * ATT_BUF;
        const uint32_t vS = kS + 8192;

        // ---- S = Q K^T (1-pass fp16) ----
        float s[8][4];
        #pragma unroll
        for (int i = 0; i < 8; i++)
            #pragma unroll
            for (int j = 0; j < 4; j++) s[i][j] = 0.f;

        #pragma unroll
        for (int t = 0; t < 4; t++) {
            uint32_t kf[8][2];
            #pragma unroll
            for (int p = 0; p < 4; p++) {
                int n = p * 16 + (lane & 7) + ((lane >> 4) << 3);
                uint32_t off = n * 128 + ((t * 32 + ((lane >> 3) & 1) * 16) ^ ((n & 7) * 16));
                LDSM_X4(kf[p*2][0], kf[p*2][1], kf[p*2+1][0], kf[p*2+1][1], kS + off);
            }
            #pragma unroll
            for (int nt = 0; nt < 8; nt++)
                MMA_F16(s[nt], qf[t], kf[nt]);
        }

        if (kb == nkb - 1) {
            int cb = kb * 64 + c2;
            #pragma unroll
            for (int nt = 0; nt < 8; nt++) {
                int c0g = cb + nt * 8;
                if (c0g     >= vlen) { s[nt][0] = -1e30f; s[nt][2] = -1e30f; }
                if (c0g + 1 >= vlen) { s[nt][1] = -1e30f; s[nt][3] = -1e30f; }
            }
        }

        // ---- max (fp32, quad shfl) ----
        float mx0 = -1e30f, mx1 = -1e30f;
        #pragma unroll
        for (int nt = 0; nt < 8; nt++) {
            mx0 = fmaxf(mx0, fmaxf(s[nt][0], s[nt][1]));
            mx1 = fmaxf(mx1, fmaxf(s[nt][2], s[nt][3]));
        }
        mx0 = fmaxf(mx0, __shfl_xor_sync(0xffffffffu, mx0, 1));
        mx0 = fmaxf(mx0, __shfl_xor_sync(0xffffffffu, mx0, 2));
        mx1 = fmaxf(mx1, __shfl_xor_sync(0xffffffffu, mx1, 1));
        mx1 = fmaxf(mx1, __shfl_xor_sync(0xffffffffu, mx1, 2));

        float mn0 = fmaxf(m_i[0], mx0), mn1 = fmaxf(m_i[1], mx1);
        float a0 = ex2f(m_i[0] - mn0), a1 = ex2f(m_i[1] - mn1);
        m_i[0] = mn0; m_i[1] = mn1;

        // ---- P = exp2(S - m) in f16x2, directly in MMA layout ----
        uint32_t ps[4][4];
        #pragma unroll
        for (int t = 0; t < 4; t++) {
            ps[t][0] = ex2h2(h2pack(s[2*t  ][0] - mn0, s[2*t  ][1] - mn0));
            ps[t][1] = ex2h2(h2pack(s[2*t  ][2] - mn1, s[2*t  ][3] - mn1));
            ps[t][2] = ex2h2(h2pack(s[2*t+1][0] - mn0, s[2*t+1][1] - mn0));
            ps[t][3] = ex2h2(h2pack(s[2*t+1][2] - mn1, s[2*t+1][3] - mn1));
        }

        // ---- row sums via ones-MMA (fp32 accumulate, no shfl) ----
        float sacc[4] = {0.f, 0.f, 0.f, 0.f};
        #pragma unroll
        for (int t = 0; t < 4; t++)
            MMA_F16(sacc, ps[t], ONES);
        l_i[0] = l_i[0] * a0 + sacc[0];
        l_i[1] = l_i[1] * a1 + sacc[2];

        #pragma unroll
        for (int nt = 0; nt < 8; nt++) {
            o[nt][0] *= a0; o[nt][1] *= a0;
            o[nt][2] *= a1; o[nt][3] *= a1;
        }

        // ---- O += P V (1-pass) ----
        #pragma unroll
        for (int t = 0; t < 4; t++) {
            uint32_t vf[8][2];
            #pragma unroll
            for (int p = 0; p < 4; p++) {
                int rowb = t * 16 + (lane & 15);
                uint32_t off = rowb * 128 + ((p * 32 + (lane >> 4) * 16) ^ ((rowb & 7) * 16));
                LDSM_X4_T(vf[p*2][0], vf[p*2][1], vf[p*2+1][0], vf[p*2+1][1], vS + off);
            }
            #pragma unroll
            for (int nt = 0; nt < 8; nt++)
                MMA_F16(o[nt], ps[t], vf[nt]);
        }
    }

    // epilogue: single fp16 to g_AO16 [B*S][D]
    const float inv0 = 1.f / l_i[0], inv1 = 1.f / l_i[1];
    const int row0 = qb * 128 + wid * 16 + r;
    const size_t base0 = (size_t)(bb * NS + row0    ) * ND + head * 64;
    const size_t base1 = (size_t)(bb * NS + row0 + 8) * ND + head * 64;
    #pragma unroll
    for (int nt = 0; nt < 8; nt++) {
        *(uint32_t*)(g_AO16 + base0 + nt * 8 + c2) = h2pack(o[nt][0] * inv0, o[nt][1] * inv0);
        *(uint32_t*)(g_AO16 + base1 + nt * 8 + c2) = h2pack(o[nt][2] * inv1, o[nt][3] * inv1);
    }
}

// ---------------------------------------------------------------------------
extern "C" void kernel_launch(void* const* d_in, const int* in_sizes, int n_in,
                              void* d_out, int out_size)
{
    const float* q  = (const float*)d_in[0];
    const float* k  = (const float*)d_in[1];
    const float* v  = (const float*)d_in[2];
    const int*   vl = (const int*)  d_in[3];
    const float* Wq = (const float*)d_in[4];
    const float* Wk = (const float*)d_in[5];
    const float* Wv = (const float*)d_in[6];
    const float* Wo = (const float*)d_in[7];
    float* out = (float*)d_out;

    cudaFuncSetAttribute(gemm_mma_kernel, cudaFuncAttributeMaxDynamicSharedMemorySize,
                         GEMM_SMEM);
    cudaFuncSetAttribute(attn_mma_kernel, cudaFuncAttributeMaxDynamicSharedMemorySize,
                         ATT_SMEM);

    prep_kernel<<<dim3(4096, 1, 7), 256>>>(q, k, v, Wq, Wk, Wv, Wo);

    gemm_mma_kernel<<<dim3(ND / 128, (NB * NS) / 128, 3), 256, GEMM_SMEM>>>(out, 0);

    attn_mma_kernel<<<dim3(NS / 128, NB * NH), 256, ATT_SMEM>>>(vl);

    gemm_mma_kernel<<<dim3(ND / 128, (NB * NS) / 128, 1), 256, GEMM_SMEM>>>(out, 1);
}

// round 16
// speedup vs baseline: 2.5084x; 1.0251x over previous
#include <cuda_runtime.h>
#include <cuda_bf16.h>
#include <cuda_fp16.h>
#include <stdint.h>

#define NB  2
#define NS  2048
#define ND  1024
#define NH  16
#define NDH 64

// Scratch (allocation-free rule: __device__ globals).
__device__ __half g_W16 [4u << 20];                    // 4 x W^T single fp16: [n][k]
__device__ __half g_X16 [3u << 22];                    // single-fp16 Xq/Xk/Xv [4096][1024]
__device__ __half g_AO16[1u << 22];                    // single-fp16 attn out [4096][1024]
// head-major [B,H,S,DH]: Q/K/V all single fp16 (Q pre-scaled by 0.125*log2e)
__device__ __half g_Q16[NB*NH*NS*NDH];
__device__ __half g_K16[NB*NH*NS*NDH];
__device__ __half g_V16[NB*NH*NS*NDH];

// ---------------------------------------------------------------------------
// helpers
// ---------------------------------------------------------------------------
__device__ __forceinline__ uint32_t smem_u32(const void* p) {
    uint32_t a;
    asm("{ .reg .u64 t; cvta.to.shared.u64 t, %1; cvt.u32.u64 %0, t; }" : "=r"(a) : "l"(p));
    return a;
}
__device__ __forceinline__ void cpasync16(uint32_t dst, const void* src) {
    asm volatile("cp.async.cg.shared.global [%0], [%1], 16;" :: "r"(dst), "l"(src));
}
#define CP_COMMIT() asm volatile("cp.async.commit_group;" ::: "memory")
#define CP_WAIT0()  asm volatile("cp.async.wait_group 0;" ::: "memory")
#define CP_WAIT1()  asm volatile("cp.async.wait_group 1;" ::: "memory")

#define LDSM_X4(r0, r1, r2, r3, addr)                                          \
    asm volatile("ldmatrix.sync.aligned.m8n8.x4.shared.b16 {%0,%1,%2,%3}, [%4];" \
        : "=r"(r0), "=r"(r1), "=r"(r2), "=r"(r3) : "r"(addr))
#define LDSM_X4_T(r0, r1, r2, r3, addr)                                        \
    asm volatile("ldmatrix.sync.aligned.m8n8.x4.trans.shared.b16 {%0,%1,%2,%3}, [%4];" \
        : "=r"(r0), "=r"(r1), "=r"(r2), "=r"(r3) : "r"(addr))

#define MMA_F16(d, a, b)                                                       \
    asm volatile("mma.sync.aligned.m16n8k16.row.col.f32.f16.f16.f32 "          \
        "{%0,%1,%2,%3},{%4,%5,%6,%7},{%8,%9},{%0,%1,%2,%3};"                   \
        : "+f"((d)[0]), "+f"((d)[1]), "+f"((d)[2]), "+f"((d)[3])               \
        : "r"((a)[0]), "r"((a)[1]), "r"((a)[2]), "r"((a)[3]),                  \
          "r"((b)[0]), "r"((b)[1]))

__device__ __forceinline__ float ex2f(float x) {
    float y; asm("ex2.approx.f32 %0, %1;" : "=f"(y) : "f"(x)); return y;
}
__device__ __forceinline__ uint32_t ex2h2(uint32_t x) {
    uint32_t y; asm("ex2.approx.f16x2 %0, %1;" : "=r"(y) : "r"(x)); return y;
}
__device__ __forceinline__ uint32_t h2pack(float a, float b) {
    __half2 h = __floats2half2_rn(a, b);
    return *(uint32_t*)&h;
}

// ---------------------------------------------------------------------------
// Prep: z 0..2 -> X fp32->fp16 convert (grid.x = 4096);
//       z 3..6 -> W transpose + fp16 convert (only grid.x < 1024 valid).
// ---------------------------------------------------------------------------
__global__ __launch_bounds__(256) void prep_kernel(
    const float* __restrict__ X0, const float* __restrict__ X1,
    const float* __restrict__ X2,
    const float* __restrict__ W0, const float* __restrict__ W1,
    const float* __restrict__ W2, const float* __restrict__ W3)
{
    const int z = blockIdx.z;
    if (z < 3) {
        const float* X = (z == 0) ? X0 : (z == 1) ? X1 : X2;
        __half* O = g_X16 + ((size_t)z << 22);
        size_t idx = (size_t)blockIdx.x * 256 + threadIdx.x;
        float4 v = *((const float4*)X + idx);
        uint2 o;
        o.x = h2pack(v.x, v.y);
        o.y = h2pack(v.z, v.w);
        *((uint2*)O + idx) = o;
    } else {
        if (blockIdx.x >= 1024) return;   // only 32x32 = 1024 W tiles
        __shared__ float t[32][33];
        int wz = z - 3;
        const float* W = (wz == 0) ? W0 : (wz == 1) ? W1 : (wz == 2) ? W2 : W3;
        __half* O = g_W16 + ((size_t)wz << 20);
        int tx = threadIdx.x & 31, ty = threadIdx.x >> 5;
        int n0 = (blockIdx.x & 31) * 32, k0 = (blockIdx.x >> 5) * 32;
        #pragma unroll
        for (int i = 0; i < 4; i++)
            t[ty + i*8][tx] = W[(size_t)(k0 + ty + i*8) * ND + n0 + tx];
        __syncthreads();
        #pragma unroll
        for (int i = 0; i < 4; i++) {
            float v = t[tx][ty + i*8];
            O[(size_t)(n0 + ty + i*8) * ND + k0 + tx] = __float2half_rn(v);
        }
    }
}

// ---------------------------------------------------------------------------
// HMMA single-pass fp16 GEMM: D = A * W. Both single fp16.
// CTA 128M x 128N, BK=64, 128 threads = 4 warps, warp tile 64m x 64n
// (A and W each duplicated only 2x in smem reads). Double-buffered 64KB,
// 2 CTAs/SM (reg cap 250).
// mode 0: z=0 -> Q (single fp16, scaled 0.125*log2e), z=1 -> K, z=2 -> V.
// mode 1: A = g_AO16, fp32 out.
// ---------------------------------------------------------------------------
#define GBUF   32768
#define G_A    0
#define G_W    16384
#define GEMM_SMEM (2 * GBUF)   // 64 KB

__global__ __launch_bounds__(128, 2) void gemm_mma_kernel(float* __restrict__ Cout, int mode)
{
    extern __shared__ char smc[];
    const uint32_t sb = smem_u32(smc);
    const int tid  = threadIdx.x;
    const int wid  = tid >> 5, lane = tid & 31;
    const int z    = blockIdx.z;

    const __half *A_g, *Wg;
    float osc = 1.f;
    if (mode == 0) {
        A_g = g_X16 + ((size_t)z << 22);
        Wg  = g_W16 + ((size_t)z << 20);
        if (z == 0) osc = 0.125f * 1.44269504f;
    } else {
        A_g = g_AO16;
        Wg  = g_W16 + ((size_t)3 << 20);
    }
    const int bM = blockIdx.y * 128, bN = blockIdx.x * 128;
    const int warp_m = (wid & 1) * 64, warp_n = (wid >> 1) * 64;

    float acc[32][4];            // [mt*8 + nt], mt 0..3 (16-row), nt 0..7 (8-col)
    #pragma unroll
    for (int i = 0; i < 32; i++)
        #pragma unroll
        for (int j = 0; j < 4; j++) acc[i][j] = 0.f;

    // Stage = 32KB: A 128x64 fp16 (16KB) | W 128x64 fp16 (16KB).
    // 2048 cp.async of 16B; 16 per thread (128 threads).
    auto cpStage = [&](int s, int buf) {
        uint32_t base = sb + buf * GBUF;
        #pragma unroll
        for (int l = 0; l < 16; l++) {
            int f = tid + l * 128;
            const __half* src;
            uint32_t dst;
            if (f < 1024) {                     // A: 128 rows x 8 chunks
                int r = f >> 3, c = f & 7;
                src = A_g + (size_t)(bM + r) * ND + s * 64 + c * 8;
                dst = base + G_A + r * 128 + ((c * 16) ^ ((r & 7) * 16));
            } else {                            // W: 128 rows x 8 chunks
                int g = f - 1024;
                int r = g >> 3, c = g & 7;
                src = Wg + (size_t)(bN + r) * ND + s * 64 + c * 8;
                dst = base + G_W + r * 128 + ((c * 16) ^ ((r & 7) * 16));
            }
            cpasync16(dst, src);
        }
        CP_COMMIT();
    };

    cpStage(0, 0);

    for (int s = 0; s < 16; s++) {
        const int buf = s & 1;
        if (s + 1 < 16) { cpStage(s + 1, buf ^ 1); CP_WAIT1(); }
        else            { CP_WAIT0(); }
        __syncthreads();

        const uint32_t aS = sb + buf * GBUF + G_A;
        const uint32_t wS = sb + buf * GBUF + G_W;

        #pragma unroll
        for (int kk = 0; kk < 4; kk++) {
            const int k0 = kk * 16;
            uint32_t af[4][4];
            #pragma unroll
            for (int mt = 0; mt < 4; mt++) {
                int row = warp_m + mt * 16 + (lane & 15);
                uint32_t off = row * 128 + ((k0 * 2 + (lane >> 4) * 16) ^ ((row & 7) * 16));
                LDSM_X4(af[mt][0], af[mt][1], af[mt][2], af[mt][3], aS + off);
            }
            uint32_t wf[8][2];
            #pragma unroll
            for (int p = 0; p < 4; p++) {
                int n = warp_n + p * 16 + (lane & 7) + ((lane >> 4) << 3);
                uint32_t off = n * 128 + ((k0 * 2 + ((lane >> 3) & 1) * 16) ^ ((n & 7) * 16));
                LDSM_X4(wf[p*2][0], wf[p*2][1], wf[p*2+1][0], wf[p*2+1][1], wS + off);
            }
            #pragma unroll
            for (int mt = 0; mt < 4; mt++)
                #pragma unroll
                for (int nt = 0; nt < 8; nt++)
                    MMA_F16(acc[mt*8 + nt], af[mt], wf[nt]);
        }
        __syncthreads();
    }

    #pragma unroll
    for (int mt = 0; mt < 4; mt++)
        #pragma unroll
        for (int nt = 0; nt < 8; nt++) {
            int m0 = bM + warp_m + mt * 16 + (lane >> 2);
            int n  = bN + warp_n + nt * 8 + (lane & 3) * 2;
            float* a4 = acc[mt*8+nt];
            if (mode == 0) {
                int h = n >> 6, dh = n & 63;
                int b0 = m0 >> 11, s0 = m0 & 2047;
                int m1 = m0 + 8, b1 = m1 >> 11, s1 = m1 & 2047;
                size_t i0 = ((size_t)(b0 * NH + h) * NS + s0) * NDH + dh;
                size_t i1 = ((size_t)(b1 * NH + h) * NS + s1) * NDH + dh;
                __half* O = (z == 0) ? g_Q16 : (z == 1) ? g_K16 : g_V16;
                *(uint32_t*)(O + i0) = h2pack(a4[0] * osc, a4[1] * osc);
                *(uint32_t*)(O + i1) = h2pack(a4[2] * osc, a4[3] * osc);
            } else {
                *(float2*)(Cout + (size_t)m0 * ND + n)       = make_float2(a4[0], a4[1]);
                *(float2*)(Cout + (size_t)(m0 + 8) * ND + n) = make_float2(a4[2], a4[3]);
            }
        }
}

// ---------------------------------------------------------------------------
// Flash attention on HMMA, all single-fp16.
// QK 1-pass; softmax: fp32 max + f16x2 exp2; row-sums via ones-MMA (no shfl);
// PV 1-pass. 2 CTAs/SM.
// ---------------------------------------------------------------------------
#define ATT_BUF  16384
#define ATT_SMEM (2 * ATT_BUF)

__global__ __launch_bounds__(256, 2) void attn_mma_kernel(const int* __restrict__ valid_lens)
{
    extern __shared__ char smc[];
    const uint32_t sb = smem_u32(smc);
    const int tid = threadIdx.x, wid = tid >> 5, lane = tid & 31;
    const int qb = blockIdx.x, bh = blockIdx.y;
    const int bb = bh >> 4, head = bh & 15;
    const int vlen = valid_lens[bb];
    const int nkb  = (vlen + 63) >> 6;

    const size_t hbase = (size_t)bh * NS * NDH;
    const __half *Q16 = g_Q16 + hbase;
    const __half *K16 = g_K16 + hbase, *V16 = g_V16 + hbase;

    const int r = lane >> 2, c2 = (lane & 3) * 2;

    uint32_t qf[4][4];
    {
        const int q0 = qb * 128 + wid * 16;
        #pragma unroll
        for (int t = 0; t < 4; t++) {
            int k0 = t * 16;
            qf[t][0] = *(const uint32_t*)(Q16 + (size_t)(q0 + r    ) * NDH + k0 + c2);
            qf[t][1] = *(const uint32_t*)(Q16 + (size_t)(q0 + r + 8) * NDH + k0 + c2);
            qf[t][2] = *(const uint32_t*)(Q16 + (size_t)(q0 + r    ) * NDH + k0 + c2 + 8);
            qf[t][3] = *(const uint32_t*)(Q16 + (size_t)(q0 + r + 8) * NDH + k0 + c2 + 8);
        }
    }

    float m_i[2] = {-1e30f, -1e30f}, l_i[2] = {0.f, 0.f};
    float o[8][4];
    #pragma unroll
    for (int i = 0; i < 8; i++)
        #pragma unroll
        for (int j = 0; j < 4; j++) o[i][j] = 0.f;

    const uint32_t ONES[2] = {0x3C003C00u, 0x3C003C00u};   // fp16 1.0 x4

    auto cpKV = [&](int kb, int buf) {
        #pragma unroll
        for (int l = 0; l < 4; l++) {
            int f   = tid + l * 256;
            int arr = f >> 9;
            int rr  = (f >> 3) & 63;
            int cc  = f & 7;
            const void* src = (arr ? V16 : K16) + (size_t)(kb * 64 + rr) * NDH + cc * 8;
            uint32_t dst = sb + buf * ATT_BUF + arr * 8192
                         + rr * 128 + ((cc * 16) ^ ((rr & 7) * 16));
            cpasync16(dst, src);
        }
        CP_COMMIT();
    };

    cpKV(0, 0);

    for (int kb = 0; kb < nkb; kb++) {
        const int buf = kb & 1;
        CP_WAIT0();
        __syncthreads();
        if (kb + 1 < nkb) cpKV(kb + 1, buf ^ 1);

        const uint32_t kS = sb + buf * ATT_BUF;
        const uint32_t vS = kS + 8192;

        // ---- S = Q K^T (1-pass fp16) ----
        float s[8][4];
        #pragma unroll
        for (int i = 0; i < 8; i++)
            #pragma unroll
            for (int j = 0; j < 4; j++) s[i][j] = 0.f;

        #pragma unroll
        for (int t = 0; t < 4; t++) {
            uint32_t kf[8][2];
            #pragma unroll
            for (int p = 0; p < 4; p++) {
                int n = p * 16 + (lane & 7) + ((lane >> 4) << 3);
                uint32_t off = n * 128 + ((t * 32 + ((lane >> 3) & 1) * 16) ^ ((n & 7) * 16));
                LDSM_X4(kf[p*2][0], kf[p*2][1], kf[p*2+1][0], kf[p*2+1][1], kS + off);
            }
            #pragma unroll
            for (int nt = 0; nt < 8; nt++)
                MMA_F16(s[nt], qf[t], kf[nt]);
        }

        if (kb == nkb - 1) {
            int cb = kb * 64 + c2;
            #pragma unroll
            for (int nt = 0; nt < 8; nt++) {
                int c0g = cb + nt * 8;
                if (c0g     >= vlen) { s[nt][0] = -1e30f; s[nt][2] = -1e30f; }
                if (c0g + 1 >= vlen) { s[nt][1] = -1e30f; s[nt][3] = -1e30f; }
            }
        }

        // ---- max (fp32, quad shfl) ----
        float mx0 = -1e30f, mx1 = -1e30f;
        #pragma unroll
        for (int nt = 0; nt < 8; nt++) {
            mx0 = fmaxf(mx0, fmaxf(s[nt][0], s[nt][1]));
            mx1 = fmaxf(mx1, fmaxf(s[nt][2], s[nt][3]));
        }
        mx0 = fmaxf(mx0, __shfl_xor_sync(0xffffffffu, mx0, 1));
        mx0 = fmaxf(mx0, __shfl_xor_sync(0xffffffffu, mx0, 2));
        mx1 = fmaxf(mx1, __shfl_xor_sync(0xffffffffu, mx1, 1));
        mx1 = fmaxf(mx1, __shfl_xor_sync(0xffffffffu, mx1, 2));

        float mn0 = fmaxf(m_i[0], mx0), mn1 = fmaxf(m_i[1], mx1);
        float a0 = ex2f(m_i[0] - mn0), a1 = ex2f(m_i[1] - mn1);
        m_i[0] = mn0; m_i[1] = mn1;

        // ---- P = exp2(S - m) in f16x2, directly in MMA layout ----
        uint32_t ps[4][4];
        #pragma unroll
        for (int t = 0; t < 4; t++) {
            ps[t][0] = ex2h2(h2pack(s[2*t  ][0] - mn0, s[2*t  ][1] - mn0));
            ps[t][1] = ex2h2(h2pack(s[2*t  ][2] - mn1, s[2*t  ][3] - mn1));
            ps[t][2] = ex2h2(h2pack(s[2*t+1][0] - mn0, s[2*t+1][1] - mn0));
            ps[t][3] = ex2h2(h2pack(s[2*t+1][2] - mn1, s[2*t+1][3] - mn1));
        }

        // ---- row sums via ones-MMA (fp32 accumulate, no shfl) ----
        float sacc[4] = {0.f, 0.f, 0.f, 0.f};
        #pragma unroll
        for (int t = 0; t < 4; t++)
            MMA_F16(sacc, ps[t], ONES);
        l_i[0] = l_i[0] * a0 + sacc[0];
        l_i[1] = l_i[1] * a1 + sacc[2];

        #pragma unroll
        for (int nt = 0; nt < 8; nt++) {
            o[nt][0] *= a0; o[nt][1] *= a0;
            o[nt][2] *= a1; o[nt][3] *= a1;
        }

        // ---- O += P V (1-pass) ----
        #pragma unroll
        for (int t = 0; t < 4; t++) {
            uint32_t vf[8][2];
            #pragma unroll
            for (int p = 0; p < 4; p++) {
                int rowb = t * 16 + (lane & 15);
                uint32_t off = rowb * 128 + ((p * 32 + (lane >> 4) * 16) ^ ((rowb & 7) * 16));
                LDSM_X4_T(vf[p*2][0], vf[p*2][1], vf[p*2+1][0], vf[p*2+1][1], vS + off);
            }
            #pragma unroll
            for (int nt = 0; nt < 8; nt++)
                MMA_F16(o[nt], ps[t], vf[nt]);
        }
    }

    // epilogue: single fp16 to g_AO16 [B*S][D]
    const float inv0 = 1.f / l_i[0], inv1 = 1.f / l_i[1];
    const int row0 = qb * 128 + wid * 16 + r;
    const size_t base0 = (size_t)(bb * NS + row0    ) * ND + head * 64;
    const size_t base1 = (size_t)(bb * NS + row0 + 8) * ND + head * 64;
    #pragma unroll
    for (int nt = 0; nt < 8; nt++) {
        *(uint32_t*)(g_AO16 + base0 + nt * 8 + c2) = h2pack(o[nt][0] * inv0, o[nt][1] * inv0);
        *(uint32_t*)(g_AO16 + base1 + nt * 8 + c2) = h2pack(o[nt][2] * inv1, o[nt][3] * inv1);
    }
}

// ---------------------------------------------------------------------------
extern "C" void kernel_launch(void* const* d_in, const int* in_sizes, int n_in,
                              void* d_out, int out_size)
{
    const float* q  = (const float*)d_in[0];
    const float* k  = (const float*)d_in[1];
    const float* v  = (const float*)d_in[2];
    const int*   vl = (const int*)  d_in[3];
    const float* Wq = (const float*)d_in[4];
    const float* Wk = (const float*)d_in[5];
    const float* Wv = (const float*)d_in[6];
    const float* Wo = (const float*)d_in[7];
    float* out = (float*)d_out;

    cudaFuncSetAttribute(gemm_mma_kernel, cudaFuncAttributeMaxDynamicSharedMemorySize,
                         GEMM_SMEM);
    cudaFuncSetAttribute(attn_mma_kernel, cudaFuncAttributeMaxDynamicSharedMemorySize,
                         ATT_SMEM);

    prep_kernel<<<dim3(4096, 1, 7), 256>>>(q, k, v, Wq, Wk, Wv, Wo);

    gemm_mma_kernel<<<dim3(ND / 128, (NB * NS) / 128, 3), 128, GEMM_SMEM>>>(out, 0);

    attn_mma_kernel<<<dim3(NS / 128, NB * NH), 256, ATT_SMEM>>>(vl);

    gemm_mma_kernel<<<dim3(ND / 128, (NB * NS) / 128, 1), 128, GEMM_SMEM>>>(out, 1);
}